// round 2
// baseline (speedup 1.0000x reference)
#include <cuda_runtime.h>
#include <stdint.h>

#define Bn 4
#define Sn 2048
#define Dn 1024
#define Hn 16
#define HDn 64

// Scratch (static device globals -- allocation-free per harness rules)
__device__ float   g_q[(size_t)Bn * Hn * Sn * HDn];  // [B,H,S,HD]
__device__ float   g_k[(size_t)Bn * Hn * Sn * HDn];
__device__ float   g_v[(size_t)Bn * Hn * Sn * HDn];
__device__ float   g_o[(size_t)Bn * Sn * Dn];        // [B,S,D]
__device__ uint8_t g_mask[(size_t)Bn * Sn * Sn];     // normalized mask (1 byte/elt)
__device__ int     g_mask_flag;                      // 0=uint8, 1=int32, 2=float32

// ---------------------------------------------------------------------------
// Mask dtype sniffer: inspect first 256 words of the raw mask buffer.
//   int32 mask  -> words are 0 or 1
//   float32 mask-> words are 0 or 0x3F800000
//   uint8 mask  -> words are 4 packed {0,1} bytes (e.g. 0x01010101), rarely 0/1
// ---------------------------------------------------------------------------
__global__ void detect_mask_kernel(const uint32_t* __restrict__ m)
{
    __shared__ int cnt_f, cnt_i;
    if (threadIdx.x == 0) { cnt_f = 0; cnt_i = 0; }
    __syncthreads();
    uint32_t w = m[threadIdx.x];
    if (w == 0x3F800000u || w == 0u) atomicAdd(&cnt_f, 1);
    if (w == 1u || w == 0u)          atomicAdd(&cnt_i, 1);
    __syncthreads();
    if (threadIdx.x == 0) {
        int flag = 0;                       // default: uint8
        if (cnt_f > 200)      flag = 2;     // float32
        else if (cnt_i > 200) flag = 1;     // int32
        g_mask_flag = flag;
    }
}

__global__ __launch_bounds__(256) void convert_mask_kernel(const void* __restrict__ m)
{
    const size_t i = (size_t)blockIdx.x * 256 + threadIdx.x;
    const int flag = g_mask_flag;
    uint8_t v;
    if (flag == 1)      v = (((const int*)m)[i]   != 0);
    else if (flag == 2) v = (((const float*)m)[i] != 0.0f);
    else                v = (((const uint8_t*)m)[i] != 0);
    g_mask[i] = v;
}

// ---------------------------------------------------------------------------
// QKV projection: C = X @ W^T, scattered into [B,H,S,HD] layout.
// BM=BN=128, BK=8, 256 threads, 8x8 per thread.
// ---------------------------------------------------------------------------
__global__ __launch_bounds__(256) void qkv_gemm_kernel(
    const float* __restrict__ X,
    const float* __restrict__ Wq,
    const float* __restrict__ Wk,
    const float* __restrict__ Wv)
{
    const float* W;
    float* dst;
    if (blockIdx.z == 0)      { W = Wq; dst = g_q; }
    else if (blockIdx.z == 1) { W = Wk; dst = g_k; }
    else                      { W = Wv; dst = g_v; }

    __shared__ float As[8][132];
    __shared__ float Bs[8][132];

    const int tid = threadIdx.x;
    const int tx = tid & 15, ty = tid >> 4;
    const int bm = blockIdx.y * 128;
    const int bn = blockIdx.x * 128;

    const int loadRow = tid >> 1;         // 0..127
    const int loadK4  = (tid & 1) * 4;    // 0 or 4
    const float* Ap = X + (size_t)(bm + loadRow) * Dn + loadK4;
    const float* Wp = W + (size_t)(bn + loadRow) * Dn + loadK4;

    float acc[8][8];
    #pragma unroll
    for (int i = 0; i < 8; i++)
        #pragma unroll
        for (int j = 0; j < 8; j++) acc[i][j] = 0.f;

    for (int k0 = 0; k0 < Dn; k0 += 8) {
        float4 a = *(const float4*)(Ap + k0);
        float4 w = *(const float4*)(Wp + k0);
        __syncthreads();
        As[loadK4 + 0][loadRow] = a.x;
        As[loadK4 + 1][loadRow] = a.y;
        As[loadK4 + 2][loadRow] = a.z;
        As[loadK4 + 3][loadRow] = a.w;
        Bs[loadK4 + 0][loadRow] = w.x;
        Bs[loadK4 + 1][loadRow] = w.y;
        Bs[loadK4 + 2][loadRow] = w.z;
        Bs[loadK4 + 3][loadRow] = w.w;
        __syncthreads();
        #pragma unroll
        for (int kk = 0; kk < 8; kk++) {
            float4 a0 = *(const float4*)&As[kk][ty * 8];
            float4 a1 = *(const float4*)&As[kk][ty * 8 + 4];
            float4 b0 = *(const float4*)&Bs[kk][tx * 8];
            float4 b1 = *(const float4*)&Bs[kk][tx * 8 + 4];
            float ar[8] = {a0.x, a0.y, a0.z, a0.w, a1.x, a1.y, a1.z, a1.w};
            float br[8] = {b0.x, b0.y, b0.z, b0.w, b1.x, b1.y, b1.z, b1.w};
            #pragma unroll
            for (int i = 0; i < 8; i++)
                #pragma unroll
                for (int j = 0; j < 8; j++)
                    acc[i][j] += ar[i] * br[j];
        }
    }

    // Scatter epilogue: n -> (h, hd), m -> (b, s). tx*8 block stays in one head.
    const int n0  = bn + tx * 8;
    const int hh  = n0 >> 6;
    const int hd0 = n0 & 63;
    #pragma unroll
    for (int i = 0; i < 8; i++) {
        int m  = bm + ty * 8 + i;
        int bb = m >> 11, ss = m & 2047;
        size_t base = (((size_t)bb * Hn + hh) * Sn + ss) * HDn + hd0;
        *(float4*)&dst[base]     = make_float4(acc[i][0], acc[i][1], acc[i][2], acc[i][3]);
        *(float4*)&dst[base + 4] = make_float4(acc[i][4], acc[i][5], acc[i][6], acc[i][7]);
    }
}

// ---------------------------------------------------------------------------
// Flash attention: grid (S/32, B*H), 256 threads (8 warps x 4 q-rows).
// Each lane owns k columns {lane, lane+32} of the 64-wide K tile and output
// dims {2*lane, 2*lane+1}.
// ---------------------------------------------------------------------------
__global__ __launch_bounds__(256) void attn_kernel()
{
    __shared__ float Ksh[64 * 68];   // pitch 68 -> conflict-free LDS.128 per-lane rows
    __shared__ float Vsh[64 * 64];
    __shared__ float Qsh[32 * 64];

    const int tid  = threadIdx.x;
    const int lane = tid & 31;
    const int warp = tid >> 5;
    const int qt = blockIdx.x, bh = blockIdx.y;
    const int b = bh >> 4, h = bh & 15;
    const int qbase = qt * 32;
    const int wrow0 = warp * 4;

    const size_t head_off = (size_t)bh * Sn * HDn;

    // Load Q tile (32 x 64)
    {
        const float* qg = g_q + head_off + (size_t)qbase * HDn;
        for (int t = tid; t < 32 * 16; t += 256) {
            int row = t >> 4, c = (t & 15) * 4;
            *(float4*)&Qsh[row * 64 + c] = *(const float4*)&qg[row * 64 + c];
        }
    }

    float  m_r[4], l_r[4];
    float2 o_r[4];
    #pragma unroll
    for (int r = 0; r < 4; r++) {
        m_r[r] = -1e30f; l_r[r] = 0.f; o_r[r] = make_float2(0.f, 0.f);
    }

    const uint8_t* mrow0 = g_mask + ((size_t)b * Sn + qbase + wrow0) * Sn;

    for (int kt = 0; kt < Sn / 64; kt++) {
        const int k0 = kt * 64;
        __syncthreads();
        {
            const float* kg = g_k + head_off + (size_t)k0 * HDn;
            const float* vg = g_v + head_off + (size_t)k0 * HDn;
            for (int t = tid; t < 64 * 16; t += 256) {
                int row = t >> 4, c = (t & 15) * 4;
                *(float4*)&Ksh[row * 68 + c] = *(const float4*)&kg[row * 64 + c];
                *(float4*)&Vsh[row * 64 + c] = *(const float4*)&vg[row * 64 + c];
            }
        }
        __syncthreads();

        // Scores: s[r][j] = q_r . k_{lane + 32j}
        float s0[4] = {0.f, 0.f, 0.f, 0.f};
        float s1[4] = {0.f, 0.f, 0.f, 0.f};
        const float* kA = &Ksh[lane * 68];
        const float* kB = &Ksh[(lane + 32) * 68];
        #pragma unroll
        for (int d = 0; d < 64; d += 4) {
            float4 ka = *(const float4*)(kA + d);
            float4 kb = *(const float4*)(kB + d);
            #pragma unroll
            for (int r = 0; r < 4; r++) {
                float4 q = *(const float4*)&Qsh[(wrow0 + r) * 64 + d];
                s0[r] += q.x * ka.x + q.y * ka.y + q.z * ka.z + q.w * ka.w;
                s1[r] += q.x * kb.x + q.y * kb.y + q.z * kb.z + q.w * kb.w;
            }
        }

        // Online softmax per row
        float p0[4], p1[4];
        #pragma unroll
        for (int r = 0; r < 4; r++) {
            const uint8_t* mr = mrow0 + (size_t)r * Sn + k0;
            bool v0 = mr[lane] != 0;
            bool v1 = mr[lane + 32] != 0;
            float sc0 = v0 ? s0[r] * 0.125f : -1e30f;
            float sc1 = v1 ? s1[r] * 0.125f : -1e30f;
            float tmax = fmaxf(sc0, sc1);
            #pragma unroll
            for (int off = 16; off; off >>= 1)
                tmax = fmaxf(tmax, __shfl_xor_sync(0xffffffffu, tmax, off));
            float mnew  = fmaxf(m_r[r], tmax);
            float alpha = __expf(m_r[r] - mnew);
            float e0 = v0 ? __expf(sc0 - mnew) : 0.f;   // exact match to ref: masked p == 0
            float e1 = v1 ? __expf(sc1 - mnew) : 0.f;
            float rs = e0 + e1;
            #pragma unroll
            for (int off = 16; off; off >>= 1)
                rs += __shfl_xor_sync(0xffffffffu, rs, off);
            l_r[r] = l_r[r] * alpha + rs;
            o_r[r].x *= alpha; o_r[r].y *= alpha;
            m_r[r] = mnew;
            p0[r] = e0; p1[r] = e1;
        }

        // O accumulation: p broadcast via shuffle (no smem round-trip)
        #pragma unroll 8
        for (int k = 0; k < 32; k++) {
            float2 v = *(const float2*)&Vsh[k * 64 + 2 * lane];
            #pragma unroll
            for (int r = 0; r < 4; r++) {
                float pv = __shfl_sync(0xffffffffu, p0[r], k);
                o_r[r].x += pv * v.x; o_r[r].y += pv * v.y;
            }
        }
        #pragma unroll 8
        for (int k = 0; k < 32; k++) {
            float2 v = *(const float2*)&Vsh[(k + 32) * 64 + 2 * lane];
            #pragma unroll
            for (int r = 0; r < 4; r++) {
                float pv = __shfl_sync(0xffffffffu, p1[r], k);
                o_r[r].x += pv * v.x; o_r[r].y += pv * v.y;
            }
        }
    }

    #pragma unroll
    for (int r = 0; r < 4; r++) {
        float inv = 1.f / fmaxf(l_r[r], 1e-30f);
        float2 res = make_float2(o_r[r].x * inv, o_r[r].y * inv);
        size_t idx = ((size_t)b * Sn + qbase + wrow0 + r) * Dn + h * 64 + 2 * lane;
        *(float2*)&g_o[idx] = res;
    }
}

// ---------------------------------------------------------------------------
// Output projection: out = O @ Wo^T (dense), same SGEMM shape.
// ---------------------------------------------------------------------------
__global__ __launch_bounds__(256) void out_gemm_kernel(
    const float* __restrict__ Wo, float* __restrict__ out)
{
    __shared__ float As[8][132];
    __shared__ float Bs[8][132];

    const int tid = threadIdx.x;
    const int tx = tid & 15, ty = tid >> 4;
    const int bm = blockIdx.y * 128;
    const int bn = blockIdx.x * 128;

    const int loadRow = tid >> 1;
    const int loadK4  = (tid & 1) * 4;
    const float* Ap = g_o + (size_t)(bm + loadRow) * Dn + loadK4;
    const float* Wp = Wo  + (size_t)(bn + loadRow) * Dn + loadK4;

    float acc[8][8];
    #pragma unroll
    for (int i = 0; i < 8; i++)
        #pragma unroll
        for (int j = 0; j < 8; j++) acc[i][j] = 0.f;

    for (int k0 = 0; k0 < Dn; k0 += 8) {
        float4 a = *(const float4*)(Ap + k0);
        float4 w = *(const float4*)(Wp + k0);
        __syncthreads();
        As[loadK4 + 0][loadRow] = a.x;
        As[loadK4 + 1][loadRow] = a.y;
        As[loadK4 + 2][loadRow] = a.z;
        As[loadK4 + 3][loadRow] = a.w;
        Bs[loadK4 + 0][loadRow] = w.x;
        Bs[loadK4 + 1][loadRow] = w.y;
        Bs[loadK4 + 2][loadRow] = w.z;
        Bs[loadK4 + 3][loadRow] = w.w;
        __syncthreads();
        #pragma unroll
        for (int kk = 0; kk < 8; kk++) {
            float4 a0 = *(const float4*)&As[kk][ty * 8];
            float4 a1 = *(const float4*)&As[kk][ty * 8 + 4];
            float4 b0 = *(const float4*)&Bs[kk][tx * 8];
            float4 b1 = *(const float4*)&Bs[kk][tx * 8 + 4];
            float ar[8] = {a0.x, a0.y, a0.z, a0.w, a1.x, a1.y, a1.z, a1.w};
            float br[8] = {b0.x, b0.y, b0.z, b0.w, b1.x, b1.y, b1.z, b1.w};
            #pragma unroll
            for (int i = 0; i < 8; i++)
                #pragma unroll
                for (int j = 0; j < 8; j++)
                    acc[i][j] += ar[i] * br[j];
        }
    }

    #pragma unroll
    for (int i = 0; i < 8; i++) {
        int m = bm + ty * 8 + i;
        size_t base = (size_t)m * Dn + bn + tx * 8;
        *(float4*)&out[base]     = make_float4(acc[i][0], acc[i][1], acc[i][2], acc[i][3]);
        *(float4*)&out[base + 4] = make_float4(acc[i][4], acc[i][5], acc[i][6], acc[i][7]);
    }
}

// ---------------------------------------------------------------------------
extern "C" void kernel_launch(void* const* d_in, const int* in_sizes, int n_in,
                              void* d_out, int out_size)
{
    const float* x    = (const float*)d_in[0];
    const void*  mask = d_in[1];                 // dtype sniffed on device
    const float* wq   = (const float*)d_in[2];
    const float* wk   = (const float*)d_in[3];
    const float* wv   = (const float*)d_in[4];
    const float* wo   = (const float*)d_in[5];
    float* out = (float*)d_out;

    detect_mask_kernel<<<1, 256>>>((const uint32_t*)mask);

    const size_t mask_elts = (size_t)Bn * Sn * Sn;
    convert_mask_kernel<<<(unsigned)(mask_elts / 256), 256>>>(mask);

    dim3 g1(Dn / 128, (Bn * Sn) / 128, 3);
    qkv_gemm_kernel<<<g1, 256>>>(x, wq, wk, wv);

    dim3 g2(Sn / 32, Bn * Hn);
    attn_kernel<<<g2, 256>>>();

    dim3 g3(Dn / 128, (Bn * Sn) / 128);
    out_gemm_kernel<<<g3, 256>>>(wo, out);
}

// round 4
// speedup vs baseline: 1.2850x; 1.2850x over previous
#include <cuda_runtime.h>
#include <cuda_bf16.h>
#include <stdint.h>

#define Bn 4
#define Sn 2048
#define Dn 1024
#define Hn 16
#define HDn 64
#define Mtot (Bn * Sn)          // 8192

// Scratch (static device globals -- allocation-free per harness rules)
__device__ float   g_q[(size_t)Bn * Hn * Sn * HDn];  // [B,H,S,HD]
__device__ float   g_k[(size_t)Bn * Hn * Sn * HDn];
__device__ float   g_v[(size_t)Bn * Hn * Sn * HDn];
__device__ float   g_o[(size_t)Bn * Sn * Dn];        // [B,S,D]
__device__ uint8_t g_mask[(size_t)Bn * Sn * Sn];     // normalized mask
__device__ int     g_mask_flag;

// split-bf16 operand buffers
__device__ __nv_bfloat16 g_ahi[(size_t)Mtot * Dn];   // X (then attn-out) hi
__device__ __nv_bfloat16 g_alo[(size_t)Mtot * Dn];   // X (then attn-out) lo
__device__ __nv_bfloat16 g_whi[(size_t)4 * Dn * Dn]; // wq,wk,wv,wo hi
__device__ __nv_bfloat16 g_wlo[(size_t)4 * Dn * Dn]; // wq,wk,wv,wo lo

// ===========================================================================
// PTX helpers (base-ISA only: ldmatrix + mma.sync -- no sm_103a features)
// ===========================================================================
__device__ __forceinline__ uint32_t smem_u32(const void* p) {
    uint32_t a;
    asm("{ .reg .u64 t; cvta.to.shared.u64 t, %1; cvt.u32.u64 %0, t; }" : "=r"(a) : "l"(p));
    return a;
}

#define LDSM4(r0, r1, r2, r3, addr) \
    asm volatile("ldmatrix.sync.aligned.m8n8.x4.shared.b16 {%0,%1,%2,%3}, [%4];" \
        : "=r"(r0), "=r"(r1), "=r"(r2), "=r"(r3) : "r"(addr))

#define MMA16816(c, a0, a1, a2, a3, b0, b1) \
    asm volatile("mma.sync.aligned.m16n8k16.row.col.f32.bf16.bf16.f32 " \
        "{%0,%1,%2,%3}, {%4,%5,%6,%7}, {%8,%9}, {%0,%1,%2,%3};" \
        : "+f"((c)[0]), "+f"((c)[1]), "+f"((c)[2]), "+f"((c)[3]) \
        : "r"(a0), "r"(a1), "r"(a2), "r"(a3), "r"(b0), "r"(b1))

// ===========================================================================
// Mask dtype sniffer + normalizer (known-good)
// ===========================================================================
__global__ void detect_mask_kernel(const uint32_t* __restrict__ m)
{
    __shared__ int cnt_f, cnt_i;
    if (threadIdx.x == 0) { cnt_f = 0; cnt_i = 0; }
    __syncthreads();
    uint32_t w = m[threadIdx.x];
    if (w == 0x3F800000u || w == 0u) atomicAdd(&cnt_f, 1);
    if (w == 1u || w == 0u)          atomicAdd(&cnt_i, 1);
    __syncthreads();
    if (threadIdx.x == 0) {
        int flag = 0;
        if (cnt_f > 200)      flag = 2;
        else if (cnt_i > 200) flag = 1;
        g_mask_flag = flag;
    }
}

__global__ __launch_bounds__(256) void convert_mask_kernel(const void* __restrict__ m)
{
    const size_t i = (size_t)blockIdx.x * 256 + threadIdx.x;
    const int flag = g_mask_flag;
    uint8_t v;
    if (flag == 1)      v = (((const int*)m)[i]   != 0);
    else if (flag == 2) v = (((const float*)m)[i] != 0.0f);
    else                v = (((const uint8_t*)m)[i] != 0);
    g_mask[i] = v;
}

// ===========================================================================
// fp32 -> (bf16 hi, bf16 lo) split.  4 elems/thread via float4.
// ===========================================================================
__global__ __launch_bounds__(256) void split_kernel(
    const float* __restrict__ src,
    __nv_bfloat16* __restrict__ hi,
    __nv_bfloat16* __restrict__ lo)
{
    const size_t i = (size_t)blockIdx.x * 256 + threadIdx.x;
    float4 x = ((const float4*)src)[i];
    __nv_bfloat16 h0 = __float2bfloat16(x.x);
    __nv_bfloat16 h1 = __float2bfloat16(x.y);
    __nv_bfloat16 h2 = __float2bfloat16(x.z);
    __nv_bfloat16 h3 = __float2bfloat16(x.w);
    __nv_bfloat16 l0 = __float2bfloat16(x.x - __bfloat162float(h0));
    __nv_bfloat16 l1 = __float2bfloat16(x.y - __bfloat162float(h1));
    __nv_bfloat16 l2 = __float2bfloat16(x.z - __bfloat162float(h2));
    __nv_bfloat16 l3 = __float2bfloat16(x.w - __bfloat162float(h3));
    uint32_t p0 = (uint32_t)__bfloat16_as_ushort(h0) | ((uint32_t)__bfloat16_as_ushort(h1) << 16);
    uint32_t p1 = (uint32_t)__bfloat16_as_ushort(h2) | ((uint32_t)__bfloat16_as_ushort(h3) << 16);
    uint32_t q0 = (uint32_t)__bfloat16_as_ushort(l0) | ((uint32_t)__bfloat16_as_ushort(l1) << 16);
    uint32_t q1 = (uint32_t)__bfloat16_as_ushort(l2) | ((uint32_t)__bfloat16_as_ushort(l3) << 16);
    ((uint2*)hi)[i] = make_uint2(p0, p1);
    ((uint2*)lo)[i] = make_uint2(q0, q1);
}

// ===========================================================================
// Split-bf16 tensor-core GEMM: C[128x128] = A[.,1024] @ W[.,1024]^T
//   D += Ah*Bh + Ah*Bl + Al*Bh    (fp32 accumulate, mma.sync m16n8k16)
// mode 0: scatter into g_q/g_k/g_v by blockIdx.z; mode 1: dense store to out.
// ===========================================================================
#define KC 32                    // fp32-K per chunk (= bf16-K per tile)
#define PITCH 40                 // halves per smem row (80B: conflict-free ldmatrix)
#define TILE_B (128 * PITCH * 2) // 10240 B per tile
#define STAGE_B (4 * TILE_B)     // Ah, Al, Bh, Bl
#define DYNSM (2 * STAGE_B)      // 81920 B

__global__ __launch_bounds__(256, 1) void mma_gemm_kernel(
    const __nv_bfloat16* __restrict__ Ahi,
    const __nv_bfloat16* __restrict__ Alo,
    const __nv_bfloat16* __restrict__ Whi,
    const __nv_bfloat16* __restrict__ Wlo,
    float* __restrict__ out,
    int mode)
{
    extern __shared__ char dsm[];
    const uint32_t sbase = smem_u32(dsm);

    const int tid  = threadIdx.x;
    const int lane = tid & 31;
    const int wid  = tid >> 5;
    const int wr   = wid >> 2;       // 0..1  (64-row block)
    const int wc   = wid & 3;        // 0..3  (32-col block)
    const int bm   = blockIdx.y * 128;
    const int bn   = blockIdx.x * 128;
    const int z    = blockIdx.z;

    const __nv_bfloat16* WhiZ = Whi + (size_t)z * Dn * Dn;
    const __nv_bfloat16* WloZ = Wlo + (size_t)z * Dn * Dn;

    // ---- global load pointers: thread t handles row t>>1, half (t&1)*16 ----
    const int grow = tid >> 1;
    const int gh   = tid & 1;
    const size_t aoff = (size_t)(bm + grow) * Dn + gh * 16;
    const size_t woff = (size_t)(bn + grow) * Dn + gh * 16;

    // smem store address (bytes) for this thread within a tile
    const uint32_t s_off = (uint32_t)grow * (PITCH * 2) + gh * 32;

    float acc[4][4][4];
    #pragma unroll
    for (int i = 0; i < 4; i++)
        #pragma unroll
        for (int j = 0; j < 4; j++)
            #pragma unroll
            for (int v = 0; v < 4; v++) acc[i][j][v] = 0.f;

    uint4 pf[8];
    auto gload = [&](int ck) {
        const size_t o = (size_t)ck * KC;
        pf[0] = *(const uint4*)(Ahi  + aoff + o);
        pf[1] = *(const uint4*)(Ahi  + aoff + o + 8);
        pf[2] = *(const uint4*)(Alo  + aoff + o);
        pf[3] = *(const uint4*)(Alo  + aoff + o + 8);
        pf[4] = *(const uint4*)(WhiZ + woff + o);
        pf[5] = *(const uint4*)(WhiZ + woff + o + 8);
        pf[6] = *(const uint4*)(WloZ + woff + o);
        pf[7] = *(const uint4*)(WloZ + woff + o + 8);
    };
    auto sstore = [&](int s) {
        char* st = dsm + s * STAGE_B;
        #pragma unroll
        for (int tb = 0; tb < 4; tb++) {
            *(uint4*)(st + tb * TILE_B + s_off)      = pf[2 * tb];
            *(uint4*)(st + tb * TILE_B + s_off + 16) = pf[2 * tb + 1];
        }
    };

    gload(0);
    sstore(0);
    __syncthreads();

    const int NC = Dn / KC;     // 32
    for (int ck = 0; ck < NC; ck++) {
        const int s = ck & 1;
        if (ck + 1 < NC) gload(ck + 1);

        const uint32_t stg = sbase + s * STAGE_B;
        #pragma unroll
        for (int pass = 0; pass < 3; pass++) {
            const uint32_t aofs = stg + ((pass == 2) ? TILE_B : 0);
            const uint32_t bofs = stg + ((pass == 1) ? 3 * TILE_B : 2 * TILE_B);
            #pragma unroll
            for (int ks = 0; ks < 2; ks++) {
                // B fragments: 4 col-frags of 8 via two x4 ldmatrix
                uint32_t b[4][2];
                #pragma unroll
                for (int jj = 0; jj < 2; jj++) {
                    int n = wc * 32 + jj * 16 + ((lane >> 4) & 1) * 8 + (lane & 7);
                    int k = ks * 16 + ((lane >> 3) & 1) * 8;
                    uint32_t ad = bofs + (uint32_t)(n * PITCH + k) * 2;
                    LDSM4(b[2 * jj][0], b[2 * jj][1], b[2 * jj + 1][0], b[2 * jj + 1][1], ad);
                }
                #pragma unroll
                for (int i = 0; i < 4; i++) {
                    int m = wr * 64 + i * 16 + ((lane >> 3) & 1) * 8 + (lane & 7);
                    int k = ks * 16 + ((lane >> 4) & 1) * 8;
                    uint32_t ad = aofs + (uint32_t)(m * PITCH + k) * 2;
                    uint32_t a0, a1, a2, a3;
                    LDSM4(a0, a1, a2, a3, ad);
                    #pragma unroll
                    for (int j = 0; j < 4; j++)
                        MMA16816(acc[i][j], a0, a1, a2, a3, b[j][0], b[j][1]);
                }
            }
        }

        if (ck + 1 < NC) {
            __syncthreads();
            sstore(s ^ 1);
            __syncthreads();
        }
    }

    // ---- epilogue ----
    #pragma unroll
    for (int i = 0; i < 4; i++) {
        #pragma unroll
        for (int j = 0; j < 4; j++) {
            int ml = wr * 64 + i * 16 + (lane >> 2);
            int nl = wc * 32 + j * 8 + 2 * (lane & 3);
            int m = bm + ml, n = bn + nl;
            float2 lo2 = make_float2(acc[i][j][0], acc[i][j][1]);
            float2 hi2 = make_float2(acc[i][j][2], acc[i][j][3]);
            if (mode == 0) {
                float* dst = (z == 0) ? g_q : (z == 1 ? g_k : g_v);
                int bb = m >> 11, ss = m & 2047;
                int hh = n >> 6,  hd = n & 63;
                size_t base = (((size_t)bb * Hn + hh) * Sn + ss) * HDn + hd;
                *(float2*)&dst[base] = lo2;
                *(float2*)&dst[base + 8 * HDn] = hi2;
            } else {
                *(float2*)&out[(size_t)m * Dn + n] = lo2;
                *(float2*)&out[(size_t)(m + 8) * Dn + n] = hi2;
            }
        }
    }
}

// ===========================================================================
// Flash attention (unchanged -- passed with rel_err 1.4e-6)
// ===========================================================================
__global__ __launch_bounds__(256) void attn_kernel()
{
    __shared__ float Ksh[64 * 68];
    __shared__ float Vsh[64 * 64];
    __shared__ float Qsh[32 * 64];

    const int tid  = threadIdx.x;
    const int lane = tid & 31;
    const int warp = tid >> 5;
    const int qt = blockIdx.x, bh = blockIdx.y;
    const int b = bh >> 4, h = bh & 15;
    const int qbase = qt * 32;
    const int wrow0 = warp * 4;

    const size_t head_off = (size_t)bh * Sn * HDn;

    {
        const float* qg = g_q + head_off + (size_t)qbase * HDn;
        for (int t = tid; t < 32 * 16; t += 256) {
            int row = t >> 4, c = (t & 15) * 4;
            *(float4*)&Qsh[row * 64 + c] = *(const float4*)&qg[row * 64 + c];
        }
    }

    float  m_r[4], l_r[4];
    float2 o_r[4];
    #pragma unroll
    for (int r = 0; r < 4; r++) {
        m_r[r] = -1e30f; l_r[r] = 0.f; o_r[r] = make_float2(0.f, 0.f);
    }

    const uint8_t* mrow0 = g_mask + ((size_t)b * Sn + qbase + wrow0) * Sn;

    for (int kt = 0; kt < Sn / 64; kt++) {
        const int k0 = kt * 64;
        __syncthreads();
        {
            const float* kg = g_k + head_off + (size_t)k0 * HDn;
            const float* vg = g_v + head_off + (size_t)k0 * HDn;
            for (int t = tid; t < 64 * 16; t += 256) {
                int row = t >> 4, c = (t & 15) * 4;
                *(float4*)&Ksh[row * 68 + c] = *(const float4*)&kg[row * 64 + c];
                *(float4*)&Vsh[row * 64 + c] = *(const float4*)&vg[row * 64 + c];
            }
        }
        __syncthreads();

        float s0[4] = {0.f, 0.f, 0.f, 0.f};
        float s1[4] = {0.f, 0.f, 0.f, 0.f};
        const float* kA = &Ksh[lane * 68];
        const float* kB = &Ksh[(lane + 32) * 68];
        #pragma unroll
        for (int d = 0; d < 64; d += 4) {
            float4 ka = *(const float4*)(kA + d);
            float4 kb = *(const float4*)(kB + d);
            #pragma unroll
            for (int r = 0; r < 4; r++) {
                float4 q = *(const float4*)&Qsh[(wrow0 + r) * 64 + d];
                s0[r] += q.x * ka.x + q.y * ka.y + q.z * ka.z + q.w * ka.w;
                s1[r] += q.x * kb.x + q.y * kb.y + q.z * kb.z + q.w * kb.w;
            }
        }

        float p0[4], p1[4];
        #pragma unroll
        for (int r = 0; r < 4; r++) {
            const uint8_t* mr = mrow0 + (size_t)r * Sn + k0;
            bool v0 = mr[lane] != 0;
            bool v1 = mr[lane + 32] != 0;
            float sc0 = v0 ? s0[r] * 0.125f : -1e30f;
            float sc1 = v1 ? s1[r] * 0.125f : -1e30f;
            float tmax = fmaxf(sc0, sc1);
            #pragma unroll
            for (int off = 16; off; off >>= 1)
                tmax = fmaxf(tmax, __shfl_xor_sync(0xffffffffu, tmax, off));
            float mnew  = fmaxf(m_r[r], tmax);
            float alpha = __expf(m_r[r] - mnew);
            float e0 = v0 ? __expf(sc0 - mnew) : 0.f;
            float e1 = v1 ? __expf(sc1 - mnew) : 0.f;
            float rs = e0 + e1;
            #pragma unroll
            for (int off = 16; off; off >>= 1)
                rs += __shfl_xor_sync(0xffffffffu, rs, off);
            l_r[r] = l_r[r] * alpha + rs;
            o_r[r].x *= alpha; o_r[r].y *= alpha;
            m_r[r] = mnew;
            p0[r] = e0; p1[r] = e1;
        }

        #pragma unroll 8
        for (int k = 0; k < 32; k++) {
            float2 v = *(const float2*)&Vsh[k * 64 + 2 * lane];
            #pragma unroll
            for (int r = 0; r < 4; r++) {
                float pv = __shfl_sync(0xffffffffu, p0[r], k);
                o_r[r].x += pv * v.x; o_r[r].y += pv * v.y;
            }
        }
        #pragma unroll 8
        for (int k = 0; k < 32; k++) {
            float2 v = *(const float2*)&Vsh[(k + 32) * 64 + 2 * lane];
            #pragma unroll
            for (int r = 0; r < 4; r++) {
                float pv = __shfl_sync(0xffffffffu, p1[r], k);
                o_r[r].x += pv * v.x; o_r[r].y += pv * v.y;
            }
        }
    }

    #pragma unroll
    for (int r = 0; r < 4; r++) {
        float inv = 1.f / fmaxf(l_r[r], 1e-30f);
        float2 res = make_float2(o_r[r].x * inv, o_r[r].y * inv);
        size_t idx = ((size_t)b * Sn + qbase + wrow0 + r) * Dn + h * 64 + 2 * lane;
        *(float2*)&g_o[idx] = res;
    }
}

// ---------------------------------------------------------------------------
extern "C" void kernel_launch(void* const* d_in, const int* in_sizes, int n_in,
                              void* d_out, int out_size)
{
    const float* x    = (const float*)d_in[0];
    const void*  mask = d_in[1];
    const float* wq   = (const float*)d_in[2];
    const float* wk   = (const float*)d_in[3];
    const float* wv   = (const float*)d_in[4];
    const float* wo   = (const float*)d_in[5];
    float* out = (float*)d_out;

    static int configured = 0;
    if (!configured) {
        cudaFuncSetAttribute(mma_gemm_kernel,
                             cudaFuncAttributeMaxDynamicSharedMemorySize, DYNSM);
        configured = 1;
    }

    detect_mask_kernel<<<1, 256>>>((const uint32_t*)mask);
    const size_t mask_elts = (size_t)Bn * Sn * Sn;
    convert_mask_kernel<<<(unsigned)(mask_elts / 256), 256>>>(mask);

    // Split operands to bf16 hi/lo
    const unsigned nX = (unsigned)((size_t)Mtot * Dn / 1024);   // float4 grids
    const unsigned nW = (unsigned)((size_t)Dn * Dn / 1024);
    __nv_bfloat16 *whi, *wlo, *ahi, *alo;
    cudaGetSymbolAddress((void**)&whi, g_whi);
    cudaGetSymbolAddress((void**)&wlo, g_wlo);
    cudaGetSymbolAddress((void**)&ahi, g_ahi);
    cudaGetSymbolAddress((void**)&alo, g_alo);
    float* go;
    cudaGetSymbolAddress((void**)&go, g_o);

    split_kernel<<<nX, 256>>>(x, ahi, alo);
    split_kernel<<<nW, 256>>>(wq, whi + 0 * (size_t)Dn * Dn, wlo + 0 * (size_t)Dn * Dn);
    split_kernel<<<nW, 256>>>(wk, whi + 1 * (size_t)Dn * Dn, wlo + 1 * (size_t)Dn * Dn);
    split_kernel<<<nW, 256>>>(wv, whi + 2 * (size_t)Dn * Dn, wlo + 2 * (size_t)Dn * Dn);
    split_kernel<<<nW, 256>>>(wo, whi + 3 * (size_t)Dn * Dn, wlo + 3 * (size_t)Dn * Dn);

    // QKV projections (tensor core, split-bf16)
    dim3 g1(Dn / 128, Mtot / 128, 3);
    mma_gemm_kernel<<<g1, 256, DYNSM>>>(ahi, alo, whi, wlo, nullptr, 0);

    dim3 g2(Sn / 32, Bn * Hn);
    attn_kernel<<<g2, 256>>>();

    // Split attention output, then output projection
    split_kernel<<<nX, 256>>>(go, ahi, alo);
    dim3 g3(Dn / 128, Mtot / 128, 1);
    mma_gemm_kernel<<<g3, 256, DYNSM>>>(ahi, alo,
                                        whi + 3 * (size_t)Dn * Dn,
                                        wlo + 3 * (size_t)Dn * Dn, out, 1);
}

// round 5
// speedup vs baseline: 3.0105x; 2.3428x over previous
#include <cuda_runtime.h>
#include <cuda_bf16.h>
#include <stdint.h>

#define Bn 4
#define Sn 2048
#define Dn 1024
#define Hn 16
#define HDn 64
#define Mtot (Bn * Sn)          // 8192

// Scratch (static device globals -- allocation-free per harness rules)
__device__ uint8_t g_mask[(size_t)Bn * Sn * Sn];
__device__ int     g_mask_flag;

// split-bf16 operand buffers
__device__ __nv_bfloat16 g_ahi[(size_t)Mtot * Dn];   // X hi, then attn-out hi
__device__ __nv_bfloat16 g_alo[(size_t)Mtot * Dn];
__device__ __nv_bfloat16 g_whi[(size_t)4 * Dn * Dn]; // wq,wk,wv,wo hi
__device__ __nv_bfloat16 g_wlo[(size_t)4 * Dn * Dn];
__device__ __nv_bfloat16 g_qhi[(size_t)Bn * Hn * Sn * HDn];  // [B,H,S,HD]
__device__ __nv_bfloat16 g_qlo[(size_t)Bn * Hn * Sn * HDn];
__device__ __nv_bfloat16 g_khi[(size_t)Bn * Hn * Sn * HDn];
__device__ __nv_bfloat16 g_klo[(size_t)Bn * Hn * Sn * HDn];
__device__ __nv_bfloat16 g_vhi[(size_t)Bn * Hn * Sn * HDn];
__device__ __nv_bfloat16 g_vlo[(size_t)Bn * Hn * Sn * HDn];

// ===========================================================================
// PTX helpers (base ISA: ldmatrix / mma.sync / cp.async -- no sm_103a gates)
// ===========================================================================
__device__ __forceinline__ uint32_t smem_u32(const void* p) {
    uint32_t a;
    asm("{ .reg .u64 t; cvta.to.shared.u64 t, %1; cvt.u32.u64 %0, t; }" : "=r"(a) : "l"(p));
    return a;
}

#define LDSM4(r0, r1, r2, r3, addr) \
    asm volatile("ldmatrix.sync.aligned.m8n8.x4.shared.b16 {%0,%1,%2,%3}, [%4];" \
        : "=r"(r0), "=r"(r1), "=r"(r2), "=r"(r3) : "r"(addr))

#define LDSM4T(r0, r1, r2, r3, addr) \
    asm volatile("ldmatrix.sync.aligned.m8n8.x4.trans.shared.b16 {%0,%1,%2,%3}, [%4];" \
        : "=r"(r0), "=r"(r1), "=r"(r2), "=r"(r3) : "r"(addr))

#define MMA16816(c, a0, a1, a2, a3, b0, b1) \
    asm volatile("mma.sync.aligned.m16n8k16.row.col.f32.bf16.bf16.f32 " \
        "{%0,%1,%2,%3}, {%4,%5,%6,%7}, {%8,%9}, {%0,%1,%2,%3};" \
        : "+f"((c)[0]), "+f"((c)[1]), "+f"((c)[2]), "+f"((c)[3]) \
        : "r"(a0), "r"(a1), "r"(a2), "r"(a3), "r"(b0), "r"(b1))

#define CPA16(dst, src) \
    asm volatile("cp.async.cg.shared.global [%0], [%1], 16;" :: "r"(dst), "l"(src) : "memory")
#define CPA_COMMIT() asm volatile("cp.async.commit_group;" ::: "memory")
#define CPA_WAIT1()  asm volatile("cp.async.wait_group 1;" ::: "memory")
#define CPA_WAIT0()  asm volatile("cp.async.wait_group 0;" ::: "memory")

// fp32 pair -> packed bf16x2 hi + bf16x2 residual (low half = first element)
__device__ __forceinline__ void split_pair(float p0, float p1, uint32_t& hi, uint32_t& lo) {
    __nv_bfloat162 h = __floats2bfloat162_rn(p0, p1);
    hi = *(uint32_t*)&h;
    float h0 = __bfloat162float(h.x), h1 = __bfloat162float(h.y);
    __nv_bfloat162 l = __floats2bfloat162_rn(p0 - h0, p1 - h1);
    lo = *(uint32_t*)&l;
}

// ===========================================================================
// Mask dtype sniffer + normalizer (known-good)
// ===========================================================================
__global__ void detect_mask_kernel(const uint32_t* __restrict__ m)
{
    __shared__ int cnt_f, cnt_i;
    if (threadIdx.x == 0) { cnt_f = 0; cnt_i = 0; }
    __syncthreads();
    uint32_t w = m[threadIdx.x];
    if (w == 0x3F800000u || w == 0u) atomicAdd(&cnt_f, 1);
    if (w == 1u || w == 0u)          atomicAdd(&cnt_i, 1);
    __syncthreads();
    if (threadIdx.x == 0) {
        int flag = 0;
        if (cnt_f > 200)      flag = 2;
        else if (cnt_i > 200) flag = 1;
        g_mask_flag = flag;
    }
}

__global__ __launch_bounds__(256) void convert_mask_kernel(const void* __restrict__ m)
{
    const size_t i = (size_t)blockIdx.x * 256 + threadIdx.x;
    const int flag = g_mask_flag;
    uint8_t v;
    if (flag == 1)      v = (((const int*)m)[i]   != 0);
    else if (flag == 2) v = (((const float*)m)[i] != 0.0f);
    else                v = (((const uint8_t*)m)[i] != 0);
    g_mask[i] = v;
}

// ===========================================================================
// fp32 -> (bf16 hi, bf16 lo) split.  4 elems/thread via float4.
// ===========================================================================
__global__ __launch_bounds__(256) void split_kernel(
    const float* __restrict__ src,
    __nv_bfloat16* __restrict__ hi,
    __nv_bfloat16* __restrict__ lo)
{
    const size_t i = (size_t)blockIdx.x * 256 + threadIdx.x;
    float4 x = ((const float4*)src)[i];
    uint32_t h0, l0, h1, l1;
    split_pair(x.x, x.y, h0, l0);
    split_pair(x.z, x.w, h1, l1);
    ((uint2*)hi)[i] = make_uint2(h0, h1);
    ((uint2*)lo)[i] = make_uint2(l0, l1);
}

// ===========================================================================
// Split-bf16 tensor-core GEMM: C[128x128] = A[.,1024] @ W[.,1024]^T
// mode 0: write bf16 hi/lo into g_{q,k,v}{hi,lo} by blockIdx.z
// mode 1: dense fp32 store to out
// ===========================================================================
#define KC 32
#define PITCH 40
#define TILE_B (128 * PITCH * 2)
#define STAGE_B (4 * TILE_B)
#define DYNSM (2 * STAGE_B)

__global__ __launch_bounds__(256, 1) void mma_gemm_kernel(
    const __nv_bfloat16* __restrict__ Ahi,
    const __nv_bfloat16* __restrict__ Alo,
    const __nv_bfloat16* __restrict__ Whi,
    const __nv_bfloat16* __restrict__ Wlo,
    float* __restrict__ out,
    int mode)
{
    extern __shared__ char dsm[];
    const uint32_t sbase = smem_u32(dsm);

    const int tid  = threadIdx.x;
    const int lane = tid & 31;
    const int wid  = tid >> 5;
    const int wr   = wid >> 2;
    const int wc   = wid & 3;
    const int bm   = blockIdx.y * 128;
    const int bn   = blockIdx.x * 128;
    const int z    = blockIdx.z;

    const __nv_bfloat16* WhiZ = Whi + (size_t)z * Dn * Dn;
    const __nv_bfloat16* WloZ = Wlo + (size_t)z * Dn * Dn;

    const int grow = tid >> 1;
    const int gh   = tid & 1;
    const size_t aoff = (size_t)(bm + grow) * Dn + gh * 16;
    const size_t woff = (size_t)(bn + grow) * Dn + gh * 16;
    const uint32_t s_off = (uint32_t)grow * (PITCH * 2) + gh * 32;

    float acc[4][4][4];
    #pragma unroll
    for (int i = 0; i < 4; i++)
        #pragma unroll
        for (int j = 0; j < 4; j++)
            #pragma unroll
            for (int v = 0; v < 4; v++) acc[i][j][v] = 0.f;

    uint4 pf[8];
    auto gload = [&](int ck) {
        const size_t o = (size_t)ck * KC;
        pf[0] = *(const uint4*)(Ahi  + aoff + o);
        pf[1] = *(const uint4*)(Ahi  + aoff + o + 8);
        pf[2] = *(const uint4*)(Alo  + aoff + o);
        pf[3] = *(const uint4*)(Alo  + aoff + o + 8);
        pf[4] = *(const uint4*)(WhiZ + woff + o);
        pf[5] = *(const uint4*)(WhiZ + woff + o + 8);
        pf[6] = *(const uint4*)(WloZ + woff + o);
        pf[7] = *(const uint4*)(WloZ + woff + o + 8);
    };
    auto sstore = [&](int s) {
        char* st = dsm + s * STAGE_B;
        #pragma unroll
        for (int tb = 0; tb < 4; tb++) {
            *(uint4*)(st + tb * TILE_B + s_off)      = pf[2 * tb];
            *(uint4*)(st + tb * TILE_B + s_off + 16) = pf[2 * tb + 1];
        }
    };

    gload(0);
    sstore(0);
    __syncthreads();

    const int NC = Dn / KC;
    for (int ck = 0; ck < NC; ck++) {
        const int s = ck & 1;
        if (ck + 1 < NC) gload(ck + 1);

        const uint32_t stg = sbase + s * STAGE_B;
        #pragma unroll
        for (int pass = 0; pass < 3; pass++) {
            const uint32_t aofs = stg + ((pass == 2) ? TILE_B : 0);
            const uint32_t bofs = stg + ((pass == 1) ? 3 * TILE_B : 2 * TILE_B);
            #pragma unroll
            for (int ks = 0; ks < 2; ks++) {
                uint32_t b[4][2];
                #pragma unroll
                for (int jj = 0; jj < 2; jj++) {
                    int n = wc * 32 + jj * 16 + ((lane >> 4) & 1) * 8 + (lane & 7);
                    int k = ks * 16 + ((lane >> 3) & 1) * 8;
                    uint32_t ad = bofs + (uint32_t)(n * PITCH + k) * 2;
                    LDSM4(b[2 * jj][0], b[2 * jj][1], b[2 * jj + 1][0], b[2 * jj + 1][1], ad);
                }
                #pragma unroll
                for (int i = 0; i < 4; i++) {
                    int m = wr * 64 + i * 16 + ((lane >> 3) & 1) * 8 + (lane & 7);
                    int k = ks * 16 + ((lane >> 4) & 1) * 8;
                    uint32_t ad = aofs + (uint32_t)(m * PITCH + k) * 2;
                    uint32_t a0, a1, a2, a3;
                    LDSM4(a0, a1, a2, a3, ad);
                    #pragma unroll
                    for (int j = 0; j < 4; j++)
                        MMA16816(acc[i][j], a0, a1, a2, a3, b[j][0], b[j][1]);
                }
            }
        }

        if (ck + 1 < NC) {
            __syncthreads();
            sstore(s ^ 1);
            __syncthreads();
        }
    }

    // ---- epilogue ----
    #pragma unroll
    for (int i = 0; i < 4; i++) {
        #pragma unroll
        for (int j = 0; j < 4; j++) {
            int ml = wr * 64 + i * 16 + (lane >> 2);
            int nl = wc * 32 + j * 8 + 2 * (lane & 3);
            int m = bm + ml, n = bn + nl;
            if (mode == 0) {
                __nv_bfloat16 *dh, *dl;
                if (z == 0)      { dh = g_qhi; dl = g_qlo; }
                else if (z == 1) { dh = g_khi; dl = g_klo; }
                else             { dh = g_vhi; dl = g_vlo; }
                int bb2 = m >> 11, ss = m & 2047;
                int hh = n >> 6,  hd = n & 63;
                size_t base = (((size_t)bb2 * Hn + hh) * Sn + ss) * HDn + hd;
                uint32_t hp, lp;
                split_pair(acc[i][j][0], acc[i][j][1], hp, lp);
                *(uint32_t*)&dh[base] = hp;  *(uint32_t*)&dl[base] = lp;
                split_pair(acc[i][j][2], acc[i][j][3], hp, lp);
                *(uint32_t*)&dh[base + 8 * HDn] = hp;  *(uint32_t*)&dl[base + 8 * HDn] = lp;
            } else {
                *(float2*)&out[(size_t)m * Dn + n] =
                    make_float2(acc[i][j][0], acc[i][j][1]);
                *(float2*)&out[(size_t)(m + 8) * Dn + n] =
                    make_float2(acc[i][j][2], acc[i][j][3]);
            }
        }
    }
}

// ===========================================================================
// Tensor-core flash attention, split-bf16 both matmuls.
// CTA: 128 q-rows x full K sweep. 8 warps x 16 q-rows.
// smem: Q hi/lo persistent + double-buffered {Kh,Kl,Vh,Vl,mask} via cp.async.
// ===========================================================================
#define AP     72                 // halves per row (144 B)
#define APB    144
#define TILE18 18432              // 128 * 144
#define OFF_KH 0
#define OFF_KL 18432
#define OFF_VH 36864
#define OFF_VL 55296
#define OFF_MK 73728
#define KVBUF  92160              // 5 * 18432
#define QSZ    36864
#define ATT_SMEM (QSZ + 2 * KVBUF)   // 221184

__global__ __launch_bounds__(256, 1) void attn_mma_kernel()
{
    extern __shared__ char smn[];
    const uint32_t sb = smem_u32(smn);
    const int tid = threadIdx.x, lane = tid & 31, w = tid >> 5;
    const int qt = blockIdx.x, bh = blockIdx.y;
    const int b = bh >> 4, h = bh & 15;
    const int qbase = qt * 128;
    const size_t head = (size_t)bh * Sn * HDn;
    const int row = tid >> 1, seg = tid & 1;
    const uint32_t rowb = (uint32_t)row * APB + seg * 64;

    // Q tile (persistent)
    {
        const uint4* qh = (const uint4*)(g_qhi + head + (size_t)(qbase + row) * HDn + seg * 32);
        const uint4* ql = (const uint4*)(g_qlo + head + (size_t)(qbase + row) * HDn + seg * 32);
        uint4* dh = (uint4*)(smn + rowb);
        uint4* dl = (uint4*)(smn + TILE18 + rowb);
        #pragma unroll
        for (int i = 0; i < 4; i++) { dh[i] = qh[i]; dl[i] = ql[i]; }
    }

    const uint8_t* mrow_g = g_mask + ((size_t)b * Sn + qbase + row) * Sn;
    const char* gkh = (const char*)(g_khi + head + (size_t)row * HDn + seg * 32);
    const char* gkl = (const char*)(g_klo + head + (size_t)row * HDn + seg * 32);
    const char* gvh = (const char*)(g_vhi + head + (size_t)row * HDn + seg * 32);
    const char* gvl = (const char*)(g_vlo + head + (size_t)row * HDn + seg * 32);

    auto issue_tile = [&](int kt, int s) {
        const int k0 = kt * 128;
        const uint32_t bb = sb + QSZ + s * KVBUF;
        const size_t go = (size_t)k0 * HDn * 2;    // byte offset for bf16 arrays
        #pragma unroll
        for (int i = 0; i < 4; i++) {
            CPA16(bb + OFF_KH + rowb + i * 16, gkh + go + i * 16);
            CPA16(bb + OFF_KL + rowb + i * 16, gkl + go + i * 16);
            CPA16(bb + OFF_VH + rowb + i * 16, gvh + go + i * 16);
            CPA16(bb + OFF_VL + rowb + i * 16, gvl + go + i * 16);
            CPA16(bb + OFF_MK + rowb + i * 16, (const char*)mrow_g + k0 + seg * 64 + i * 16);
        }
        CPA_COMMIT();
    };

    float o[8][4];
    #pragma unroll
    for (int j = 0; j < 8; j++)
        #pragma unroll
        for (int v = 0; v < 4; v++) o[j][v] = 0.f;
    float m_r0 = -1e30f, m_r1 = -1e30f, l_r0 = 0.f, l_r1 = 0.f;

    const int wq0  = w * 16;
    const int r_lo = lane >> 2, c4 = lane & 3;
    const int mA = wq0 + ((lane >> 3) & 1) * 8 + (lane & 7);
    const int kA = ((lane >> 4) & 1) * 8;
    const uint32_t aQh = sb + (uint32_t)(mA * AP + kA) * 2;
    const uint32_t aQl = aQh + TILE18;
    const int nK = ((lane >> 4) & 1) * 8 + (lane & 7);
    const int kK = ((lane >> 3) & 1) * 8;
    const int kV = ((lane >> 3) & 1) * 8 + (lane & 7);
    const int nV = ((lane >> 4) & 1) * 8;

    issue_tile(0, 0);

    for (int kt = 0; kt < 16; kt++) {
        const int s = kt & 1;
        if (kt < 15) { issue_tile(kt + 1, s ^ 1); CPA_WAIT1(); }
        else         { CPA_WAIT0(); }
        __syncthreads();
        const uint32_t bb = sb + QSZ + s * KVBUF;

        // ---- S = Q K^T (3 split passes) ----
        float sacc[16][4];
        #pragma unroll
        for (int j = 0; j < 16; j++)
            #pragma unroll
            for (int v = 0; v < 4; v++) sacc[j][v] = 0.f;

        #pragma unroll
        for (int ks = 0; ks < 4; ks++) {
            uint32_t ah0, ah1, ah2, ah3, al0, al1, al2, al3;
            LDSM4(ah0, ah1, ah2, ah3, aQh + ks * 32);
            LDSM4(al0, al1, al2, al3, aQl + ks * 32);
            #pragma unroll
            for (int jj = 0; jj < 8; jj++) {
                const int j0 = 2 * jj;
                const uint32_t kaddr = bb + (uint32_t)((j0 * 8 + nK) * AP + ks * 16 + kK) * 2;
                uint32_t b0, b1, b2, b3;
                LDSM4(b0, b1, b2, b3, kaddr + OFF_KH);
                MMA16816(sacc[j0],     ah0, ah1, ah2, ah3, b0, b1);
                MMA16816(sacc[j0 + 1], ah0, ah1, ah2, ah3, b2, b3);
                MMA16816(sacc[j0],     al0, al1, al2, al3, b0, b1);
                MMA16816(sacc[j0 + 1], al0, al1, al2, al3, b2, b3);
                LDSM4(b0, b1, b2, b3, kaddr + OFF_KL);
                MMA16816(sacc[j0],     ah0, ah1, ah2, ah3, b0, b1);
                MMA16816(sacc[j0 + 1], ah0, ah1, ah2, ah3, b2, b3);
            }
        }

        // ---- mask + online softmax ----
        const char* mrp = smn + (QSZ + s * KVBUF + OFF_MK) + (wq0 + r_lo) * APB + 2 * c4;
        float tm0 = -1e30f, tm1 = -1e30f;
        #pragma unroll
        for (int j = 0; j < 16; j++) {
            unsigned short mm1 = *(const unsigned short*)(mrp + j * 8);
            unsigned short mm2 = *(const unsigned short*)(mrp + 8 * APB + j * 8);
            float s0 = (mm1 & 0x00FF) ? sacc[j][0] * 0.125f : -1e30f;
            float s1 = (mm1 & 0xFF00) ? sacc[j][1] * 0.125f : -1e30f;
            float s2 = (mm2 & 0x00FF) ? sacc[j][2] * 0.125f : -1e30f;
            float s3 = (mm2 & 0xFF00) ? sacc[j][3] * 0.125f : -1e30f;
            sacc[j][0] = s0; sacc[j][1] = s1; sacc[j][2] = s2; sacc[j][3] = s3;
            tm0 = fmaxf(tm0, fmaxf(s0, s1));
            tm1 = fmaxf(tm1, fmaxf(s2, s3));
        }
        tm0 = fmaxf(tm0, __shfl_xor_sync(0xffffffffu, tm0, 1));
        tm0 = fmaxf(tm0, __shfl_xor_sync(0xffffffffu, tm0, 2));
        tm1 = fmaxf(tm1, __shfl_xor_sync(0xffffffffu, tm1, 1));
        tm1 = fmaxf(tm1, __shfl_xor_sync(0xffffffffu, tm1, 2));
        const float mn0 = fmaxf(m_r0, tm0), mn1 = fmaxf(m_r1, tm1);
        const float al_0 = __expf(m_r0 - mn0), al_1 = __expf(m_r1 - mn1);
        m_r0 = mn0; m_r1 = mn1;
        float ps0 = 0.f, ps1 = 0.f;
        #pragma unroll
        for (int j = 0; j < 16; j++) {
            float p0 = __expf(sacc[j][0] - mn0); sacc[j][0] = p0; ps0 += p0;
            float p1 = __expf(sacc[j][1] - mn0); sacc[j][1] = p1; ps0 += p1;
            float p2 = __expf(sacc[j][2] - mn1); sacc[j][2] = p2; ps1 += p2;
            float p3 = __expf(sacc[j][3] - mn1); sacc[j][3] = p3; ps1 += p3;
        }
        ps0 += __shfl_xor_sync(0xffffffffu, ps0, 1);
        ps0 += __shfl_xor_sync(0xffffffffu, ps0, 2);
        ps1 += __shfl_xor_sync(0xffffffffu, ps1, 1);
        ps1 += __shfl_xor_sync(0xffffffffu, ps1, 2);
        l_r0 = l_r0 * al_0 + ps0;
        l_r1 = l_r1 * al_1 + ps1;
        #pragma unroll
        for (int j = 0; j < 8; j++) {
            o[j][0] *= al_0; o[j][1] *= al_0; o[j][2] *= al_1; o[j][3] *= al_1;
        }

        // ---- O += P V (3 split passes, V via ldmatrix.trans) ----
        #pragma unroll
        for (int kt2 = 0; kt2 < 8; kt2++) {
            const int j0 = 2 * kt2;
            uint32_t ahi0, ahi1, ahi2, ahi3, alo0, alo1, alo2, alo3;
            split_pair(sacc[j0][0],     sacc[j0][1],     ahi0, alo0);
            split_pair(sacc[j0][2],     sacc[j0][3],     ahi1, alo1);
            split_pair(sacc[j0 + 1][0], sacc[j0 + 1][1], ahi2, alo2);
            split_pair(sacc[j0 + 1][2], sacc[j0 + 1][3], ahi3, alo3);
            #pragma unroll
            for (int jj = 0; jj < 4; jj++) {
                const int jv = 2 * jj;
                const uint32_t va = bb + (uint32_t)((kt2 * 16 + kV) * AP + jv * 8 + nV) * 2;
                uint32_t v0, v1, v2, v3;
                LDSM4T(v0, v1, v2, v3, va + OFF_VH);
                MMA16816(o[jv],     ahi0, ahi1, ahi2, ahi3, v0, v1);
                MMA16816(o[jv + 1], ahi0, ahi1, ahi2, ahi3, v2, v3);
                MMA16816(o[jv],     alo0, alo1, alo2, alo3, v0, v1);
                MMA16816(o[jv + 1], alo0, alo1, alo2, alo3, v2, v3);
                LDSM4T(v0, v1, v2, v3, va + OFF_VL);
                MMA16816(o[jv],     ahi0, ahi1, ahi2, ahi3, v0, v1);
                MMA16816(o[jv + 1], ahi0, ahi1, ahi2, ahi3, v2, v3);
            }
        }
        __syncthreads();
    }

    // ---- epilogue: O/l -> bf16 hi/lo into out-GEMM operand buffers ----
    const float inv0 = 1.f / fmaxf(l_r0, 1e-30f);
    const float inv1 = 1.f / fmaxf(l_r1, 1e-30f);
    const int r1g = qbase + wq0 + r_lo;
    #pragma unroll
    for (int j = 0; j < 8; j++) {
        const size_t idx0 = ((size_t)b * Sn + r1g) * Dn + h * 64 + j * 8 + 2 * c4;
        uint32_t hp, lp;
        split_pair(o[j][0] * inv0, o[j][1] * inv0, hp, lp);
        *(uint32_t*)&g_ahi[idx0] = hp;  *(uint32_t*)&g_alo[idx0] = lp;
        split_pair(o[j][2] * inv1, o[j][3] * inv1, hp, lp);
        *(uint32_t*)&g_ahi[idx0 + 8 * Dn] = hp;  *(uint32_t*)&g_alo[idx0 + 8 * Dn] = lp;
    }
}

// ---------------------------------------------------------------------------
extern "C" void kernel_launch(void* const* d_in, const int* in_sizes, int n_in,
                              void* d_out, int out_size)
{
    const float* x    = (const float*)d_in[0];
    const void*  mask = d_in[1];
    const float* wq   = (const float*)d_in[2];
    const float* wk   = (const float*)d_in[3];
    const float* wv   = (const float*)d_in[4];
    const float* wo   = (const float*)d_in[5];
    float* out = (float*)d_out;

    static int configured = 0;
    if (!configured) {
        cudaFuncSetAttribute(mma_gemm_kernel,
                             cudaFuncAttributeMaxDynamicSharedMemorySize, DYNSM);
        cudaFuncSetAttribute(attn_mma_kernel,
                             cudaFuncAttributeMaxDynamicSharedMemorySize, ATT_SMEM);
        configured = 1;
    }

    detect_mask_kernel<<<1, 256>>>((const uint32_t*)mask);
    const size_t mask_elts = (size_t)Bn * Sn * Sn;
    convert_mask_kernel<<<(unsigned)(mask_elts / 256), 256>>>(mask);

    __nv_bfloat16 *whi, *wlo, *ahi, *alo;
    cudaGetSymbolAddress((void**)&whi, g_whi);
    cudaGetSymbolAddress((void**)&wlo, g_wlo);
    cudaGetSymbolAddress((void**)&ahi, g_ahi);
    cudaGetSymbolAddress((void**)&alo, g_alo);

    const unsigned nX = (unsigned)((size_t)Mtot * Dn / 1024);
    const unsigned nW = (unsigned)((size_t)Dn * Dn / 1024);
    split_kernel<<<nX, 256>>>(x, ahi, alo);
    split_kernel<<<nW, 256>>>(wq, whi + 0 * (size_t)Dn * Dn, wlo + 0 * (size_t)Dn * Dn);
    split_kernel<<<nW, 256>>>(wk, whi + 1 * (size_t)Dn * Dn, wlo + 1 * (size_t)Dn * Dn);
    split_kernel<<<nW, 256>>>(wv, whi + 2 * (size_t)Dn * Dn, wlo + 2 * (size_t)Dn * Dn);
    split_kernel<<<nW, 256>>>(wo, whi + 3 * (size_t)Dn * Dn, wlo + 3 * (size_t)Dn * Dn);

    // QKV projections -> bf16 hi/lo Q/K/V
    dim3 g1(Dn / 128, Mtot / 128, 3);
    mma_gemm_kernel<<<g1, 256, DYNSM>>>(ahi, alo, whi, wlo, nullptr, 0);

    // Tensor-core flash attention -> writes g_ahi/g_alo
    dim3 g2(Sn / 128, Bn * Hn);
    attn_mma_kernel<<<g2, 256, ATT_SMEM>>>();

    // Output projection
    dim3 g3(Dn / 128, Mtot / 128, 1);
    mma_gemm_kernel<<<g3, 256, DYNSM>>>(ahi, alo,
                                        whi + 3 * (size_t)Dn * Dn,
                                        wlo + 3 * (size_t)Dn * Dn, out, 1);
}

// round 6
// speedup vs baseline: 3.9095x; 1.2986x over previous
#include <cuda_runtime.h>
#include <cuda_fp16.h>
#include <stdint.h>

#define Bn 4
#define Sn 2048
#define Dn 1024
#define Hn 16
#define HDn 64
#define Mtot (Bn * Sn)          // 8192

// Scratch (static device globals -- allocation-free per harness rules)
__device__ uint8_t g_mask[(size_t)Bn * Sn * Sn];
__device__ int     g_mask_flag;

// split-fp16 operand buffers (B-side needs hi only)
__device__ __half g_ahi[(size_t)Mtot * Dn];   // X hi, then attn-out hi
__device__ __half g_alo[(size_t)Mtot * Dn];
__device__ __half g_whi[(size_t)4 * Dn * Dn]; // wq,wk,wv,wo hi
__device__ __half g_qhi[(size_t)Bn * Hn * Sn * HDn];  // [B,H,S,HD]
__device__ __half g_qlo[(size_t)Bn * Hn * Sn * HDn];
__device__ __half g_khi[(size_t)Bn * Hn * Sn * HDn];  // hi only
__device__ __half g_vhi[(size_t)Bn * Hn * Sn * HDn];  // hi only

// ===========================================================================
// PTX helpers (base ISA: ldmatrix / mma.sync / cp.async)
// ===========================================================================
__device__ __forceinline__ uint32_t smem_u32(const void* p) {
    uint32_t a;
    asm("{ .reg .u64 t; cvta.to.shared.u64 t, %1; cvt.u32.u64 %0, t; }" : "=r"(a) : "l"(p));
    return a;
}

#define LDSM4(r0, r1, r2, r3, addr) \
    asm volatile("ldmatrix.sync.aligned.m8n8.x4.shared.b16 {%0,%1,%2,%3}, [%4];" \
        : "=r"(r0), "=r"(r1), "=r"(r2), "=r"(r3) : "r"(addr))

#define LDSM4T(r0, r1, r2, r3, addr) \
    asm volatile("ldmatrix.sync.aligned.m8n8.x4.trans.shared.b16 {%0,%1,%2,%3}, [%4];" \
        : "=r"(r0), "=r"(r1), "=r"(r2), "=r"(r3) : "r"(addr))

#define MMA16816(c, a0, a1, a2, a3, b0, b1) \
    asm volatile("mma.sync.aligned.m16n8k16.row.col.f32.f16.f16.f32 " \
        "{%0,%1,%2,%3}, {%4,%5,%6,%7}, {%8,%9}, {%0,%1,%2,%3};" \
        : "+f"((c)[0]), "+f"((c)[1]), "+f"((c)[2]), "+f"((c)[3]) \
        : "r"(a0), "r"(a1), "r"(a2), "r"(a3), "r"(b0), "r"(b1))

#define CPA16(dst, src) \
    asm volatile("cp.async.cg.shared.global [%0], [%1], 16;" :: "r"(dst), "l"(src) : "memory")
#define CPA_COMMIT() asm volatile("cp.async.commit_group;" ::: "memory")
#define CPA_WAIT1()  asm volatile("cp.async.wait_group 1;" ::: "memory")
#define CPA_WAIT0()  asm volatile("cp.async.wait_group 0;" ::: "memory")

// fp32 pair -> packed fp16x2 hi + fp16x2 residual
__device__ __forceinline__ void split_pair(float p0, float p1, uint32_t& hi, uint32_t& lo) {
    __half2 h = __floats2half2_rn(p0, p1);
    hi = *(uint32_t*)&h;
    float h0 = __low2float(h), h1 = __high2float(h);
    __half2 l = __floats2half2_rn(p0 - h0, p1 - h1);
    lo = *(uint32_t*)&l;
}

// ===========================================================================
// Mask dtype sniffer + normalizer (known-good)
// ===========================================================================
__global__ void detect_mask_kernel(const uint32_t* __restrict__ m)
{
    __shared__ int cnt_f, cnt_i;
    if (threadIdx.x == 0) { cnt_f = 0; cnt_i = 0; }
    __syncthreads();
    uint32_t w = m[threadIdx.x];
    if (w == 0x3F800000u || w == 0u) atomicAdd(&cnt_f, 1);
    if (w == 1u || w == 0u)          atomicAdd(&cnt_i, 1);
    __syncthreads();
    if (threadIdx.x == 0) {
        int flag = 0;
        if (cnt_f > 200)      flag = 2;
        else if (cnt_i > 200) flag = 1;
        g_mask_flag = flag;
    }
}

__global__ __launch_bounds__(256) void convert_mask_kernel(const void* __restrict__ m)
{
    const size_t i = (size_t)blockIdx.x * 256 + threadIdx.x;
    const int flag = g_mask_flag;
    uint8_t v;
    if (flag == 1)      v = (((const int*)m)[i]   != 0);
    else if (flag == 2) v = (((const float*)m)[i] != 0.0f);
    else                v = (((const uint8_t*)m)[i] != 0);
    g_mask[i] = v;
}

// ===========================================================================
// fp32 -> (fp16 hi, fp16 lo) split for X;  fp32 -> fp16 hi-only for weights
// ===========================================================================
__global__ __launch_bounds__(256) void split_x_kernel(
    const float* __restrict__ src,
    __half* __restrict__ hi,
    __half* __restrict__ lo)
{
    const size_t i = (size_t)blockIdx.x * 256 + threadIdx.x;
    float4 x = ((const float4*)src)[i];
    uint32_t h0, l0, h1, l1;
    split_pair(x.x, x.y, h0, l0);
    split_pair(x.z, x.w, h1, l1);
    ((uint2*)hi)[i] = make_uint2(h0, h1);
    ((uint2*)lo)[i] = make_uint2(l0, l1);
}

__global__ __launch_bounds__(256) void cvt_w_kernel(
    const float* __restrict__ w0, const float* __restrict__ w1,
    const float* __restrict__ w2, const float* __restrict__ w3)
{
    const int z = blockIdx.y;
    const float* src = (z == 0) ? w0 : (z == 1) ? w1 : (z == 2) ? w2 : w3;
    const size_t i = (size_t)blockIdx.x * 256 + threadIdx.x;
    float4 x = ((const float4*)src)[i];
    __half2 a = __floats2half2_rn(x.x, x.y);
    __half2 b = __floats2half2_rn(x.z, x.w);
    ((uint2*)(g_whi + (size_t)z * Dn * Dn))[i] =
        make_uint2(*(uint32_t*)&a, *(uint32_t*)&b);
}

// ===========================================================================
// Split-fp16 2-pass tensor-core GEMM: C[128x128] = A[.,1024] @ W[.,1024]^T
//   D = Ah*Bh + Al*Bh   (cp.async 2-stage pipeline)
// mode 0: z picks q (hi+lo) / k (hi) / v (hi) epilogue; mode 1: fp32 to out.
// ===========================================================================
#define KC 32
#define PITCH 40                 // halves per smem row (80 B)
#define TILE_B (128 * PITCH * 2) // 10240
#define STG (3 * TILE_B)         // Ah, Al, Bh = 30720
#define DYNSM (2 * STG)          // 61440

__global__ __launch_bounds__(256, 1) void mma_gemm_kernel(
    const __half* __restrict__ Ahi,
    const __half* __restrict__ Alo,
    const __half* __restrict__ Whi,
    float* __restrict__ out,
    int mode)
{
    extern __shared__ char dsm[];
    const uint32_t sbase = smem_u32(dsm);

    const int tid  = threadIdx.x;
    const int lane = tid & 31;
    const int wid  = tid >> 5;
    const int wr   = wid >> 2;
    const int wc   = wid & 3;
    const int bm   = blockIdx.y * 128;
    const int bn   = blockIdx.x * 128;
    const int z    = blockIdx.z;

    const __half* WhiZ = Whi + (size_t)z * Dn * Dn;

    const int row = tid >> 1;
    const int gh  = tid & 1;
    const __half* sA_h = Ahi  + (size_t)(bm + row) * Dn + gh * 16;
    const __half* sA_l = Alo  + (size_t)(bm + row) * Dn + gh * 16;
    const __half* sB_h = WhiZ + (size_t)(bn + row) * Dn + gh * 16;
    const uint32_t sd0 = sbase + (uint32_t)row * (PITCH * 2) + gh * 32;

    const int NC = Dn / KC;     // 32
    auto issue = [&](int ck) {
        const uint32_t sd = sd0 + (ck & 1) * STG;
        const size_t o = (size_t)ck * KC;
        CPA16(sd,                     sA_h + o);
        CPA16(sd + 16,                sA_h + o + 8);
        CPA16(sd + TILE_B,            sA_l + o);
        CPA16(sd + TILE_B + 16,       sA_l + o + 8);
        CPA16(sd + 2 * TILE_B,        sB_h + o);
        CPA16(sd + 2 * TILE_B + 16,   sB_h + o + 8);
        CPA_COMMIT();
    };

    float acc[4][4][4];
    #pragma unroll
    for (int i = 0; i < 4; i++)
        #pragma unroll
        for (int j = 0; j < 4; j++)
            #pragma unroll
            for (int v = 0; v < 4; v++) acc[i][j][v] = 0.f;

    issue(0);
    issue(1);

    for (int ck = 0; ck < NC; ck++) {
        if (ck == NC - 1) { CPA_WAIT0(); } else { CPA_WAIT1(); }
        __syncthreads();

        const uint32_t stg = sbase + (ck & 1) * STG;
        #pragma unroll
        for (int ks = 0; ks < 2; ks++) {
            uint32_t b[4][2];
            #pragma unroll
            for (int jj = 0; jj < 2; jj++) {
                int n = wc * 32 + jj * 16 + ((lane >> 4) & 1) * 8 + (lane & 7);
                int k = ks * 16 + ((lane >> 3) & 1) * 8;
                uint32_t ad = stg + 2 * TILE_B + (uint32_t)(n * PITCH + k) * 2;
                LDSM4(b[2 * jj][0], b[2 * jj][1], b[2 * jj + 1][0], b[2 * jj + 1][1], ad);
            }
            #pragma unroll
            for (int i = 0; i < 4; i++) {
                int m = wr * 64 + i * 16 + ((lane >> 3) & 1) * 8 + (lane & 7);
                int k = ks * 16 + ((lane >> 4) & 1) * 8;
                uint32_t adh = stg + (uint32_t)(m * PITCH + k) * 2;
                uint32_t a0, a1, a2, a3;
                LDSM4(a0, a1, a2, a3, adh);
                #pragma unroll
                for (int j = 0; j < 4; j++)
                    MMA16816(acc[i][j], a0, a1, a2, a3, b[j][0], b[j][1]);
                LDSM4(a0, a1, a2, a3, adh + TILE_B);
                #pragma unroll
                for (int j = 0; j < 4; j++)
                    MMA16816(acc[i][j], a0, a1, a2, a3, b[j][0], b[j][1]);
            }
        }
        __syncthreads();
        if (ck + 2 < NC) issue(ck + 2);
    }

    // ---- epilogue ----
    #pragma unroll
    for (int i = 0; i < 4; i++) {
        #pragma unroll
        for (int j = 0; j < 4; j++) {
            int ml = wr * 64 + i * 16 + (lane >> 2);
            int nl = wc * 32 + j * 8 + 2 * (lane & 3);
            int m = bm + ml, n = bn + nl;
            if (mode == 0) {
                int bb2 = m >> 11, ss = m & 2047;
                int hh = n >> 6,  hd = n & 63;
                size_t base = (((size_t)bb2 * Hn + hh) * Sn + ss) * HDn + hd;
                uint32_t hp, lp;
                if (z == 0) {
                    split_pair(acc[i][j][0], acc[i][j][1], hp, lp);
                    *(uint32_t*)&g_qhi[base] = hp;  *(uint32_t*)&g_qlo[base] = lp;
                    split_pair(acc[i][j][2], acc[i][j][3], hp, lp);
                    *(uint32_t*)&g_qhi[base + 8 * HDn] = hp;
                    *(uint32_t*)&g_qlo[base + 8 * HDn] = lp;
                } else {
                    __half* dh = (z == 1) ? g_khi : g_vhi;
                    __half2 h = __floats2half2_rn(acc[i][j][0], acc[i][j][1]);
                    *(uint32_t*)&dh[base] = *(uint32_t*)&h;
                    h = __floats2half2_rn(acc[i][j][2], acc[i][j][3]);
                    *(uint32_t*)&dh[base + 8 * HDn] = *(uint32_t*)&h;
                }
            } else {
                *(float2*)&out[(size_t)m * Dn + n] =
                    make_float2(acc[i][j][0], acc[i][j][1]);
                *(float2*)&out[(size_t)(m + 8) * Dn + n] =
                    make_float2(acc[i][j][2], acc[i][j][3]);
            }
        }
    }
}

// ===========================================================================
// Tensor-core flash attention, split-fp16 2-pass both matmuls.
// CTA: 128 q-rows x full K sweep. 8 warps x 16 rows.
// smem: Qh/Ql persistent + double-buffered {Kh, Vh, mask} via cp.async.
// ===========================================================================
#define AP     72                 // halves per row (144 B)
#define APB    144
#define TILE18 18432              // 128 * 144
#define OFF_KH 0
#define OFF_VH 18432
#define OFF_MK 36864
#define KVBUF  55296              // 3 * 18432
#define QSZ    36864
#define ATT_SMEM (QSZ + 2 * KVBUF)   // 147456

__global__ __launch_bounds__(256, 1) void attn_mma_kernel()
{
    extern __shared__ char smn[];
    const uint32_t sb = smem_u32(smn);
    const int tid = threadIdx.x, lane = tid & 31, w = tid >> 5;
    const int qt = blockIdx.x, bh = blockIdx.y;
    const int b = bh >> 4, h = bh & 15;
    const int qbase = qt * 128;
    const size_t head = (size_t)bh * Sn * HDn;
    const int row = tid >> 1, seg = tid & 1;
    const uint32_t rowb = (uint32_t)row * APB + seg * 64;

    // Q tile (persistent, hi + lo)
    {
        const uint4* qh = (const uint4*)(g_qhi + head + (size_t)(qbase + row) * HDn + seg * 32);
        const uint4* ql = (const uint4*)(g_qlo + head + (size_t)(qbase + row) * HDn + seg * 32);
        uint4* dh = (uint4*)(smn + rowb);
        uint4* dl = (uint4*)(smn + TILE18 + rowb);
        #pragma unroll
        for (int i = 0; i < 4; i++) { dh[i] = qh[i]; dl[i] = ql[i]; }
    }

    const uint8_t* mrow_g = g_mask + ((size_t)b * Sn + qbase + row) * Sn;
    const char* gkh = (const char*)(g_khi + head + (size_t)row * HDn + seg * 32);
    const char* gvh = (const char*)(g_vhi + head + (size_t)row * HDn + seg * 32);

    auto issue_tile = [&](int kt, int s) {
        const int k0 = kt * 128;
        const uint32_t bb = sb + QSZ + s * KVBUF;
        const size_t go = (size_t)k0 * HDn * 2;
        #pragma unroll
        for (int i = 0; i < 4; i++) {
            CPA16(bb + OFF_KH + rowb + i * 16, gkh + go + i * 16);
            CPA16(bb + OFF_VH + rowb + i * 16, gvh + go + i * 16);
            CPA16(bb + OFF_MK + rowb + i * 16, (const char*)mrow_g + k0 + seg * 64 + i * 16);
        }
        CPA_COMMIT();
    };

    float o[8][4];
    #pragma unroll
    for (int j = 0; j < 8; j++)
        #pragma unroll
        for (int v = 0; v < 4; v++) o[j][v] = 0.f;
    float m_r0 = -1e30f, m_r1 = -1e30f, l_r0 = 0.f, l_r1 = 0.f;

    const int wq0  = w * 16;
    const int r_lo = lane >> 2, c4 = lane & 3;
    const int mA = wq0 + ((lane >> 3) & 1) * 8 + (lane & 7);
    const int kA = ((lane >> 4) & 1) * 8;
    const uint32_t aQh = sb + (uint32_t)(mA * AP + kA) * 2;
    const uint32_t aQl = aQh + TILE18;
    const int nK = ((lane >> 4) & 1) * 8 + (lane & 7);
    const int kK = ((lane >> 3) & 1) * 8;
    const int kV = ((lane >> 3) & 1) * 8 + (lane & 7);
    const int nV = ((lane >> 4) & 1) * 8;

    issue_tile(0, 0);

    for (int kt = 0; kt < 16; kt++) {
        const int s = kt & 1;
        if (kt < 15) { issue_tile(kt + 1, s ^ 1); CPA_WAIT1(); }
        else         { CPA_WAIT0(); }
        __syncthreads();
        const uint32_t bb = sb + QSZ + s * KVBUF;

        // ---- S = Q K^T  (Qh*Kh + Ql*Kh) ----
        float sacc[16][4];
        #pragma unroll
        for (int j = 0; j < 16; j++)
            #pragma unroll
            for (int v = 0; v < 4; v++) sacc[j][v] = 0.f;

        #pragma unroll
        for (int ks = 0; ks < 4; ks++) {
            uint32_t ah0, ah1, ah2, ah3, al0, al1, al2, al3;
            LDSM4(ah0, ah1, ah2, ah3, aQh + ks * 32);
            LDSM4(al0, al1, al2, al3, aQl + ks * 32);
            #pragma unroll
            for (int jj = 0; jj < 8; jj++) {
                const int j0 = 2 * jj;
                const uint32_t kaddr =
                    bb + OFF_KH + (uint32_t)((j0 * 8 + nK) * AP + ks * 16 + kK) * 2;
                uint32_t b0, b1, b2, b3;
                LDSM4(b0, b1, b2, b3, kaddr);
                MMA16816(sacc[j0],     ah0, ah1, ah2, ah3, b0, b1);
                MMA16816(sacc[j0 + 1], ah0, ah1, ah2, ah3, b2, b3);
                MMA16816(sacc[j0],     al0, al1, al2, al3, b0, b1);
                MMA16816(sacc[j0 + 1], al0, al1, al2, al3, b2, b3);
            }
        }

        // ---- mask + online softmax ----
        const char* mrp = smn + (QSZ + s * KVBUF + OFF_MK) + (wq0 + r_lo) * APB + 2 * c4;
        float tm0 = -1e30f, tm1 = -1e30f;
        #pragma unroll
        for (int j = 0; j < 16; j++) {
            unsigned short mm1 = *(const unsigned short*)(mrp + j * 8);
            unsigned short mm2 = *(const unsigned short*)(mrp + 8 * APB + j * 8);
            float s0 = (mm1 & 0x00FF) ? sacc[j][0] * 0.125f : -1e30f;
            float s1 = (mm1 & 0xFF00) ? sacc[j][1] * 0.125f : -1e30f;
            float s2 = (mm2 & 0x00FF) ? sacc[j][2] * 0.125f : -1e30f;
            float s3 = (mm2 & 0xFF00) ? sacc[j][3] * 0.125f : -1e30f;
            sacc[j][0] = s0; sacc[j][1] = s1; sacc[j][2] = s2; sacc[j][3] = s3;
            tm0 = fmaxf(tm0, fmaxf(s0, s1));
            tm1 = fmaxf(tm1, fmaxf(s2, s3));
        }
        tm0 = fmaxf(tm0, __shfl_xor_sync(0xffffffffu, tm0, 1));
        tm0 = fmaxf(tm0, __shfl_xor_sync(0xffffffffu, tm0, 2));
        tm1 = fmaxf(tm1, __shfl_xor_sync(0xffffffffu, tm1, 1));
        tm1 = fmaxf(tm1, __shfl_xor_sync(0xffffffffu, tm1, 2));
        const float mn0 = fmaxf(m_r0, tm0), mn1 = fmaxf(m_r1, tm1);
        const float al_0 = __expf(m_r0 - mn0), al_1 = __expf(m_r1 - mn1);
        m_r0 = mn0; m_r1 = mn1;
        float ps0 = 0.f, ps1 = 0.f;
        #pragma unroll
        for (int j = 0; j < 16; j++) {
            float p0 = __expf(sacc[j][0] - mn0); sacc[j][0] = p0; ps0 += p0;
            float p1 = __expf(sacc[j][1] - mn0); sacc[j][1] = p1; ps0 += p1;
            float p2 = __expf(sacc[j][2] - mn1); sacc[j][2] = p2; ps1 += p2;
            float p3 = __expf(sacc[j][3] - mn1); sacc[j][3] = p3; ps1 += p3;
        }
        ps0 += __shfl_xor_sync(0xffffffffu, ps0, 1);
        ps0 += __shfl_xor_sync(0xffffffffu, ps0, 2);
        ps1 += __shfl_xor_sync(0xffffffffu, ps1, 1);
        ps1 += __shfl_xor_sync(0xffffffffu, ps1, 2);
        l_r0 = l_r0 * al_0 + ps0;
        l_r1 = l_r1 * al_1 + ps1;
        #pragma unroll
        for (int j = 0; j < 8; j++) {
            o[j][0] *= al_0; o[j][1] *= al_0; o[j][2] *= al_1; o[j][3] *= al_1;
        }

        // ---- O += P V  (Ph*Vh + Pl*Vh, V via ldmatrix.trans) ----
        #pragma unroll
        for (int kt2 = 0; kt2 < 8; kt2++) {
            const int j0 = 2 * kt2;
            uint32_t ahi0, ahi1, ahi2, ahi3, alo0, alo1, alo2, alo3;
            split_pair(sacc[j0][0],     sacc[j0][1],     ahi0, alo0);
            split_pair(sacc[j0][2],     sacc[j0][3],     ahi1, alo1);
            split_pair(sacc[j0 + 1][0], sacc[j0 + 1][1], ahi2, alo2);
            split_pair(sacc[j0 + 1][2], sacc[j0 + 1][3], ahi3, alo3);
            #pragma unroll
            for (int jj = 0; jj < 4; jj++) {
                const int jv = 2 * jj;
                const uint32_t va =
                    bb + OFF_VH + (uint32_t)((kt2 * 16 + kV) * AP + jv * 8 + nV) * 2;
                uint32_t v0, v1, v2, v3;
                LDSM4T(v0, v1, v2, v3, va);
                MMA16816(o[jv],     ahi0, ahi1, ahi2, ahi3, v0, v1);
                MMA16816(o[jv + 1], ahi0, ahi1, ahi2, ahi3, v2, v3);
                MMA16816(o[jv],     alo0, alo1, alo2, alo3, v0, v1);
                MMA16816(o[jv + 1], alo0, alo1, alo2, alo3, v2, v3);
            }
        }
        __syncthreads();
    }

    // ---- epilogue: O/l -> fp16 hi/lo into out-GEMM operand buffers ----
    const float inv0 = 1.f / fmaxf(l_r0, 1e-30f);
    const float inv1 = 1.f / fmaxf(l_r1, 1e-30f);
    const int r1g = qbase + wq0 + r_lo;
    #pragma unroll
    for (int j = 0; j < 8; j++) {
        const size_t idx0 = ((size_t)b * Sn + r1g) * Dn + h * 64 + j * 8 + 2 * c4;
        uint32_t hp, lp;
        split_pair(o[j][0] * inv0, o[j][1] * inv0, hp, lp);
        *(uint32_t*)&g_ahi[idx0] = hp;  *(uint32_t*)&g_alo[idx0] = lp;
        split_pair(o[j][2] * inv1, o[j][3] * inv1, hp, lp);
        *(uint32_t*)&g_ahi[idx0 + 8 * Dn] = hp;  *(uint32_t*)&g_alo[idx0 + 8 * Dn] = lp;
    }
}

// ---------------------------------------------------------------------------
extern "C" void kernel_launch(void* const* d_in, const int* in_sizes, int n_in,
                              void* d_out, int out_size)
{
    const float* x    = (const float*)d_in[0];
    const void*  mask = d_in[1];
    const float* wq   = (const float*)d_in[2];
    const float* wk   = (const float*)d_in[3];
    const float* wv   = (const float*)d_in[4];
    const float* wo   = (const float*)d_in[5];
    float* out = (float*)d_out;

    cudaFuncSetAttribute(mma_gemm_kernel,
                         cudaFuncAttributeMaxDynamicSharedMemorySize, DYNSM);
    cudaFuncSetAttribute(attn_mma_kernel,
                         cudaFuncAttributeMaxDynamicSharedMemorySize, ATT_SMEM);

    detect_mask_kernel<<<1, 256>>>((const uint32_t*)mask);
    const size_t mask_elts = (size_t)Bn * Sn * Sn;
    convert_mask_kernel<<<(unsigned)(mask_elts / 256), 256>>>(mask);

    __half *ahi, *alo, *whi;
    cudaGetSymbolAddress((void**)&ahi, g_ahi);
    cudaGetSymbolAddress((void**)&alo, g_alo);
    cudaGetSymbolAddress((void**)&whi, g_whi);

    const unsigned nX = (unsigned)((size_t)Mtot * Dn / 1024);
    const unsigned nW = (unsigned)((size_t)Dn * Dn / 1024);
    split_x_kernel<<<nX, 256>>>(x, ahi, alo);
    dim3 gw(nW, 4);
    cvt_w_kernel<<<gw, 256>>>(wq, wk, wv, wo);

    // QKV projections -> fp16 Q(hi,lo), K(hi), V(hi)
    dim3 g1(Dn / 128, Mtot / 128, 3);
    mma_gemm_kernel<<<g1, 256, DYNSM>>>(ahi, alo, whi, nullptr, 0);

    // Tensor-core flash attention -> writes g_ahi/g_alo
    dim3 g2(Sn / 128, Bn * Hn);
    attn_mma_kernel<<<g2, 256, ATT_SMEM>>>();

    // Output projection
    dim3 g3(Dn / 128, Mtot / 128, 1);
    mma_gemm_kernel<<<g3, 256, DYNSM>>>(ahi, alo,
                                        whi + 3 * (size_t)Dn * Dn, out, 1);
}

// round 7
// speedup vs baseline: 4.5163x; 1.1552x over previous
#include <cuda_runtime.h>
#include <cuda_fp16.h>
#include <stdint.h>

#define Bn 4
#define Sn 2048
#define Dn 1024
#define Hn 16
#define HDn 64
#define Mtot (Bn * Sn)          // 8192

// Scratch (static device globals -- allocation-free per harness rules)
__device__ uint32_t g_maskbits[(size_t)Bn * Sn * Sn / 32];   // 1 bit / elt
__device__ int      g_mask_flag;

// split-fp16 operand buffers
__device__ __half g_ahi[(size_t)Mtot * Dn];   // X hi, then attn-out hi
__device__ __half g_alo[(size_t)Mtot * Dn];
__device__ __half g_whi[(size_t)4 * Dn * Dn]; // wq,wk,wv,wo hi
__device__ __half g_qhi[(size_t)Bn * Hn * Sn * HDn];  // [B,H,S,HD] hi only
__device__ __half g_khi[(size_t)Bn * Hn * Sn * HDn];
__device__ __half g_vhi[(size_t)Bn * Hn * Sn * HDn];

// ===========================================================================
// PTX helpers (base ISA: ldmatrix / mma.sync / cp.async)
// ===========================================================================
__device__ __forceinline__ uint32_t smem_u32(const void* p) {
    uint32_t a;
    asm("{ .reg .u64 t; cvta.to.shared.u64 t, %1; cvt.u32.u64 %0, t; }" : "=r"(a) : "l"(p));
    return a;
}

#define LDSM4(r0, r1, r2, r3, addr) \
    asm volatile("ldmatrix.sync.aligned.m8n8.x4.shared.b16 {%0,%1,%2,%3}, [%4];" \
        : "=r"(r0), "=r"(r1), "=r"(r2), "=r"(r3) : "r"(addr))

#define LDSM4T(r0, r1, r2, r3, addr) \
    asm volatile("ldmatrix.sync.aligned.m8n8.x4.trans.shared.b16 {%0,%1,%2,%3}, [%4];" \
        : "=r"(r0), "=r"(r1), "=r"(r2), "=r"(r3) : "r"(addr))

#define MMA16816(c, a0, a1, a2, a3, b0, b1) \
    asm volatile("mma.sync.aligned.m16n8k16.row.col.f32.f16.f16.f32 " \
        "{%0,%1,%2,%3}, {%4,%5,%6,%7}, {%8,%9}, {%0,%1,%2,%3};" \
        : "+f"((c)[0]), "+f"((c)[1]), "+f"((c)[2]), "+f"((c)[3]) \
        : "r"(a0), "r"(a1), "r"(a2), "r"(a3), "r"(b0), "r"(b1))

#define CPA16(dst, src) \
    asm volatile("cp.async.cg.shared.global [%0], [%1], 16;" :: "r"(dst), "l"(src) : "memory")
#define CPA_COMMIT() asm volatile("cp.async.commit_group;" ::: "memory")
#define CPA_WAIT1()  asm volatile("cp.async.wait_group 1;" ::: "memory")
#define CPA_WAIT0()  asm volatile("cp.async.wait_group 0;" ::: "memory")

// fp32 pair -> packed fp16x2 hi + fp16x2 residual
__device__ __forceinline__ void split_pair(float p0, float p1, uint32_t& hi, uint32_t& lo) {
    __half2 h = __floats2half2_rn(p0, p1);
    hi = *(uint32_t*)&h;
    float h0 = __low2float(h), h1 = __high2float(h);
    __half2 l = __floats2half2_rn(p0 - h0, p1 - h1);
    lo = *(uint32_t*)&l;
}

// ===========================================================================
// Mask: dtype sniffer + ballot bit-packer
// ===========================================================================
__global__ void detect_mask_kernel(const uint32_t* __restrict__ m)
{
    __shared__ int cnt_w;
    if (threadIdx.x == 0) cnt_w = 0;
    __syncthreads();
    uint32_t w = m[threadIdx.x];
    // int32 mask words are 0/1; float32 words are 0/0x3F800000; uint8 words
    // are 4 packed bytes (e.g. 0x01010101) -- rarely plain 0/1.
    if (w == 0u || w == 1u || w == 0x3F800000u) atomicAdd(&cnt_w, 1);
    __syncthreads();
    if (threadIdx.x == 0) g_mask_flag = (cnt_w > 200) ? 1 : 0;  // 1 = 4-byte elems
}

__global__ __launch_bounds__(256) void pack_mask_kernel(const void* __restrict__ m)
{
    const size_t i = (size_t)blockIdx.x * 256 + threadIdx.x;   // element index
    bool v;
    if (g_mask_flag)
        v = ((const uint32_t*)m)[i] != 0u;   // int32 or float32: nonzero bits
    else
        v = ((const uint8_t*)m)[i] != 0;
    uint32_t w = __ballot_sync(0xffffffffu, v);
    if ((threadIdx.x & 31) == 0) g_maskbits[i >> 5] = w;
}

// ===========================================================================
// fp32 -> (fp16 hi, fp16 lo) split for X;  fp32 -> fp16 hi-only for weights
// ===========================================================================
__global__ __launch_bounds__(256) void split_x_kernel(
    const float* __restrict__ src,
    __half* __restrict__ hi,
    __half* __restrict__ lo)
{
    const size_t i = (size_t)blockIdx.x * 256 + threadIdx.x;
    float4 x = ((const float4*)src)[i];
    uint32_t h0, l0, h1, l1;
    split_pair(x.x, x.y, h0, l0);
    split_pair(x.z, x.w, h1, l1);
    ((uint2*)hi)[i] = make_uint2(h0, h1);
    ((uint2*)lo)[i] = make_uint2(l0, l1);
}

__global__ __launch_bounds__(256) void cvt_w_kernel(
    const float* __restrict__ w0, const float* __restrict__ w1,
    const float* __restrict__ w2, const float* __restrict__ w3)
{
    const int z = blockIdx.y;
    const float* src = (z == 0) ? w0 : (z == 1) ? w1 : (z == 2) ? w2 : w3;
    const size_t i = (size_t)blockIdx.x * 256 + threadIdx.x;
    float4 x = ((const float4*)src)[i];
    __half2 a = __floats2half2_rn(x.x, x.y);
    __half2 b = __floats2half2_rn(x.z, x.w);
    ((uint2*)(g_whi + (size_t)z * Dn * Dn))[i] =
        make_uint2(*(uint32_t*)&a, *(uint32_t*)&b);
}

// ===========================================================================
// Split-fp16 2-pass tensor-core GEMM: C[128x128] = A[.,1024] @ W[.,1024]^T
//   D = Ah*Bh + Al*Bh   (cp.async 2-stage pipeline)
// mode 0: write fp16 hi into g_q/k/v by blockIdx.z; mode 1: fp32 to out.
// ===========================================================================
#define KC 32
#define PITCH 40                 // halves per smem row (80 B)
#define TILE_B (128 * PITCH * 2) // 10240
#define STG (3 * TILE_B)         // Ah, Al, Bh = 30720
#define DYNSM (2 * STG)          // 61440

__global__ __launch_bounds__(256, 1) void mma_gemm_kernel(
    const __half* __restrict__ Ahi,
    const __half* __restrict__ Alo,
    const __half* __restrict__ Whi,
    float* __restrict__ out,
    int mode)
{
    extern __shared__ char dsm[];
    const uint32_t sbase = smem_u32(dsm);

    const int tid  = threadIdx.x;
    const int lane = tid & 31;
    const int wid  = tid >> 5;
    const int wr   = wid >> 2;
    const int wc   = wid & 3;
    const int bm   = blockIdx.y * 128;
    const int bn   = blockIdx.x * 128;
    const int z    = blockIdx.z;

    const __half* WhiZ = Whi + (size_t)z * Dn * Dn;

    const int row = tid >> 1;
    const int gh  = tid & 1;
    const __half* sA_h = Ahi  + (size_t)(bm + row) * Dn + gh * 16;
    const __half* sA_l = Alo  + (size_t)(bm + row) * Dn + gh * 16;
    const __half* sB_h = WhiZ + (size_t)(bn + row) * Dn + gh * 16;
    const uint32_t sd0 = sbase + (uint32_t)row * (PITCH * 2) + gh * 32;

    const int NC = Dn / KC;     // 32
    auto issue = [&](int ck) {
        const uint32_t sd = sd0 + (ck & 1) * STG;
        const size_t o = (size_t)ck * KC;
        CPA16(sd,                     sA_h + o);
        CPA16(sd + 16,                sA_h + o + 8);
        CPA16(sd + TILE_B,            sA_l + o);
        CPA16(sd + TILE_B + 16,       sA_l + o + 8);
        CPA16(sd + 2 * TILE_B,        sB_h + o);
        CPA16(sd + 2 * TILE_B + 16,   sB_h + o + 8);
        CPA_COMMIT();
    };

    float acc[4][4][4];
    #pragma unroll
    for (int i = 0; i < 4; i++)
        #pragma unroll
        for (int j = 0; j < 4; j++)
            #pragma unroll
            for (int v = 0; v < 4; v++) acc[i][j][v] = 0.f;

    issue(0);
    issue(1);

    for (int ck = 0; ck < NC; ck++) {
        if (ck == NC - 1) { CPA_WAIT0(); } else { CPA_WAIT1(); }
        __syncthreads();

        const uint32_t stg = sbase + (ck & 1) * STG;
        #pragma unroll
        for (int ks = 0; ks < 2; ks++) {
            uint32_t b[4][2];
            #pragma unroll
            for (int jj = 0; jj < 2; jj++) {
                int n = wc * 32 + jj * 16 + ((lane >> 4) & 1) * 8 + (lane & 7);
                int k = ks * 16 + ((lane >> 3) & 1) * 8;
                uint32_t ad = stg + 2 * TILE_B + (uint32_t)(n * PITCH + k) * 2;
                LDSM4(b[2 * jj][0], b[2 * jj][1], b[2 * jj + 1][0], b[2 * jj + 1][1], ad);
            }
            #pragma unroll
            for (int i = 0; i < 4; i++) {
                int m = wr * 64 + i * 16 + ((lane >> 3) & 1) * 8 + (lane & 7);
                int k = ks * 16 + ((lane >> 4) & 1) * 8;
                uint32_t adh = stg + (uint32_t)(m * PITCH + k) * 2;
                uint32_t a0, a1, a2, a3;
                LDSM4(a0, a1, a2, a3, adh);
                #pragma unroll
                for (int j = 0; j < 4; j++)
                    MMA16816(acc[i][j], a0, a1, a2, a3, b[j][0], b[j][1]);
                LDSM4(a0, a1, a2, a3, adh + TILE_B);
                #pragma unroll
                for (int j = 0; j < 4; j++)
                    MMA16816(acc[i][j], a0, a1, a2, a3, b[j][0], b[j][1]);
            }
        }
        __syncthreads();
        if (ck + 2 < NC) issue(ck + 2);
    }

    // ---- epilogue ----
    #pragma unroll
    for (int i = 0; i < 4; i++) {
        #pragma unroll
        for (int j = 0; j < 4; j++) {
            int ml = wr * 64 + i * 16 + (lane >> 2);
            int nl = wc * 32 + j * 8 + 2 * (lane & 3);
            int m = bm + ml, n = bn + nl;
            if (mode == 0) {
                __half* dh = (z == 0) ? g_qhi : (z == 1) ? g_khi : g_vhi;
                int bb2 = m >> 11, ss = m & 2047;
                int hh = n >> 6,  hd = n & 63;
                size_t base = (((size_t)bb2 * Hn + hh) * Sn + ss) * HDn + hd;
                __half2 h = __floats2half2_rn(acc[i][j][0], acc[i][j][1]);
                *(uint32_t*)&dh[base] = *(uint32_t*)&h;
                h = __floats2half2_rn(acc[i][j][2], acc[i][j][3]);
                *(uint32_t*)&dh[base + 8 * HDn] = *(uint32_t*)&h;
            } else {
                *(float2*)&out[(size_t)m * Dn + n] =
                    make_float2(acc[i][j][0], acc[i][j][1]);
                *(float2*)&out[(size_t)(m + 8) * Dn + n] =
                    make_float2(acc[i][j][2], acc[i][j][3]);
            }
        }
    }
}

// ===========================================================================
// Tensor-core flash attention, single-pass fp16 MMAs (Qh*Kh, Ph*Vh).
// CTA: 128 q-rows x full K sweep. 8 warps x 16 rows.
// smem: Qh persistent + double-buffered {Kh, Vh, mask-bits} via cp.async.
// ===========================================================================
#define AP     72                 // halves per row (144 B)
#define APB    144
#define TILE18 18432              // 128 * 144
#define OFF_KH 0
#define OFF_VH 18432
#define OFF_MK 36864              // 128 rows x 16 B of bits
#define KVBUF  38912              // 2*18432 + 2048
#define QSZ    18432
#define ATT_SMEM (QSZ + 2 * KVBUF)   // 96256

__global__ __launch_bounds__(256, 1) void attn_mma_kernel()
{
    extern __shared__ char smn[];
    const uint32_t sb = smem_u32(smn);
    const int tid = threadIdx.x, lane = tid & 31, w = tid >> 5;
    const int qt = blockIdx.x, bh = blockIdx.y;
    const int b = bh >> 4, h = bh & 15;
    const int qbase = qt * 128;
    const size_t head = (size_t)bh * Sn * HDn;
    const int row = tid >> 1, seg = tid & 1;
    const uint32_t rowb = (uint32_t)row * APB + seg * 64;

    // Q tile (persistent, hi only)
    {
        const uint4* qh = (const uint4*)(g_qhi + head + (size_t)(qbase + row) * HDn + seg * 32);
        uint4* dh = (uint4*)(smn + rowb);
        #pragma unroll
        for (int i = 0; i < 4; i++) dh[i] = qh[i];
    }

    // bit-mask: row r occupies 256 B; per k-tile we need 16 B starting at kt*16
    const char* mbits_row = (const char*)g_maskbits + ((size_t)b * Sn + qbase + row) * (Sn / 8);
    const char* gkh = (const char*)(g_khi + head + (size_t)row * HDn + seg * 32);
    const char* gvh = (const char*)(g_vhi + head + (size_t)row * HDn + seg * 32);

    auto issue_tile = [&](int kt, int s) {
        const uint32_t bb = sb + QSZ + s * KVBUF;
        const size_t go = (size_t)kt * 128 * HDn * 2;
        #pragma unroll
        for (int i = 0; i < 4; i++) {
            CPA16(bb + OFF_KH + rowb + i * 16, gkh + go + i * 16);
            CPA16(bb + OFF_VH + rowb + i * 16, gvh + go + i * 16);
        }
        if (seg == 0)
            CPA16(bb + OFF_MK + (uint32_t)row * 16, mbits_row + kt * 16);
        CPA_COMMIT();
    };

    float o[8][4];
    #pragma unroll
    for (int j = 0; j < 8; j++)
        #pragma unroll
        for (int v = 0; v < 4; v++) o[j][v] = 0.f;
    float m_r0 = -1e30f, m_r1 = -1e30f, l_r0 = 0.f, l_r1 = 0.f;

    const int wq0  = w * 16;
    const int r_lo = lane >> 2, c4 = lane & 3;
    const int mA = wq0 + ((lane >> 3) & 1) * 8 + (lane & 7);
    const int kA = ((lane >> 4) & 1) * 8;
    const uint32_t aQh = sb + (uint32_t)(mA * AP + kA) * 2;
    const int nK = ((lane >> 4) & 1) * 8 + (lane & 7);
    const int kK = ((lane >> 3) & 1) * 8;
    const int kV = ((lane >> 3) & 1) * 8 + (lane & 7);
    const int nV = ((lane >> 4) & 1) * 8;

    issue_tile(0, 0);

    for (int kt = 0; kt < 16; kt++) {
        const int s = kt & 1;
        if (kt < 15) { issue_tile(kt + 1, s ^ 1); CPA_WAIT1(); }
        else         { CPA_WAIT0(); }
        __syncthreads();
        const uint32_t bb = sb + QSZ + s * KVBUF;

        // ---- S = Qh Kh^T (single pass) ----
        float sacc[16][4];
        #pragma unroll
        for (int j = 0; j < 16; j++)
            #pragma unroll
            for (int v = 0; v < 4; v++) sacc[j][v] = 0.f;

        #pragma unroll
        for (int ks = 0; ks < 4; ks++) {
            uint32_t ah0, ah1, ah2, ah3;
            LDSM4(ah0, ah1, ah2, ah3, aQh + ks * 32);
            #pragma unroll
            for (int jj = 0; jj < 8; jj++) {
                const int j0 = 2 * jj;
                const uint32_t kaddr =
                    bb + OFF_KH + (uint32_t)((j0 * 8 + nK) * AP + ks * 16 + kK) * 2;
                uint32_t b0, b1, b2, b3;
                LDSM4(b0, b1, b2, b3, kaddr);
                MMA16816(sacc[j0],     ah0, ah1, ah2, ah3, b0, b1);
                MMA16816(sacc[j0 + 1], ah0, ah1, ah2, ah3, b2, b3);
            }
        }

        // ---- bit-mask + online softmax ----
        const uint4 mw0 = *(const uint4*)(smn + QSZ + s * KVBUF + OFF_MK + (wq0 + r_lo) * 16);
        const uint4 mw1 = *(const uint4*)(smn + QSZ + s * KVBUF + OFF_MK + (wq0 + r_lo + 8) * 16);
        uint32_t w0a[4] = {mw0.x, mw0.y, mw0.z, mw0.w};
        uint32_t w1a[4] = {mw1.x, mw1.y, mw1.z, mw1.w};
        float tm0 = -1e30f, tm1 = -1e30f;
        #pragma unroll
        for (int j = 0; j < 16; j++) {
            const uint32_t bits0 = w0a[j >> 2] >> (8 * (j & 3) + 2 * c4);
            const uint32_t bits1 = w1a[j >> 2] >> (8 * (j & 3) + 2 * c4);
            float s0 = (bits0 & 1u) ? sacc[j][0] * 0.125f : -1e30f;
            float s1 = (bits0 & 2u) ? sacc[j][1] * 0.125f : -1e30f;
            float s2 = (bits1 & 1u) ? sacc[j][2] * 0.125f : -1e30f;
            float s3 = (bits1 & 2u) ? sacc[j][3] * 0.125f : -1e30f;
            sacc[j][0] = s0; sacc[j][1] = s1; sacc[j][2] = s2; sacc[j][3] = s3;
            tm0 = fmaxf(tm0, fmaxf(s0, s1));
            tm1 = fmaxf(tm1, fmaxf(s2, s3));
        }
        tm0 = fmaxf(tm0, __shfl_xor_sync(0xffffffffu, tm0, 1));
        tm0 = fmaxf(tm0, __shfl_xor_sync(0xffffffffu, tm0, 2));
        tm1 = fmaxf(tm1, __shfl_xor_sync(0xffffffffu, tm1, 1));
        tm1 = fmaxf(tm1, __shfl_xor_sync(0xffffffffu, tm1, 2));
        const float mn0 = fmaxf(m_r0, tm0), mn1 = fmaxf(m_r1, tm1);
        const float al_0 = __expf(m_r0 - mn0), al_1 = __expf(m_r1 - mn1);
        m_r0 = mn0; m_r1 = mn1;
        float ps0 = 0.f, ps1 = 0.f;
        #pragma unroll
        for (int j = 0; j < 16; j++) {
            float p0 = __expf(sacc[j][0] - mn0); sacc[j][0] = p0; ps0 += p0;
            float p1 = __expf(sacc[j][1] - mn0); sacc[j][1] = p1; ps0 += p1;
            float p2 = __expf(sacc[j][2] - mn1); sacc[j][2] = p2; ps1 += p2;
            float p3 = __expf(sacc[j][3] - mn1); sacc[j][3] = p3; ps1 += p3;
        }
        ps0 += __shfl_xor_sync(0xffffffffu, ps0, 1);
        ps0 += __shfl_xor_sync(0xffffffffu, ps0, 2);
        ps1 += __shfl_xor_sync(0xffffffffu, ps1, 1);
        ps1 += __shfl_xor_sync(0xffffffffu, ps1, 2);
        l_r0 = l_r0 * al_0 + ps0;
        l_r1 = l_r1 * al_1 + ps1;
        #pragma unroll
        for (int j = 0; j < 8; j++) {
            o[j][0] *= al_0; o[j][1] *= al_0; o[j][2] *= al_1; o[j][3] *= al_1;
        }

        // ---- O += Ph Vh (single pass, V via ldmatrix.trans) ----
        #pragma unroll
        for (int kt2 = 0; kt2 < 8; kt2++) {
            const int j0 = 2 * kt2;
            __half2 hp;
            hp = __floats2half2_rn(sacc[j0][0], sacc[j0][1]);
            const uint32_t p0 = *(uint32_t*)&hp;
            hp = __floats2half2_rn(sacc[j0][2], sacc[j0][3]);
            const uint32_t p1 = *(uint32_t*)&hp;
            hp = __floats2half2_rn(sacc[j0 + 1][0], sacc[j0 + 1][1]);
            const uint32_t p2 = *(uint32_t*)&hp;
            hp = __floats2half2_rn(sacc[j0 + 1][2], sacc[j0 + 1][3]);
            const uint32_t p3 = *(uint32_t*)&hp;
            #pragma unroll
            for (int jj = 0; jj < 4; jj++) {
                const int jv = 2 * jj;
                const uint32_t va =
                    bb + OFF_VH + (uint32_t)((kt2 * 16 + kV) * AP + jv * 8 + nV) * 2;
                uint32_t v0, v1, v2, v3;
                LDSM4T(v0, v1, v2, v3, va);
                MMA16816(o[jv],     p0, p1, p2, p3, v0, v1);
                MMA16816(o[jv + 1], p0, p1, p2, p3, v2, v3);
            }
        }
        __syncthreads();
    }

    // ---- epilogue: O/l -> fp16 hi/lo into out-GEMM operand buffers ----
    const float inv0 = 1.f / fmaxf(l_r0, 1e-30f);
    const float inv1 = 1.f / fmaxf(l_r1, 1e-30f);
    const int r1g = qbase + wq0 + r_lo;
    #pragma unroll
    for (int j = 0; j < 8; j++) {
        const size_t idx0 = ((size_t)b * Sn + r1g) * Dn + h * 64 + j * 8 + 2 * c4;
        uint32_t hp, lp;
        split_pair(o[j][0] * inv0, o[j][1] * inv0, hp, lp);
        *(uint32_t*)&g_ahi[idx0] = hp;  *(uint32_t*)&g_alo[idx0] = lp;
        split_pair(o[j][2] * inv1, o[j][3] * inv1, hp, lp);
        *(uint32_t*)&g_ahi[idx0 + 8 * Dn] = hp;  *(uint32_t*)&g_alo[idx0 + 8 * Dn] = lp;
    }
}

// ---------------------------------------------------------------------------
extern "C" void kernel_launch(void* const* d_in, const int* in_sizes, int n_in,
                              void* d_out, int out_size)
{
    const float* x    = (const float*)d_in[0];
    const void*  mask = d_in[1];
    const float* wq   = (const float*)d_in[2];
    const float* wk   = (const float*)d_in[3];
    const float* wv   = (const float*)d_in[4];
    const float* wo   = (const float*)d_in[5];
    float* out = (float*)d_out;

    cudaFuncSetAttribute(mma_gemm_kernel,
                         cudaFuncAttributeMaxDynamicSharedMemorySize, DYNSM);
    cudaFuncSetAttribute(attn_mma_kernel,
                         cudaFuncAttributeMaxDynamicSharedMemorySize, ATT_SMEM);

    detect_mask_kernel<<<1, 256>>>((const uint32_t*)mask);
    const size_t mask_elts = (size_t)Bn * Sn * Sn;
    pack_mask_kernel<<<(unsigned)(mask_elts / 256), 256>>>(mask);

    __half *ahi, *alo, *whi;
    cudaGetSymbolAddress((void**)&ahi, g_ahi);
    cudaGetSymbolAddress((void**)&alo, g_alo);
    cudaGetSymbolAddress((void**)&whi, g_whi);

    const unsigned nX = (unsigned)((size_t)Mtot * Dn / 1024);
    const unsigned nW = (unsigned)((size_t)Dn * Dn / 1024);
    split_x_kernel<<<nX, 256>>>(x, ahi, alo);
    dim3 gw(nW, 4);
    cvt_w_kernel<<<gw, 256>>>(wq, wk, wv, wo);

    // QKV projections -> fp16 Q/K/V (hi)
    dim3 g1(Dn / 128, Mtot / 128, 3);
    mma_gemm_kernel<<<g1, 256, DYNSM>>>(ahi, alo, whi, nullptr, 0);

    // Tensor-core flash attention -> writes g_ahi/g_alo
    dim3 g2(Sn / 128, Bn * Hn);
    attn_mma_kernel<<<g2, 256, ATT_SMEM>>>();

    // Output projection
    dim3 g3(Dn / 128, Mtot / 128, 1);
    mma_gemm_kernel<<<g3, 256, DYNSM>>>(ahi, alo,
                                        whi + 3 * (size_t)Dn * Dn, out, 1);
}

// round 9
// speedup vs baseline: 4.8198x; 1.0672x over previous
#include <cuda_runtime.h>
#include <cuda_fp16.h>
#include <stdint.h>

#define Bn 4
#define Sn 2048
#define Dn 1024
#define Hn 16
#define HDn 64
#define Mtot (Bn * Sn)          // 8192

// Scratch (static device globals -- allocation-free per harness rules)
__device__ uint32_t g_maskbits[(size_t)Bn * Sn * Sn / 32];   // 1 bit / elt
__device__ int      g_mask_flag;

// fp16 operand buffers
__device__ __half g_ahi[(size_t)Mtot * Dn];   // X hi, then attn-out hi
__device__ __half g_alo[(size_t)Mtot * Dn];   // attn-out lo (out-proj 2-pass)
__device__ __half g_whi[(size_t)4 * Dn * Dn]; // wq,wk,wv,wo hi
__device__ __half g_qhi[(size_t)Bn * Hn * Sn * HDn];  // [B,H,S,HD] hi only
__device__ __half g_khi[(size_t)Bn * Hn * Sn * HDn];
__device__ __half g_vhi[(size_t)Bn * Hn * Sn * HDn];

// ===========================================================================
// PTX helpers (base ISA: ldmatrix / mma.sync / cp.async)
// ===========================================================================
__device__ __forceinline__ uint32_t smem_u32(const void* p) {
    uint32_t a;
    asm("{ .reg .u64 t; cvta.to.shared.u64 t, %1; cvt.u32.u64 %0, t; }" : "=r"(a) : "l"(p));
    return a;
}

#define LDSM4(r0, r1, r2, r3, addr) \
    asm volatile("ldmatrix.sync.aligned.m8n8.x4.shared.b16 {%0,%1,%2,%3}, [%4];" \
        : "=r"(r0), "=r"(r1), "=r"(r2), "=r"(r3) : "r"(addr))

#define LDSM4T(r0, r1, r2, r3, addr) \
    asm volatile("ldmatrix.sync.aligned.m8n8.x4.trans.shared.b16 {%0,%1,%2,%3}, [%4];" \
        : "=r"(r0), "=r"(r1), "=r"(r2), "=r"(r3) : "r"(addr))

#define MMA16816(c, a0, a1, a2, a3, b0, b1) \
    asm volatile("mma.sync.aligned.m16n8k16.row.col.f32.f16.f16.f32 " \
        "{%0,%1,%2,%3}, {%4,%5,%6,%7}, {%8,%9}, {%0,%1,%2,%3};" \
        : "+f"((c)[0]), "+f"((c)[1]), "+f"((c)[2]), "+f"((c)[3]) \
        : "r"(a0), "r"(a1), "r"(a2), "r"(a3), "r"(b0), "r"(b1))

#define CPA16(dst, src) \
    asm volatile("cp.async.cg.shared.global [%0], [%1], 16;" :: "r"(dst), "l"(src) : "memory")
#define CPA_COMMIT() asm volatile("cp.async.commit_group;" ::: "memory")
#define CPA_WAIT1()  asm volatile("cp.async.wait_group 1;" ::: "memory")
#define CPA_WAIT0()  asm volatile("cp.async.wait_group 0;" ::: "memory")

// fp32 pair -> packed fp16x2 hi + fp16x2 residual
__device__ __forceinline__ void split_pair(float p0, float p1, uint32_t& hi, uint32_t& lo) {
    __half2 h = __floats2half2_rn(p0, p1);
    hi = *(uint32_t*)&h;
    float h0 = __low2float(h), h1 = __high2float(h);
    __half2 l = __floats2half2_rn(p0 - h0, p1 - h1);
    lo = *(uint32_t*)&l;
}

// ===========================================================================
// Mask: dtype sniffer + ballot bit-packer
// ===========================================================================
__global__ void detect_mask_kernel(const uint32_t* __restrict__ m)
{
    __shared__ int cnt_w;
    if (threadIdx.x == 0) cnt_w = 0;
    __syncthreads();
    uint32_t w = m[threadIdx.x];
    if (w == 0u || w == 1u || w == 0x3F800000u) atomicAdd(&cnt_w, 1);
    __syncthreads();
    if (threadIdx.x == 0) g_mask_flag = (cnt_w > 200) ? 1 : 0;  // 1 = 4-byte elems
}

__global__ __launch_bounds__(256) void pack_mask_kernel(const void* __restrict__ m)
{
    const size_t i = (size_t)blockIdx.x * 256 + threadIdx.x;
    bool v;
    if (g_mask_flag)
        v = ((const uint32_t*)m)[i] != 0u;
    else
        v = ((const uint8_t*)m)[i] != 0;
    uint32_t w = __ballot_sync(0xffffffffu, v);
    if ((threadIdx.x & 31) == 0) g_maskbits[i >> 5] = w;
}

// ===========================================================================
// fp32 -> fp16 hi-only conversions (proven R7 structure)
// ===========================================================================
__global__ __launch_bounds__(256) void cvt_x_kernel(const float* __restrict__ src)
{
    const size_t i = (size_t)blockIdx.x * 256 + threadIdx.x;
    float4 v = ((const float4*)src)[i];
    __half2 a = __floats2half2_rn(v.x, v.y);
    __half2 b = __floats2half2_rn(v.z, v.w);
    ((uint2*)g_ahi)[i] = make_uint2(*(uint32_t*)&a, *(uint32_t*)&b);
}

__global__ __launch_bounds__(256) void cvt_w_kernel(
    const float* __restrict__ w0, const float* __restrict__ w1,
    const float* __restrict__ w2, const float* __restrict__ w3)
{
    const int z = blockIdx.y;
    const float* src = (z == 0) ? w0 : (z == 1) ? w1 : (z == 2) ? w2 : w3;
    const size_t i = (size_t)blockIdx.x * 256 + threadIdx.x;
    float4 v = ((const float4*)src)[i];
    __half2 a = __floats2half2_rn(v.x, v.y);
    __half2 b = __floats2half2_rn(v.z, v.w);
    ((uint2*)(g_whi + (size_t)z * Dn * Dn))[i] =
        make_uint2(*(uint32_t*)&a, *(uint32_t*)&b);
}

// ===========================================================================
// fp16 tensor-core GEMM: C[128x128] = A[.,1024] @ W[.,1024]^T
//   two_pass=0: D = Ah*Bh          (QKV projections; outputs rounded to fp16)
//   two_pass=1: D = Ah*Bh + Al*Bh  (output projection; fp32 result)
// mode 0: write fp16 hi into g_q/k/v by blockIdx.z; mode 1: fp32 to out.
// ===========================================================================
#define KC 32
#define PITCH 40                 // halves per smem row (80 B)
#define TILE_B (128 * PITCH * 2) // 10240
#define STG (3 * TILE_B)         // Ah, Al, Bh = 30720
#define DYNSM (2 * STG)          // 61440

__global__ __launch_bounds__(256, 1) void mma_gemm_kernel(
    const __half* __restrict__ Ahi,
    const __half* __restrict__ Alo,
    const __half* __restrict__ Whi,
    float* __restrict__ out,
    int mode, int two_pass)
{
    extern __shared__ char dsm[];
    const uint32_t sbase = smem_u32(dsm);

    const int tid  = threadIdx.x;
    const int lane = tid & 31;
    const int wid  = tid >> 5;
    const int wr   = wid >> 2;
    const int wc   = wid & 3;
    const int bm   = blockIdx.y * 128;
    const int bn   = blockIdx.x * 128;
    const int z    = blockIdx.z;

    const __half* WhiZ = Whi + (size_t)z * Dn * Dn;

    const int row = tid >> 1;
    const int gh  = tid & 1;
    const __half* sA_h = Ahi  + (size_t)(bm + row) * Dn + gh * 16;
    const __half* sA_l = Alo  + (size_t)(bm + row) * Dn + gh * 16;
    const __half* sB_h = WhiZ + (size_t)(bn + row) * Dn + gh * 16;
    const uint32_t sd0 = sbase + (uint32_t)row * (PITCH * 2) + gh * 32;

    const int NC = Dn / KC;     // 32
    auto issue = [&](int ck) {
        const uint32_t sd = sd0 + (ck & 1) * STG;
        const size_t o = (size_t)ck * KC;
        CPA16(sd,                     sA_h + o);
        CPA16(sd + 16,                sA_h + o + 8);
        if (two_pass) {
            CPA16(sd + TILE_B,        sA_l + o);
            CPA16(sd + TILE_B + 16,   sA_l + o + 8);
        }
        CPA16(sd + 2 * TILE_B,        sB_h + o);
        CPA16(sd + 2 * TILE_B + 16,   sB_h + o + 8);
        CPA_COMMIT();
    };

    float acc[4][4][4];
    #pragma unroll
    for (int i = 0; i < 4; i++)
        #pragma unroll
        for (int j = 0; j < 4; j++)
            #pragma unroll
            for (int v = 0; v < 4; v++) acc[i][j][v] = 0.f;

    issue(0);
    issue(1);

    for (int ck = 0; ck < NC; ck++) {
        if (ck == NC - 1) { CPA_WAIT0(); } else { CPA_WAIT1(); }
        __syncthreads();

        const uint32_t stg = sbase + (ck & 1) * STG;
        #pragma unroll
        for (int ks = 0; ks < 2; ks++) {
            uint32_t b[4][2];
            #pragma unroll
            for (int jj = 0; jj < 2; jj++) {
                int n = wc * 32 + jj * 16 + ((lane >> 4) & 1) * 8 + (lane & 7);
                int k = ks * 16 + ((lane >> 3) & 1) * 8;
                uint32_t ad = stg + 2 * TILE_B + (uint32_t)(n * PITCH + k) * 2;
                LDSM4(b[2 * jj][0], b[2 * jj][1], b[2 * jj + 1][0], b[2 * jj + 1][1], ad);
            }
            #pragma unroll
            for (int i = 0; i < 4; i++) {
                int m = wr * 64 + i * 16 + ((lane >> 3) & 1) * 8 + (lane & 7);
                int k = ks * 16 + ((lane >> 4) & 1) * 8;
                uint32_t adh = stg + (uint32_t)(m * PITCH + k) * 2;
                uint32_t a0, a1, a2, a3;
                LDSM4(a0, a1, a2, a3, adh);
                #pragma unroll
                for (int j = 0; j < 4; j++)
                    MMA16816(acc[i][j], a0, a1, a2, a3, b[j][0], b[j][1]);
                if (two_pass) {
                    LDSM4(a0, a1, a2, a3, adh + TILE_B);
                    #pragma unroll
                    for (int j = 0; j < 4; j++)
                        MMA16816(acc[i][j], a0, a1, a2, a3, b[j][0], b[j][1]);
                }
            }
        }
        __syncthreads();
        if (ck + 2 < NC) issue(ck + 2);
    }

    // ---- epilogue ----
    #pragma unroll
    for (int i = 0; i < 4; i++) {
        #pragma unroll
        for (int j = 0; j < 4; j++) {
            int ml = wr * 64 + i * 16 + (lane >> 2);
            int nl = wc * 32 + j * 8 + 2 * (lane & 3);
            int m = bm + ml, n = bn + nl;
            if (mode == 0) {
                __half* dh = (z == 0) ? g_qhi : (z == 1) ? g_khi : g_vhi;
                int bb2 = m >> 11, ss = m & 2047;
                int hh = n >> 6,  hd = n & 63;
                size_t base = (((size_t)bb2 * Hn + hh) * Sn + ss) * HDn + hd;
                __half2 h = __floats2half2_rn(acc[i][j][0], acc[i][j][1]);
                *(uint32_t*)&dh[base] = *(uint32_t*)&h;
                h = __floats2half2_rn(acc[i][j][2], acc[i][j][3]);
                *(uint32_t*)&dh[base + 8 * HDn] = *(uint32_t*)&h;
            } else {
                *(float2*)&out[(size_t)m * Dn + n] =
                    make_float2(acc[i][j][0], acc[i][j][1]);
                *(float2*)&out[(size_t)(m + 8) * Dn + n] =
                    make_float2(acc[i][j][2], acc[i][j][3]);
            }
        }
    }
}

// ===========================================================================
// Tensor-core flash attention, single-pass fp16 MMAs (Qh*Kh, Ph*Vh).
// CTA: 128 q-rows x full K sweep. 8 warps x 16 rows.
// smem: Qh persistent + double-buffered {Kh, Vh, mask-bits} via cp.async.
// ===========================================================================
#define AP     72                 // halves per row (144 B)
#define APB    144
#define TILE18 18432              // 128 * 144
#define OFF_KH 0
#define OFF_VH 18432
#define OFF_MK 36864              // 128 rows x 16 B of bits
#define KVBUF  38912              // 2*18432 + 2048
#define QSZ    18432
#define ATT_SMEM (QSZ + 2 * KVBUF)   // 96256

__global__ __launch_bounds__(256, 1) void attn_mma_kernel()
{
    extern __shared__ char smn[];
    const uint32_t sb = smem_u32(smn);
    const int tid = threadIdx.x, lane = tid & 31, w = tid >> 5;
    const int qt = blockIdx.x, bh = blockIdx.y;
    const int b = bh >> 4, h = bh & 15;
    const int qbase = qt * 128;
    const size_t head = (size_t)bh * Sn * HDn;
    const int row = tid >> 1, seg = tid & 1;
    const uint32_t rowb = (uint32_t)row * APB + seg * 64;

    // Q tile (persistent, hi only)
    {
        const uint4* qh = (const uint4*)(g_qhi + head + (size_t)(qbase + row) * HDn + seg * 32);
        uint4* dh = (uint4*)(smn + rowb);
        #pragma unroll
        for (int i = 0; i < 4; i++) dh[i] = qh[i];
    }

    const char* mbits_row = (const char*)g_maskbits + ((size_t)b * Sn + qbase + row) * (Sn / 8);
    const char* gkh = (const char*)(g_khi + head + (size_t)row * HDn + seg * 32);
    const char* gvh = (const char*)(g_vhi + head + (size_t)row * HDn + seg * 32);

    auto issue_tile = [&](int kt, int s) {
        const uint32_t bb = sb + QSZ + s * KVBUF;
        const size_t go = (size_t)kt * 128 * HDn * 2;
        #pragma unroll
        for (int i = 0; i < 4; i++) {
            CPA16(bb + OFF_KH + rowb + i * 16, gkh + go + i * 16);
            CPA16(bb + OFF_VH + rowb + i * 16, gvh + go + i * 16);
        }
        if (seg == 0)
            CPA16(bb + OFF_MK + (uint32_t)row * 16, mbits_row + kt * 16);
        CPA_COMMIT();
    };

    float o[8][4];
    #pragma unroll
    for (int j = 0; j < 8; j++)
        #pragma unroll
        for (int v = 0; v < 4; v++) o[j][v] = 0.f;
    float m_r0 = -1e30f, m_r1 = -1e30f, l_r0 = 0.f, l_r1 = 0.f;

    const int wq0  = w * 16;
    const int r_lo = lane >> 2, c4 = lane & 3;
    const int mA = wq0 + ((lane >> 3) & 1) * 8 + (lane & 7);
    const int kA = ((lane >> 4) & 1) * 8;
    const uint32_t aQh = sb + (uint32_t)(mA * AP + kA) * 2;
    const int nK = ((lane >> 4) & 1) * 8 + (lane & 7);
    const int kK = ((lane >> 3) & 1) * 8;
    const int kV = ((lane >> 3) & 1) * 8 + (lane & 7);
    const int nV = ((lane >> 4) & 1) * 8;

    issue_tile(0, 0);

    for (int kt = 0; kt < 16; kt++) {
        const int s = kt & 1;
        if (kt < 15) { issue_tile(kt + 1, s ^ 1); CPA_WAIT1(); }
        else         { CPA_WAIT0(); }
        __syncthreads();
        const uint32_t bb = sb + QSZ + s * KVBUF;

        // ---- S = Qh Kh^T (single pass) ----
        float sacc[16][4];
        #pragma unroll
        for (int j = 0; j < 16; j++)
            #pragma unroll
            for (int v = 0; v < 4; v++) sacc[j][v] = 0.f;

        #pragma unroll
        for (int ks = 0; ks < 4; ks++) {
            uint32_t ah0, ah1, ah2, ah3;
            LDSM4(ah0, ah1, ah2, ah3, aQh + ks * 32);
            #pragma unroll
            for (int jj = 0; jj < 8; jj++) {
                const int j0 = 2 * jj;
                const uint32_t kaddr =
                    bb + OFF_KH + (uint32_t)((j0 * 8 + nK) * AP + ks * 16 + kK) * 2;
                uint32_t b0, b1, b2, b3;
                LDSM4(b0, b1, b2, b3, kaddr);
                MMA16816(sacc[j0],     ah0, ah1, ah2, ah3, b0, b1);
                MMA16816(sacc[j0 + 1], ah0, ah1, ah2, ah3, b2, b3);
            }
        }

        // ---- bit-mask + online softmax ----
        const uint4 mw0 = *(const uint4*)(smn + QSZ + s * KVBUF + OFF_MK + (wq0 + r_lo) * 16);
        const uint4 mw1 = *(const uint4*)(smn + QSZ + s * KVBUF + OFF_MK + (wq0 + r_lo + 8) * 16);
        uint32_t w0a[4] = {mw0.x, mw0.y, mw0.z, mw0.w};
        uint32_t w1a[4] = {mw1.x, mw1.y, mw1.z, mw1.w};
        float tm0 = -1e30f, tm1 = -1e30f;
        #pragma unroll
        for (int j = 0; j < 16; j++) {
            const uint32_t bits0 = w0a[j >> 2] >> (8 * (j & 3) + 2 * c4);
            const uint32_t bits1 = w1a[j >> 2] >> (8 * (j & 3) + 2 * c4);
            float s0 = (bits0 & 1u) ? sacc[j][0] * 0.125f : -1e30f;
            float s1 = (bits0 & 2u) ? sacc[j][1] * 0.125f : -1e30f;
            float s2 = (bits1 & 1u) ? sacc[j][2] * 0.125f : -1e30f;
            float s3 = (bits1 & 2u) ? sacc[j][3] * 0.125f : -1e30f;
            sacc[j][0] = s0; sacc[j][1] = s1; sacc[j][2] = s2; sacc[j][3] = s3;
            tm0 = fmaxf(tm0, fmaxf(s0, s1));
            tm1 = fmaxf(tm1, fmaxf(s2, s3));
        }
        tm0 = fmaxf(tm0, __shfl_xor_sync(0xffffffffu, tm0, 1));
        tm0 = fmaxf(tm0, __shfl_xor_sync(0xffffffffu, tm0, 2));
        tm1 = fmaxf(tm1, __shfl_xor_sync(0xffffffffu, tm1, 1));
        tm1 = fmaxf(tm1, __shfl_xor_sync(0xffffffffu, tm1, 2));
        const float mn0 = fmaxf(m_r0, tm0), mn1 = fmaxf(m_r1, tm1);
        const float al_0 = __expf(m_r0 - mn0), al_1 = __expf(m_r1 - mn1);
        m_r0 = mn0; m_r1 = mn1;
        float ps0 = 0.f, ps1 = 0.f;
        #pragma unroll
        for (int j = 0; j < 16; j++) {
            float p0 = __expf(sacc[j][0] - mn0); sacc[j][0] = p0; ps0 += p0;
            float p1 = __expf(sacc[j][1] - mn0); sacc[j][1] = p1; ps0 += p1;
            float p2 = __expf(sacc[j][2] - mn1); sacc[j][2] = p2; ps1 += p2;
            float p3 = __expf(sacc[j][3] - mn1); sacc[j][3] = p3; ps1 += p3;
        }
        ps0 += __shfl_xor_sync(0xffffffffu, ps0, 1);
        ps0 += __shfl_xor_sync(0xffffffffu, ps0, 2);
        ps1 += __shfl_xor_sync(0xffffffffu, ps1, 1);
        ps1 += __shfl_xor_sync(0xffffffffu, ps1, 2);
        l_r0 = l_r0 * al_0 + ps0;
        l_r1 = l_r1 * al_1 + ps1;
        #pragma unroll
        for (int j = 0; j < 8; j++) {
            o[j][0] *= al_0; o[j][1] *= al_0; o[j][2] *= al_1; o[j][3] *= al_1;
        }

        // ---- O += Ph Vh (single pass, V via ldmatrix.trans) ----
        #pragma unroll
        for (int kt2 = 0; kt2 < 8; kt2++) {
            const int j0 = 2 * kt2;
            __half2 hp;
            hp = __floats2half2_rn(sacc[j0][0], sacc[j0][1]);
            const uint32_t p0 = *(uint32_t*)&hp;
            hp = __floats2half2_rn(sacc[j0][2], sacc[j0][3]);
            const uint32_t p1 = *(uint32_t*)&hp;
            hp = __floats2half2_rn(sacc[j0 + 1][0], sacc[j0 + 1][1]);
            const uint32_t p2 = *(uint32_t*)&hp;
            hp = __floats2half2_rn(sacc[j0 + 1][2], sacc[j0 + 1][3]);
            const uint32_t p3 = *(uint32_t*)&hp;
            #pragma unroll
            for (int jj = 0; jj < 4; jj++) {
                const int jv = 2 * jj;
                const uint32_t va =
                    bb + OFF_VH + (uint32_t)((kt2 * 16 + kV) * AP + jv * 8 + nV) * 2;
                uint32_t v0, v1, v2, v3;
                LDSM4T(v0, v1, v2, v3, va);
                MMA16816(o[jv],     p0, p1, p2, p3, v0, v1);
                MMA16816(o[jv + 1], p0, p1, p2, p3, v2, v3);
            }
        }
        __syncthreads();
    }

    // ---- epilogue: O/l -> fp16 hi/lo into out-GEMM operand buffers ----
    const float inv0 = 1.f / fmaxf(l_r0, 1e-30f);
    const float inv1 = 1.f / fmaxf(l_r1, 1e-30f);
    const int r1g = qbase + wq0 + r_lo;
    #pragma unroll
    for (int j = 0; j < 8; j++) {
        const size_t idx0 = ((size_t)b * Sn + r1g) * Dn + h * 64 + j * 8 + 2 * c4;
        uint32_t hp, lp;
        split_pair(o[j][0] * inv0, o[j][1] * inv0, hp, lp);
        *(uint32_t*)&g_ahi[idx0] = hp;  *(uint32_t*)&g_alo[idx0] = lp;
        split_pair(o[j][2] * inv1, o[j][3] * inv1, hp, lp);
        *(uint32_t*)&g_ahi[idx0 + 8 * Dn] = hp;  *(uint32_t*)&g_alo[idx0 + 8 * Dn] = lp;
    }
}

// ---------------------------------------------------------------------------
extern "C" void kernel_launch(void* const* d_in, const int* in_sizes, int n_in,
                              void* d_out, int out_size)
{
    const float* x    = (const float*)d_in[0];
    const void*  mask = d_in[1];
    const float* wq   = (const float*)d_in[2];
    const float* wk   = (const float*)d_in[3];
    const float* wv   = (const float*)d_in[4];
    const float* wo   = (const float*)d_in[5];
    float* out = (float*)d_out;

    cudaFuncSetAttribute(mma_gemm_kernel,
                         cudaFuncAttributeMaxDynamicSharedMemorySize, DYNSM);
    cudaFuncSetAttribute(attn_mma_kernel,
                         cudaFuncAttributeMaxDynamicSharedMemorySize, ATT_SMEM);

    detect_mask_kernel<<<1, 256>>>((const uint32_t*)mask);
    const size_t mask_elts = (size_t)Bn * Sn * Sn;
    pack_mask_kernel<<<(unsigned)(mask_elts / 256), 256>>>(mask);

    __half *ahi, *alo, *whi;
    cudaGetSymbolAddress((void**)&ahi, g_ahi);
    cudaGetSymbolAddress((void**)&alo, g_alo);
    cudaGetSymbolAddress((void**)&whi, g_whi);

    const unsigned nX = (unsigned)((size_t)Mtot * Dn / 1024);
    const unsigned nW = (unsigned)((size_t)Dn * Dn / 1024);
    cvt_x_kernel<<<nX, 256>>>(x);
    cvt_w_kernel<<<dim3(nW, 4), 256>>>(wq, wk, wv, wo);

    // QKV projections -> fp16 Q/K/V (hi), single-pass
    dim3 g1(Dn / 128, Mtot / 128, 3);
    mma_gemm_kernel<<<g1, 256, DYNSM>>>(ahi, alo, whi, nullptr, 0, 0);

    // Tensor-core flash attention -> writes g_ahi/g_alo
    dim3 g2(Sn / 128, Bn * Hn);
    attn_mma_kernel<<<g2, 256, ATT_SMEM>>>();

    // Output projection (2-pass for final fp32 accuracy)
    dim3 g3(Dn / 128, Mtot / 128, 1);
    mma_gemm_kernel<<<g3, 256, DYNSM>>>(ahi, alo,
                                        whi + 3 * (size_t)Dn * Dn, out, 1, 1);
}

// round 10
// speedup vs baseline: 6.4211x; 1.3322x over previous
#include <cuda_runtime.h>
#include <cuda_fp16.h>
#include <stdint.h>

#define Bn 4
#define Sn 2048
#define Dn 1024
#define Hn 16
#define HDn 64
#define Mtot (Bn * Sn)          // 8192

// Scratch (static device globals -- allocation-free per harness rules)
__device__ uint32_t g_maskbits[(size_t)Bn * Sn * Sn / 32];   // 1 bit / elt
__device__ int      g_mask_flag;

// fp16 operand buffers (all hi-only now)
__device__ __half g_ahi[(size_t)Mtot * Dn];   // X hi, then attn-out hi
__device__ __half g_whi[(size_t)4 * Dn * Dn]; // wq,wk,wv,wo hi
__device__ __half g_qhi[(size_t)Bn * Hn * Sn * HDn];  // [B,H,S,HD]
__device__ __half g_khi[(size_t)Bn * Hn * Sn * HDn];
__device__ __half g_vhi[(size_t)Bn * Hn * Sn * HDn];

// ===========================================================================
// PTX helpers (base ISA: ldmatrix / mma.sync / cp.async)
// ===========================================================================
__device__ __forceinline__ uint32_t smem_u32(const void* p) {
    uint32_t a;
    asm("{ .reg .u64 t; cvta.to.shared.u64 t, %1; cvt.u32.u64 %0, t; }" : "=r"(a) : "l"(p));
    return a;
}

#define LDSM4(r0, r1, r2, r3, addr) \
    asm volatile("ldmatrix.sync.aligned.m8n8.x4.shared.b16 {%0,%1,%2,%3}, [%4];" \
        : "=r"(r0), "=r"(r1), "=r"(r2), "=r"(r3) : "r"(addr))

#define LDSM4T(r0, r1, r2, r3, addr) \
    asm volatile("ldmatrix.sync.aligned.m8n8.x4.trans.shared.b16 {%0,%1,%2,%3}, [%4];" \
        : "=r"(r0), "=r"(r1), "=r"(r2), "=r"(r3) : "r"(addr))

#define MMA16816(c, a0, a1, a2, a3, b0, b1) \
    asm volatile("mma.sync.aligned.m16n8k16.row.col.f32.f16.f16.f32 " \
        "{%0,%1,%2,%3}, {%4,%5,%6,%7}, {%8,%9}, {%0,%1,%2,%3};" \
        : "+f"((c)[0]), "+f"((c)[1]), "+f"((c)[2]), "+f"((c)[3]) \
        : "r"(a0), "r"(a1), "r"(a2), "r"(a3), "r"(b0), "r"(b1))

#define CPA16(dst, src) \
    asm volatile("cp.async.cg.shared.global [%0], [%1], 16;" :: "r"(dst), "l"(src) : "memory")
#define CPA_COMMIT() asm volatile("cp.async.commit_group;" ::: "memory")
#define CPA_WAIT1()  asm volatile("cp.async.wait_group 1;" ::: "memory")
#define CPA_WAIT0()  asm volatile("cp.async.wait_group 0;" ::: "memory")

// ===========================================================================
// Mask: dtype sniffer + vectorized bit-packer (4 elems/thread, shuffle-OR)
// ===========================================================================
__global__ void detect_mask_kernel(const uint32_t* __restrict__ m)
{
    __shared__ int cnt_w;
    if (threadIdx.x == 0) cnt_w = 0;
    __syncthreads();
    uint32_t w = m[threadIdx.x];
    if (w == 0u || w == 1u || w == 0x3F800000u) atomicAdd(&cnt_w, 1);
    __syncthreads();
    if (threadIdx.x == 0) g_mask_flag = (cnt_w > 200) ? 1 : 0;  // 1 = 4-byte elems
}

__global__ __launch_bounds__(256) void pack_mask_kernel(const void* __restrict__ m)
{
    // Each thread handles 4 consecutive elements (index idx*4 .. idx*4+3).
    const size_t idx = (size_t)blockIdx.x * 256 + threadIdx.x;
    const int lane = threadIdx.x & 31;
    uint32_t nib;
    if (g_mask_flag) {              // 4-byte elements: load uint4
        uint4 v = ((const uint4*)m)[idx];
        nib = (v.x != 0u) | ((v.y != 0u) << 1) | ((v.z != 0u) << 2) | ((v.w != 0u) << 3);
    } else {                        // 1-byte elements: load one word = 4 bytes
        uint32_t v = ((const uint32_t*)m)[idx];
        nib = ((v & 0x000000FFu) ? 1u : 0u) | ((v & 0x0000FF00u) ? 2u : 0u)
            | ((v & 0x00FF0000u) ? 4u : 0u) | ((v & 0xFF000000u) ? 8u : 0u);
    }
    uint32_t sh = nib << (4 * (lane & 7));
    sh |= __shfl_xor_sync(0xffffffffu, sh, 1);
    sh |= __shfl_xor_sync(0xffffffffu, sh, 2);
    sh |= __shfl_xor_sync(0xffffffffu, sh, 4);
    if ((lane & 7) == 0) g_maskbits[idx >> 3] = sh;
}

// ===========================================================================
// fp32 -> fp16 hi conversion: one launch covers X (8 slices) + 4 weights.
// grid = (1024, 12): z<8 -> X chunk z; z>=8 -> weight z-8.
// ===========================================================================
__global__ __launch_bounds__(256) void cvt_all_kernel(
    const float* __restrict__ x,
    const float* __restrict__ w0, const float* __restrict__ w1,
    const float* __restrict__ w2, const float* __restrict__ w3)
{
    const int z = blockIdx.y;
    const float* src;
    __half* dst;
    if (z < 8) {
        src = x   + (size_t)z * (Mtot / 8) * Dn;
        dst = g_ahi + (size_t)z * (Mtot / 8) * Dn;
    } else {
        const float* ws[4] = {w0, w1, w2, w3};
        src = ws[z - 8];
        dst = g_whi + (size_t)(z - 8) * Dn * Dn;
    }
    const size_t i = (size_t)blockIdx.x * 256 + threadIdx.x;
    float4 v = ((const float4*)src)[i];
    __half2 a = __floats2half2_rn(v.x, v.y);
    __half2 b = __floats2half2_rn(v.z, v.w);
    ((uint2*)dst)[i] = make_uint2(*(uint32_t*)&a, *(uint32_t*)&b);
}

// ===========================================================================
// fp16 tensor-core GEMM (single pass): C[128x128] = Ah[.,1024] @ Wh[.,1024]^T
// mode 0: write fp16 into g_q/k/v by blockIdx.z; mode 1: fp32 to out.
// ===========================================================================
#define KC 32
#define PITCH 40                 // halves per smem row (80 B)
#define TILE_B (128 * PITCH * 2) // 10240
#define STG (2 * TILE_B)         // Ah, Bh = 20480
#define DYNSM (2 * STG)          // 40960

__global__ __launch_bounds__(256, 1) void mma_gemm_kernel(
    const __half* __restrict__ Ahi,
    const __half* __restrict__ Whi,
    float* __restrict__ out,
    int mode)
{
    extern __shared__ char dsm[];
    const uint32_t sbase = smem_u32(dsm);

    const int tid  = threadIdx.x;
    const int lane = tid & 31;
    const int wid  = tid >> 5;
    const int wr   = wid >> 2;
    const int wc   = wid & 3;
    const int bm   = blockIdx.y * 128;
    const int bn   = blockIdx.x * 128;
    const int z    = blockIdx.z;

    const __half* WhiZ = Whi + (size_t)z * Dn * Dn;

    const int row = tid >> 1;
    const int gh  = tid & 1;
    const __half* sA_h = Ahi  + (size_t)(bm + row) * Dn + gh * 16;
    const __half* sB_h = WhiZ + (size_t)(bn + row) * Dn + gh * 16;
    const uint32_t sd0 = sbase + (uint32_t)row * (PITCH * 2) + gh * 32;

    const int NC = Dn / KC;     // 32
    auto issue = [&](int ck) {
        const uint32_t sd = sd0 + (ck & 1) * STG;
        const size_t o = (size_t)ck * KC;
        CPA16(sd,                 sA_h + o);
        CPA16(sd + 16,            sA_h + o + 8);
        CPA16(sd + TILE_B,        sB_h + o);
        CPA16(sd + TILE_B + 16,   sB_h + o + 8);
        CPA_COMMIT();
    };

    float acc[4][4][4];
    #pragma unroll
    for (int i = 0; i < 4; i++)
        #pragma unroll
        for (int j = 0; j < 4; j++)
            #pragma unroll
            for (int v = 0; v < 4; v++) acc[i][j][v] = 0.f;

    issue(0);
    issue(1);

    for (int ck = 0; ck < NC; ck++) {
        if (ck == NC - 1) { CPA_WAIT0(); } else { CPA_WAIT1(); }
        __syncthreads();

        const uint32_t stg = sbase + (ck & 1) * STG;
        #pragma unroll
        for (int ks = 0; ks < 2; ks++) {
            uint32_t b[4][2];
            #pragma unroll
            for (int jj = 0; jj < 2; jj++) {
                int n = wc * 32 + jj * 16 + ((lane >> 4) & 1) * 8 + (lane & 7);
                int k = ks * 16 + ((lane >> 3) & 1) * 8;
                uint32_t ad = stg + TILE_B + (uint32_t)(n * PITCH + k) * 2;
                LDSM4(b[2 * jj][0], b[2 * jj][1], b[2 * jj + 1][0], b[2 * jj + 1][1], ad);
            }
            #pragma unroll
            for (int i = 0; i < 4; i++) {
                int m = wr * 64 + i * 16 + ((lane >> 3) & 1) * 8 + (lane & 7);
                int k = ks * 16 + ((lane >> 4) & 1) * 8;
                uint32_t adh = stg + (uint32_t)(m * PITCH + k) * 2;
                uint32_t a0, a1, a2, a3;
                LDSM4(a0, a1, a2, a3, adh);
                #pragma unroll
                for (int j = 0; j < 4; j++)
                    MMA16816(acc[i][j], a0, a1, a2, a3, b[j][0], b[j][1]);
            }
        }
        __syncthreads();
        if (ck + 2 < NC) issue(ck + 2);
    }

    // ---- epilogue ----
    #pragma unroll
    for (int i = 0; i < 4; i++) {
        #pragma unroll
        for (int j = 0; j < 4; j++) {
            int ml = wr * 64 + i * 16 + (lane >> 2);
            int nl = wc * 32 + j * 8 + 2 * (lane & 3);
            int m = bm + ml, n = bn + nl;
            if (mode == 0) {
                __half* dh = (z == 0) ? g_qhi : (z == 1) ? g_khi : g_vhi;
                int bb2 = m >> 11, ss = m & 2047;
                int hh = n >> 6,  hd = n & 63;
                size_t base = (((size_t)bb2 * Hn + hh) * Sn + ss) * HDn + hd;
                __half2 h = __floats2half2_rn(acc[i][j][0], acc[i][j][1]);
                *(uint32_t*)&dh[base] = *(uint32_t*)&h;
                h = __floats2half2_rn(acc[i][j][2], acc[i][j][3]);
                *(uint32_t*)&dh[base + 8 * HDn] = *(uint32_t*)&h;
            } else {
                *(float2*)&out[(size_t)m * Dn + n] =
                    make_float2(acc[i][j][0], acc[i][j][1]);
                *(float2*)&out[(size_t)(m + 8) * Dn + n] =
                    make_float2(acc[i][j][2], acc[i][j][3]);
            }
        }
    }
}

// ===========================================================================
// Tensor-core flash attention, single-pass fp16 MMAs (Qh*Kh, Ph*Vh).
// CTA: 128 q-rows x full K sweep. 8 warps x 16 rows.
// smem: Qh persistent + double-buffered {Kh, Vh, mask-bits} via cp.async.
// ===========================================================================
#define AP     72                 // halves per row (144 B)
#define APB    144
#define TILE18 18432              // 128 * 144
#define OFF_KH 0
#define OFF_VH 18432
#define OFF_MK 36864              // 128 rows x 16 B of bits
#define KVBUF  38912              // 2*18432 + 2048
#define QSZ    18432
#define ATT_SMEM (QSZ + 2 * KVBUF)   // 96256

__global__ __launch_bounds__(256, 1) void attn_mma_kernel()
{
    extern __shared__ char smn[];
    const uint32_t sb = smem_u32(smn);
    const int tid = threadIdx.x, lane = tid & 31, w = tid >> 5;
    const int qt = blockIdx.x, bh = blockIdx.y;
    const int b = bh >> 4, h = bh & 15;
    const int qbase = qt * 128;
    const size_t head = (size_t)bh * Sn * HDn;
    const int row = tid >> 1, seg = tid & 1;
    const uint32_t rowb = (uint32_t)row * APB + seg * 64;

    // Q tile (persistent)
    {
        const uint4* qh = (const uint4*)(g_qhi + head + (size_t)(qbase + row) * HDn + seg * 32);
        uint4* dh = (uint4*)(smn + rowb);
        #pragma unroll
        for (int i = 0; i < 4; i++) dh[i] = qh[i];
    }

    const char* mbits_row = (const char*)g_maskbits + ((size_t)b * Sn + qbase + row) * (Sn / 8);
    const char* gkh = (const char*)(g_khi + head + (size_t)row * HDn + seg * 32);
    const char* gvh = (const char*)(g_vhi + head + (size_t)row * HDn + seg * 32);

    auto issue_tile = [&](int kt, int s) {
        const uint32_t bb = sb + QSZ + s * KVBUF;
        const size_t go = (size_t)kt * 128 * HDn * 2;
        #pragma unroll
        for (int i = 0; i < 4; i++) {
            CPA16(bb + OFF_KH + rowb + i * 16, gkh + go + i * 16);
            CPA16(bb + OFF_VH + rowb + i * 16, gvh + go + i * 16);
        }
        if (seg == 0)
            CPA16(bb + OFF_MK + (uint32_t)row * 16, mbits_row + kt * 16);
        CPA_COMMIT();
    };

    float o[8][4];
    #pragma unroll
    for (int j = 0; j < 8; j++)
        #pragma unroll
        for (int v = 0; v < 4; v++) o[j][v] = 0.f;
    float m_r0 = -1e30f, m_r1 = -1e30f, l_r0 = 0.f, l_r1 = 0.f;

    const int wq0  = w * 16;
    const int r_lo = lane >> 2, c4 = lane & 3;
    const int mA = wq0 + ((lane >> 3) & 1) * 8 + (lane & 7);
    const int kA = ((lane >> 4) & 1) * 8;
    const uint32_t aQh = sb + (uint32_t)(mA * AP + kA) * 2;
    const int nK = ((lane >> 4) & 1) * 8 + (lane & 7);
    const int kK = ((lane >> 3) & 1) * 8;
    const int kV = ((lane >> 3) & 1) * 8 + (lane & 7);
    const int nV = ((lane >> 4) & 1) * 8;

    issue_tile(0, 0);

    for (int kt = 0; kt < 16; kt++) {
        const int s = kt & 1;
        if (kt < 15) { issue_tile(kt + 1, s ^ 1); CPA_WAIT1(); }
        else         { CPA_WAIT0(); }
        __syncthreads();
        const uint32_t bb = sb + QSZ + s * KVBUF;

        // ---- S = Qh Kh^T (single pass) ----
        float sacc[16][4];
        #pragma unroll
        for (int j = 0; j < 16; j++)
            #pragma unroll
            for (int v = 0; v < 4; v++) sacc[j][v] = 0.f;

        #pragma unroll
        for (int ks = 0; ks < 4; ks++) {
            uint32_t ah0, ah1, ah2, ah3;
            LDSM4(ah0, ah1, ah2, ah3, aQh + ks * 32);
            #pragma unroll
            for (int jj = 0; jj < 8; jj++) {
                const int j0 = 2 * jj;
                const uint32_t kaddr =
                    bb + OFF_KH + (uint32_t)((j0 * 8 + nK) * AP + ks * 16 + kK) * 2;
                uint32_t b0, b1, b2, b3;
                LDSM4(b0, b1, b2, b3, kaddr);
                MMA16816(sacc[j0],     ah0, ah1, ah2, ah3, b0, b1);
                MMA16816(sacc[j0 + 1], ah0, ah1, ah2, ah3, b2, b3);
            }
        }

        // ---- bit-mask + online softmax ----
        const uint4 mw0 = *(const uint4*)(smn + QSZ + s * KVBUF + OFF_MK + (wq0 + r_lo) * 16);
        const uint4 mw1 = *(const uint4*)(smn + QSZ + s * KVBUF + OFF_MK + (wq0 + r_lo + 8) * 16);
        uint32_t w0a[4] = {mw0.x, mw0.y, mw0.z, mw0.w};
        uint32_t w1a[4] = {mw1.x, mw1.y, mw1.z, mw1.w};
        float tm0 = -1e30f, tm1 = -1e30f;
        #pragma unroll
        for (int j = 0; j < 16; j++) {
            const uint32_t bits0 = w0a[j >> 2] >> (8 * (j & 3) + 2 * c4);
            const uint32_t bits1 = w1a[j >> 2] >> (8 * (j & 3) + 2 * c4);
            float s0 = (bits0 & 1u) ? sacc[j][0] * 0.125f : -1e30f;
            float s1 = (bits0 & 2u) ? sacc[j][1] * 0.125f : -1e30f;
            float s2 = (bits1 & 1u) ? sacc[j][2] * 0.125f : -1e30f;
            float s3 = (bits1 & 2u) ? sacc[j][3] * 0.125f : -1e30f;
            sacc[j][0] = s0; sacc[j][1] = s1; sacc[j][2] = s2; sacc[j][3] = s3;
            tm0 = fmaxf(tm0, fmaxf(s0, s1));
            tm1 = fmaxf(tm1, fmaxf(s2, s3));
        }
        tm0 = fmaxf(tm0, __shfl_xor_sync(0xffffffffu, tm0, 1));
        tm0 = fmaxf(tm0, __shfl_xor_sync(0xffffffffu, tm0, 2));
        tm1 = fmaxf(tm1, __shfl_xor_sync(0xffffffffu, tm1, 1));
        tm1 = fmaxf(tm1, __shfl_xor_sync(0xffffffffu, tm1, 2));
        const float mn0 = fmaxf(m_r0, tm0), mn1 = fmaxf(m_r1, tm1);
        const float al_0 = __expf(m_r0 - mn0), al_1 = __expf(m_r1 - mn1);
        m_r0 = mn0; m_r1 = mn1;
        float ps0 = 0.f, ps1 = 0.f;
        #pragma unroll
        for (int j = 0; j < 16; j++) {
            float p0 = __expf(sacc[j][0] - mn0); sacc[j][0] = p0; ps0 += p0;
            float p1 = __expf(sacc[j][1] - mn0); sacc[j][1] = p1; ps0 += p1;
            float p2 = __expf(sacc[j][2] - mn1); sacc[j][2] = p2; ps1 += p2;
            float p3 = __expf(sacc[j][3] - mn1); sacc[j][3] = p3; ps1 += p3;
        }
        ps0 += __shfl_xor_sync(0xffffffffu, ps0, 1);
        ps0 += __shfl_xor_sync(0xffffffffu, ps0, 2);
        ps1 += __shfl_xor_sync(0xffffffffu, ps1, 1);
        ps1 += __shfl_xor_sync(0xffffffffu, ps1, 2);
        l_r0 = l_r0 * al_0 + ps0;
        l_r1 = l_r1 * al_1 + ps1;
        #pragma unroll
        for (int j = 0; j < 8; j++) {
            o[j][0] *= al_0; o[j][1] *= al_0; o[j][2] *= al_1; o[j][3] *= al_1;
        }

        // ---- O += Ph Vh (single pass, V via ldmatrix.trans) ----
        #pragma unroll
        for (int kt2 = 0; kt2 < 8; kt2++) {
            const int j0 = 2 * kt2;
            __half2 hp;
            hp = __floats2half2_rn(sacc[j0][0], sacc[j0][1]);
            const uint32_t p0 = *(uint32_t*)&hp;
            hp = __floats2half2_rn(sacc[j0][2], sacc[j0][3]);
            const uint32_t p1 = *(uint32_t*)&hp;
            hp = __floats2half2_rn(sacc[j0 + 1][0], sacc[j0 + 1][1]);
            const uint32_t p2 = *(uint32_t*)&hp;
            hp = __floats2half2_rn(sacc[j0 + 1][2], sacc[j0 + 1][3]);
            const uint32_t p3 = *(uint32_t*)&hp;
            #pragma unroll
            for (int jj = 0; jj < 4; jj++) {
                const int jv = 2 * jj;
                const uint32_t va =
                    bb + OFF_VH + (uint32_t)((kt2 * 16 + kV) * AP + jv * 8 + nV) * 2;
                uint32_t v0, v1, v2, v3;
                LDSM4T(v0, v1, v2, v3, va);
                MMA16816(o[jv],     p0, p1, p2, p3, v0, v1);
                MMA16816(o[jv + 1], p0, p1, p2, p3, v2, v3);
            }
        }
        __syncthreads();
    }

    // ---- epilogue: O/l -> fp16 into out-GEMM operand buffer ----
    const float inv0 = 1.f / fmaxf(l_r0, 1e-30f);
    const float inv1 = 1.f / fmaxf(l_r1, 1e-30f);
    const int r1g = qbase + wq0 + r_lo;
    #pragma unroll
    for (int j = 0; j < 8; j++) {
        const size_t idx0 = ((size_t)b * Sn + r1g) * Dn + h * 64 + j * 8 + 2 * c4;
        __half2 h2;
        h2 = __floats2half2_rn(o[j][0] * inv0, o[j][1] * inv0);
        *(uint32_t*)&g_ahi[idx0] = *(uint32_t*)&h2;
        h2 = __floats2half2_rn(o[j][2] * inv1, o[j][3] * inv1);
        *(uint32_t*)&g_ahi[idx0 + 8 * Dn] = *(uint32_t*)&h2;
    }
}

// ---------------------------------------------------------------------------
extern "C" void kernel_launch(void* const* d_in, const int* in_sizes, int n_in,
                              void* d_out, int out_size)
{
    const float* x    = (const float*)d_in[0];
    const void*  mask = d_in[1];
    const float* wq   = (const float*)d_in[2];
    const float* wk   = (const float*)d_in[3];
    const float* wv   = (const float*)d_in[4];
    const float* wo   = (const float*)d_in[5];
    float* out = (float*)d_out;

    cudaFuncSetAttribute(mma_gemm_kernel,
                         cudaFuncAttributeMaxDynamicSharedMemorySize, DYNSM);
    cudaFuncSetAttribute(attn_mma_kernel,
                         cudaFuncAttributeMaxDynamicSharedMemorySize, ATT_SMEM);

    detect_mask_kernel<<<1, 256>>>((const uint32_t*)mask);
    const size_t mask_elts = (size_t)Bn * Sn * Sn;
    pack_mask_kernel<<<(unsigned)(mask_elts / 1024), 256>>>(mask);

    __half *ahi, *whi;
    cudaGetSymbolAddress((void**)&ahi, g_ahi);
    cudaGetSymbolAddress((void**)&whi, g_whi);

    // X (8 slices) + 4 weights -> fp16 in one launch
    cvt_all_kernel<<<dim3((unsigned)((size_t)Dn * Dn / 1024), 12), 256>>>(x, wq, wk, wv, wo);

    // QKV projections -> fp16 Q/K/V, single-pass
    dim3 g1(Dn / 128, Mtot / 128, 3);
    mma_gemm_kernel<<<g1, 256, DYNSM>>>(ahi, whi, nullptr, 0);

    // Tensor-core flash attention -> writes g_ahi
    dim3 g2(Sn / 128, Bn * Hn);
    attn_mma_kernel<<<g2, 256, ATT_SMEM>>>();

    // Output projection (single-pass)
    dim3 g3(Dn / 128, Mtot / 128, 1);
    mma_gemm_kernel<<<g3, 256, DYNSM>>>(ahi, whi + 3 * (size_t)Dn * Dn, out, 1);
}

// round 11
// speedup vs baseline: 6.5528x; 1.0205x over previous
#include <cuda_runtime.h>
#include <cuda_fp16.h>
#include <stdint.h>

#define Bn 4
#define Sn 2048
#define Dn 1024
#define Hn 16
#define HDn 64
#define Mtot (Bn * Sn)          // 8192

// Scratch (static device globals -- allocation-free per harness rules)
__device__ uint32_t g_maskbits[(size_t)Bn * Sn * Sn / 32];   // 1 bit / elt
__device__ int      g_mask_flag;

// fp16 operand buffers (all hi-only)
__device__ __half g_ahi[(size_t)Mtot * Dn];   // X hi, then attn-out hi
__device__ __half g_whi[(size_t)4 * Dn * Dn]; // wq,wk,wv,wo hi
__device__ __half g_qhi[(size_t)Bn * Hn * Sn * HDn];  // [B,H,S,HD]
__device__ __half g_khi[(size_t)Bn * Hn * Sn * HDn];
__device__ __half g_vhi[(size_t)Bn * Hn * Sn * HDn];

// ===========================================================================
// PTX helpers (base ISA: ldmatrix / mma.sync / cp.async)
// ===========================================================================
__device__ __forceinline__ uint32_t smem_u32(const void* p) {
    uint32_t a;
    asm("{ .reg .u64 t; cvta.to.shared.u64 t, %1; cvt.u32.u64 %0, t; }" : "=r"(a) : "l"(p));
    return a;
}

#define LDSM4(r0, r1, r2, r3, addr) \
    asm volatile("ldmatrix.sync.aligned.m8n8.x4.shared.b16 {%0,%1,%2,%3}, [%4];" \
        : "=r"(r0), "=r"(r1), "=r"(r2), "=r"(r3) : "r"(addr))

#define LDSM4T(r0, r1, r2, r3, addr) \
    asm volatile("ldmatrix.sync.aligned.m8n8.x4.trans.shared.b16 {%0,%1,%2,%3}, [%4];" \
        : "=r"(r0), "=r"(r1), "=r"(r2), "=r"(r3) : "r"(addr))

#define MMA16816(c, a0, a1, a2, a3, b0, b1) \
    asm volatile("mma.sync.aligned.m16n8k16.row.col.f32.f16.f16.f32 " \
        "{%0,%1,%2,%3}, {%4,%5,%6,%7}, {%8,%9}, {%0,%1,%2,%3};" \
        : "+f"((c)[0]), "+f"((c)[1]), "+f"((c)[2]), "+f"((c)[3]) \
        : "r"(a0), "r"(a1), "r"(a2), "r"(a3), "r"(b0), "r"(b1))

#define CPA16(dst, src) \
    asm volatile("cp.async.cg.shared.global [%0], [%1], 16;" :: "r"(dst), "l"(src) : "memory")
#define CPA_COMMIT() asm volatile("cp.async.commit_group;" ::: "memory")
#define CPA_WAIT1()  asm volatile("cp.async.wait_group 1;" ::: "memory")
#define CPA_WAIT0()  asm volatile("cp.async.wait_group 0;" ::: "memory")

// ===========================================================================
// Mask: dtype sniffer + vectorized bit-packer (4 elems/thread, shuffle-OR)
// ===========================================================================
__global__ void detect_mask_kernel(const uint32_t* __restrict__ m)
{
    __shared__ int cnt_w;
    if (threadIdx.x == 0) cnt_w = 0;
    __syncthreads();
    uint32_t w = m[threadIdx.x];
    if (w == 0u || w == 1u || w == 0x3F800000u) atomicAdd(&cnt_w, 1);
    __syncthreads();
    if (threadIdx.x == 0) g_mask_flag = (cnt_w > 200) ? 1 : 0;  // 1 = 4-byte elems
}

__global__ __launch_bounds__(256) void pack_mask_kernel(const void* __restrict__ m)
{
    const size_t idx = (size_t)blockIdx.x * 256 + threadIdx.x;
    const int lane = threadIdx.x & 31;
    uint32_t nib;
    if (g_mask_flag) {
        uint4 v = ((const uint4*)m)[idx];
        nib = (v.x != 0u) | ((v.y != 0u) << 1) | ((v.z != 0u) << 2) | ((v.w != 0u) << 3);
    } else {
        uint32_t v = ((const uint32_t*)m)[idx];
        nib = ((v & 0x000000FFu) ? 1u : 0u) | ((v & 0x0000FF00u) ? 2u : 0u)
            | ((v & 0x00FF0000u) ? 4u : 0u) | ((v & 0xFF000000u) ? 8u : 0u);
    }
    uint32_t sh = nib << (4 * (lane & 7));
    sh |= __shfl_xor_sync(0xffffffffu, sh, 1);
    sh |= __shfl_xor_sync(0xffffffffu, sh, 2);
    sh |= __shfl_xor_sync(0xffffffffu, sh, 4);
    if ((lane & 7) == 0) g_maskbits[idx >> 3] = sh;
}

// ===========================================================================
// fp32 -> fp16 hi conversion: one launch covers X (8 slices) + 4 weights.
// ===========================================================================
__global__ __launch_bounds__(256) void cvt_all_kernel(
    const float* __restrict__ x,
    const float* __restrict__ w0, const float* __restrict__ w1,
    const float* __restrict__ w2, const float* __restrict__ w3)
{
    const int z = blockIdx.y;
    const float* src;
    __half* dst;
    if (z < 8) {
        src = x   + (size_t)z * (Mtot / 8) * Dn;
        dst = g_ahi + (size_t)z * (Mtot / 8) * Dn;
    } else {
        const float* ws[4] = {w0, w1, w2, w3};
        src = ws[z - 8];
        dst = g_whi + (size_t)(z - 8) * Dn * Dn;
    }
    const size_t i = (size_t)blockIdx.x * 256 + threadIdx.x;
    float4 v = ((const float4*)src)[i];
    __half2 a = __floats2half2_rn(v.x, v.y);
    __half2 b = __floats2half2_rn(v.z, v.w);
    ((uint2*)dst)[i] = make_uint2(*(uint32_t*)&a, *(uint32_t*)&b);
}

// ===========================================================================
// fp16 tensor-core GEMM (single pass): C[128x128] = Ah[.,1024] @ Wh[.,1024]^T
// 2 CTAs/SM for latency hiding (regs 126 <= 128, smem 2x40960 fits).
// ===========================================================================
#define KC 32
#define PITCH 40                 // halves per smem row (80 B)
#define TILE_B (128 * PITCH * 2) // 10240
#define STG (2 * TILE_B)         // Ah, Bh = 20480
#define DYNSM (2 * STG)          // 40960

__global__ __launch_bounds__(256, 2) void mma_gemm_kernel(
    const __half* __restrict__ Ahi,
    const __half* __restrict__ Whi,
    float* __restrict__ out,
    int mode)
{
    extern __shared__ char dsm[];
    const uint32_t sbase = smem_u32(dsm);

    const int tid  = threadIdx.x;
    const int lane = tid & 31;
    const int wid  = tid >> 5;
    const int wr   = wid >> 2;
    const int wc   = wid & 3;
    const int bm   = blockIdx.y * 128;
    const int bn   = blockIdx.x * 128;
    const int z    = blockIdx.z;

    const __half* WhiZ = Whi + (size_t)z * Dn * Dn;

    const int row = tid >> 1;
    const int gh  = tid & 1;
    const __half* sA_h = Ahi  + (size_t)(bm + row) * Dn + gh * 16;
    const __half* sB_h = WhiZ + (size_t)(bn + row) * Dn + gh * 16;
    const uint32_t sd0 = sbase + (uint32_t)row * (PITCH * 2) + gh * 32;

    const int NC = Dn / KC;     // 32
    auto issue = [&](int ck) {
        const uint32_t sd = sd0 + (ck & 1) * STG;
        const size_t o = (size_t)ck * KC;
        CPA16(sd,                 sA_h + o);
        CPA16(sd + 16,            sA_h + o + 8);
        CPA16(sd + TILE_B,        sB_h + o);
        CPA16(sd + TILE_B + 16,   sB_h + o + 8);
        CPA_COMMIT();
    };

    float acc[4][4][4];
    #pragma unroll
    for (int i = 0; i < 4; i++)
        #pragma unroll
        for (int j = 0; j < 4; j++)
            #pragma unroll
            for (int v = 0; v < 4; v++) acc[i][j][v] = 0.f;

    issue(0);
    issue(1);

    for (int ck = 0; ck < NC; ck++) {
        if (ck == NC - 1) { CPA_WAIT0(); } else { CPA_WAIT1(); }
        __syncthreads();

        const uint32_t stg = sbase + (ck & 1) * STG;
        #pragma unroll
        for (int ks = 0; ks < 2; ks++) {
            uint32_t b[4][2];
            #pragma unroll
            for (int jj = 0; jj < 2; jj++) {
                int n = wc * 32 + jj * 16 + ((lane >> 4) & 1) * 8 + (lane & 7);
                int k = ks * 16 + ((lane >> 3) & 1) * 8;
                uint32_t ad = stg + TILE_B + (uint32_t)(n * PITCH + k) * 2;
                LDSM4(b[2 * jj][0], b[2 * jj][1], b[2 * jj + 1][0], b[2 * jj + 1][1], ad);
            }
            #pragma unroll
            for (int i = 0; i < 4; i++) {
                int m = wr * 64 + i * 16 + ((lane >> 3) & 1) * 8 + (lane & 7);
                int k = ks * 16 + ((lane >> 4) & 1) * 8;
                uint32_t adh = stg + (uint32_t)(m * PITCH + k) * 2;
                uint32_t a0, a1, a2, a3;
                LDSM4(a0, a1, a2, a3, adh);
                #pragma unroll
                for (int j = 0; j < 4; j++)
                    MMA16816(acc[i][j], a0, a1, a2, a3, b[j][0], b[j][1]);
            }
        }
        __syncthreads();
        if (ck + 2 < NC) issue(ck + 2);
    }

    // ---- epilogue ----
    #pragma unroll
    for (int i = 0; i < 4; i++) {
        #pragma unroll
        for (int j = 0; j < 4; j++) {
            int ml = wr * 64 + i * 16 + (lane >> 2);
            int nl = wc * 32 + j * 8 + 2 * (lane & 3);
            int m = bm + ml, n = bn + nl;
            if (mode == 0) {
                __half* dh = (z == 0) ? g_qhi : (z == 1) ? g_khi : g_vhi;
                int bb2 = m >> 11, ss = m & 2047;
                int hh = n >> 6,  hd = n & 63;
                size_t base = (((size_t)bb2 * Hn + hh) * Sn + ss) * HDn + hd;
                __half2 h = __floats2half2_rn(acc[i][j][0], acc[i][j][1]);
                *(uint32_t*)&dh[base] = *(uint32_t*)&h;
                h = __floats2half2_rn(acc[i][j][2], acc[i][j][3]);
                *(uint32_t*)&dh[base + 8 * HDn] = *(uint32_t*)&h;
            } else {
                *(float2*)&out[(size_t)m * Dn + n] =
                    make_float2(acc[i][j][0], acc[i][j][1]);
                *(float2*)&out[(size_t)(m + 8) * Dn + n] =
                    make_float2(acc[i][j][2], acc[i][j][3]);
            }
        }
    }
}

// ===========================================================================
// Tensor-core flash attention, single-pass fp16 MMAs (Qh*Kh, Ph*Vh).
// 2 CTAs/SM (smem 2x96256 = 188 KB fits; regs capped at 128).
// ===========================================================================
#define AP     72                 // halves per row (144 B)
#define APB    144
#define TILE18 18432              // 128 * 144
#define OFF_KH 0
#define OFF_VH 18432
#define OFF_MK 36864              // 128 rows x 16 B of bits
#define KVBUF  38912              // 2*18432 + 2048
#define QSZ    18432
#define ATT_SMEM (QSZ + 2 * KVBUF)   // 96256

__global__ __launch_bounds__(256, 2) void attn_mma_kernel()
{
    extern __shared__ char smn[];
    const uint32_t sb = smem_u32(smn);
    const int tid = threadIdx.x, lane = tid & 31, w = tid >> 5;
    const int qt = blockIdx.x, bh = blockIdx.y;
    const int b = bh >> 4, h = bh & 15;
    const int qbase = qt * 128;
    const size_t head = (size_t)bh * Sn * HDn;
    const int row = tid >> 1, seg = tid & 1;
    const uint32_t rowb = (uint32_t)row * APB + seg * 64;

    // Q tile (persistent)
    {
        const uint4* qh = (const uint4*)(g_qhi + head + (size_t)(qbase + row) * HDn + seg * 32);
        uint4* dh = (uint4*)(smn + rowb);
        #pragma unroll
        for (int i = 0; i < 4; i++) dh[i] = qh[i];
    }

    const char* mbits_row = (const char*)g_maskbits + ((size_t)b * Sn + qbase + row) * (Sn / 8);
    const char* gkh = (const char*)(g_khi + head + (size_t)row * HDn + seg * 32);
    const char* gvh = (const char*)(g_vhi + head + (size_t)row * HDn + seg * 32);

    auto issue_tile = [&](int kt, int s) {
        const uint32_t bb = sb + QSZ + s * KVBUF;
        const size_t go = (size_t)kt * 128 * HDn * 2;
        #pragma unroll
        for (int i = 0; i < 4; i++) {
            CPA16(bb + OFF_KH + rowb + i * 16, gkh + go + i * 16);
            CPA16(bb + OFF_VH + rowb + i * 16, gvh + go + i * 16);
        }
        if (seg == 0)
            CPA16(bb + OFF_MK + (uint32_t)row * 16, mbits_row + kt * 16);
        CPA_COMMIT();
    };

    float o[8][4];
    #pragma unroll
    for (int j = 0; j < 8; j++)
        #pragma unroll
        for (int v = 0; v < 4; v++) o[j][v] = 0.f;
    float m_r0 = -1e30f, m_r1 = -1e30f, l_r0 = 0.f, l_r1 = 0.f;

    const int wq0  = w * 16;
    const int r_lo = lane >> 2, c4 = lane & 3;
    const int mA = wq0 + ((lane >> 3) & 1) * 8 + (lane & 7);
    const int kA = ((lane >> 4) & 1) * 8;
    const uint32_t aQh = sb + (uint32_t)(mA * AP + kA) * 2;
    const int nK = ((lane >> 4) & 1) * 8 + (lane & 7);
    const int kK = ((lane >> 3) & 1) * 8;
    const int kV = ((lane >> 3) & 1) * 8 + (lane & 7);
    const int nV = ((lane >> 4) & 1) * 8;

    issue_tile(0, 0);

    for (int kt = 0; kt < 16; kt++) {
        const int s = kt & 1;
        if (kt < 15) { issue_tile(kt + 1, s ^ 1); CPA_WAIT1(); }
        else         { CPA_WAIT0(); }
        __syncthreads();
        const uint32_t bb = sb + QSZ + s * KVBUF;

        // ---- S = Qh Kh^T (single pass) ----
        float sacc[16][4];
        #pragma unroll
        for (int j = 0; j < 16; j++)
            #pragma unroll
            for (int v = 0; v < 4; v++) sacc[j][v] = 0.f;

        #pragma unroll
        for (int ks = 0; ks < 4; ks++) {
            uint32_t ah0, ah1, ah2, ah3;
            LDSM4(ah0, ah1, ah2, ah3, aQh + ks * 32);
            #pragma unroll
            for (int jj = 0; jj < 8; jj++) {
                const int j0 = 2 * jj;
                const uint32_t kaddr =
                    bb + OFF_KH + (uint32_t)((j0 * 8 + nK) * AP + ks * 16 + kK) * 2;
                uint32_t b0, b1, b2, b3;
                LDSM4(b0, b1, b2, b3, kaddr);
                MMA16816(sacc[j0],     ah0, ah1, ah2, ah3, b0, b1);
                MMA16816(sacc[j0 + 1], ah0, ah1, ah2, ah3, b2, b3);
            }
        }

        // ---- bit-mask + online softmax ----
        const uint4 mw0 = *(const uint4*)(smn + QSZ + s * KVBUF + OFF_MK + (wq0 + r_lo) * 16);
        const uint4 mw1 = *(const uint4*)(smn + QSZ + s * KVBUF + OFF_MK + (wq0 + r_lo + 8) * 16);
        uint32_t w0a[4] = {mw0.x, mw0.y, mw0.z, mw0.w};
        uint32_t w1a[4] = {mw1.x, mw1.y, mw1.z, mw1.w};
        float tm0 = -1e30f, tm1 = -1e30f;
        #pragma unroll
        for (int j = 0; j < 16; j++) {
            const uint32_t bits0 = w0a[j >> 2] >> (8 * (j & 3) + 2 * c4);
            const uint32_t bits1 = w1a[j >> 2] >> (8 * (j & 3) + 2 * c4);
            float s0 = (bits0 & 1u) ? sacc[j][0] * 0.125f : -1e30f;
            float s1 = (bits0 & 2u) ? sacc[j][1] * 0.125f : -1e30f;
            float s2 = (bits1 & 1u) ? sacc[j][2] * 0.125f : -1e30f;
            float s3 = (bits1 & 2u) ? sacc[j][3] * 0.125f : -1e30f;
            sacc[j][0] = s0; sacc[j][1] = s1; sacc[j][2] = s2; sacc[j][3] = s3;
            tm0 = fmaxf(tm0, fmaxf(s0, s1));
            tm1 = fmaxf(tm1, fmaxf(s2, s3));
        }
        tm0 = fmaxf(tm0, __shfl_xor_sync(0xffffffffu, tm0, 1));
        tm0 = fmaxf(tm0, __shfl_xor_sync(0xffffffffu, tm0, 2));
        tm1 = fmaxf(tm1, __shfl_xor_sync(0xffffffffu, tm1, 1));
        tm1 = fmaxf(tm1, __shfl_xor_sync(0xffffffffu, tm1, 2));
        const float mn0 = fmaxf(m_r0, tm0), mn1 = fmaxf(m_r1, tm1);
        const float al_0 = __expf(m_r0 - mn0), al_1 = __expf(m_r1 - mn1);
        m_r0 = mn0; m_r1 = mn1;
        float ps0 = 0.f, ps1 = 0.f;
        #pragma unroll
        for (int j = 0; j < 16; j++) {
            float p0 = __expf(sacc[j][0] - mn0); sacc[j][0] = p0; ps0 += p0;
            float p1 = __expf(sacc[j][1] - mn0); sacc[j][1] = p1; ps0 += p1;
            float p2 = __expf(sacc[j][2] - mn1); sacc[j][2] = p2; ps1 += p2;
            float p3 = __expf(sacc[j][3] - mn1); sacc[j][3] = p3; ps1 += p3;
        }
        ps0 += __shfl_xor_sync(0xffffffffu, ps0, 1);
        ps0 += __shfl_xor_sync(0xffffffffu, ps0, 2);
        ps1 += __shfl_xor_sync(0xffffffffu, ps1, 1);
        ps1 += __shfl_xor_sync(0xffffffffu, ps1, 2);
        l_r0 = l_r0 * al_0 + ps0;
        l_r1 = l_r1 * al_1 + ps1;
        #pragma unroll
        for (int j = 0; j < 8; j++) {
            o[j][0] *= al_0; o[j][1] *= al_0; o[j][2] *= al_1; o[j][3] *= al_1;
        }

        // ---- O += Ph Vh (single pass, V via ldmatrix.trans) ----
        #pragma unroll
        for (int kt2 = 0; kt2 < 8; kt2++) {
            const int j0 = 2 * kt2;
            __half2 hp;
            hp = __floats2half2_rn(sacc[j0][0], sacc[j0][1]);
            const uint32_t p0 = *(uint32_t*)&hp;
            hp = __floats2half2_rn(sacc[j0][2], sacc[j0][3]);
            const uint32_t p1 = *(uint32_t*)&hp;
            hp = __floats2half2_rn(sacc[j0 + 1][0], sacc[j0 + 1][1]);
            const uint32_t p2 = *(uint32_t*)&hp;
            hp = __floats2half2_rn(sacc[j0 + 1][2], sacc[j0 + 1][3]);
            const uint32_t p3 = *(uint32_t*)&hp;
            #pragma unroll
            for (int jj = 0; jj < 4; jj++) {
                const int jv = 2 * jj;
                const uint32_t va =
                    bb + OFF_VH + (uint32_t)((kt2 * 16 + kV) * AP + jv * 8 + nV) * 2;
                uint32_t v0, v1, v2, v3;
                LDSM4T(v0, v1, v2, v3, va);
                MMA16816(o[jv],     p0, p1, p2, p3, v0, v1);
                MMA16816(o[jv + 1], p0, p1, p2, p3, v2, v3);
            }
        }
        __syncthreads();
    }

    // ---- epilogue: O/l -> fp16 into out-GEMM operand buffer ----
    const float inv0 = 1.f / fmaxf(l_r0, 1e-30f);
    const float inv1 = 1.f / fmaxf(l_r1, 1e-30f);
    const int r1g = qbase + wq0 + r_lo;
    #pragma unroll
    for (int j = 0; j < 8; j++) {
        const size_t idx0 = ((size_t)b * Sn + r1g) * Dn + h * 64 + j * 8 + 2 * c4;
        __half2 h2;
        h2 = __floats2half2_rn(o[j][0] * inv0, o[j][1] * inv0);
        *(uint32_t*)&g_ahi[idx0] = *(uint32_t*)&h2;
        h2 = __floats2half2_rn(o[j][2] * inv1, o[j][3] * inv1);
        *(uint32_t*)&g_ahi[idx0 + 8 * Dn] = *(uint32_t*)&h2;
    }
}

// ---------------------------------------------------------------------------
extern "C" void kernel_launch(void* const* d_in, const int* in_sizes, int n_in,
                              void* d_out, int out_size)
{
    const float* x    = (const float*)d_in[0];
    const void*  mask = d_in[1];
    const float* wq   = (const float*)d_in[2];
    const float* wk   = (const float*)d_in[3];
    const float* wv   = (const float*)d_in[4];
    const float* wo   = (const float*)d_in[5];
    float* out = (float*)d_out;

    cudaFuncSetAttribute(mma_gemm_kernel,
                         cudaFuncAttributeMaxDynamicSharedMemorySize, DYNSM);
    cudaFuncSetAttribute(attn_mma_kernel,
                         cudaFuncAttributeMaxDynamicSharedMemorySize, ATT_SMEM);

    detect_mask_kernel<<<1, 256>>>((const uint32_t*)mask);
    const size_t mask_elts = (size_t)Bn * Sn * Sn;
    pack_mask_kernel<<<(unsigned)(mask_elts / 1024), 256>>>(mask);

    __half *ahi, *whi;
    cudaGetSymbolAddress((void**)&ahi, g_ahi);
    cudaGetSymbolAddress((void**)&whi, g_whi);

    // X (8 slices) + 4 weights -> fp16 in one launch
    cvt_all_kernel<<<dim3((unsigned)((size_t)Dn * Dn / 1024), 12), 256>>>(x, wq, wk, wv, wo);

    // QKV projections -> fp16 Q/K/V, single-pass
    dim3 g1(Dn / 128, Mtot / 128, 3);
    mma_gemm_kernel<<<g1, 256, DYNSM>>>(ahi, whi, nullptr, 0);

    // Tensor-core flash attention -> writes g_ahi
    dim3 g2(Sn / 128, Bn * Hn);
    attn_mma_kernel<<<g2, 256, ATT_SMEM>>>();

    // Output projection (single-pass)
    dim3 g3(Dn / 128, Mtot / 128, 1);
    mma_gemm_kernel<<<g3, 256, DYNSM>>>(ahi, whi + 3 * (size_t)Dn * Dn, out, 1);
}

// round 12
// speedup vs baseline: 6.7922x; 1.0365x over previous
#include <cuda_runtime.h>
#include <cuda_fp16.h>
#include <stdint.h>

#define Bn 4
#define Sn 2048
#define Dn 1024
#define Hn 16
#define HDn 64
#define Mtot (Bn * Sn)          // 8192

// Scratch (static device globals -- allocation-free per harness rules)
__device__ uint32_t g_maskbits[(size_t)Bn * Sn * Sn / 32];   // 1 bit / elt
__device__ int      g_mask_flag;

// fp16 operand buffers (all hi-only)
__device__ __half g_ahi[(size_t)Mtot * Dn];   // X hi, then attn-out hi
__device__ __half g_whi[(size_t)4 * Dn * Dn]; // wq,wk,wv,wo hi
__device__ __half g_qhi[(size_t)Bn * Hn * Sn * HDn];  // [B,H,S,HD]
__device__ __half g_khi[(size_t)Bn * Hn * Sn * HDn];
__device__ __half g_vhi[(size_t)Bn * Hn * Sn * HDn];

// ===========================================================================
// PTX helpers (base ISA: ldmatrix / mma.sync / cp.async)
// ===========================================================================
__device__ __forceinline__ uint32_t smem_u32(const void* p) {
    uint32_t a;
    asm("{ .reg .u64 t; cvta.to.shared.u64 t, %1; cvt.u32.u64 %0, t; }" : "=r"(a) : "l"(p));
    return a;
}

#define LDSM4(r0, r1, r2, r3, addr) \
    asm volatile("ldmatrix.sync.aligned.m8n8.x4.shared.b16 {%0,%1,%2,%3}, [%4];" \
        : "=r"(r0), "=r"(r1), "=r"(r2), "=r"(r3) : "r"(addr))

#define LDSM4T(r0, r1, r2, r3, addr) \
    asm volatile("ldmatrix.sync.aligned.m8n8.x4.trans.shared.b16 {%0,%1,%2,%3}, [%4];" \
        : "=r"(r0), "=r"(r1), "=r"(r2), "=r"(r3) : "r"(addr))

#define MMA16816(c, a0, a1, a2, a3, b0, b1) \
    asm volatile("mma.sync.aligned.m16n8k16.row.col.f32.f16.f16.f32 " \
        "{%0,%1,%2,%3}, {%4,%5,%6,%7}, {%8,%9}, {%0,%1,%2,%3};" \
        : "+f"((c)[0]), "+f"((c)[1]), "+f"((c)[2]), "+f"((c)[3]) \
        : "r"(a0), "r"(a1), "r"(a2), "r"(a3), "r"(b0), "r"(b1))

#define CPA16(dst, src) \
    asm volatile("cp.async.cg.shared.global [%0], [%1], 16;" :: "r"(dst), "l"(src) : "memory")
#define CPA_COMMIT() asm volatile("cp.async.commit_group;" ::: "memory")
#define CPA_WAITG(n) asm volatile("cp.async.wait_group %0;" :: "n"(n) : "memory")

// ===========================================================================
// Mask: dtype sniffer + vectorized bit-packer (4 elems/thread, shuffle-OR)
// ===========================================================================
__global__ void detect_mask_kernel(const uint32_t* __restrict__ m)
{
    __shared__ int cnt_w;
    if (threadIdx.x == 0) cnt_w = 0;
    __syncthreads();
    uint32_t w = m[threadIdx.x];
    if (w == 0u || w == 1u || w == 0x3F800000u) atomicAdd(&cnt_w, 1);
    __syncthreads();
    if (threadIdx.x == 0) g_mask_flag = (cnt_w > 200) ? 1 : 0;  // 1 = 4-byte elems
}

__global__ __launch_bounds__(256) void pack_mask_kernel(const void* __restrict__ m)
{
    const size_t idx = (size_t)blockIdx.x * 256 + threadIdx.x;
    const int lane = threadIdx.x & 31;
    uint32_t nib;
    if (g_mask_flag) {
        uint4 v = ((const uint4*)m)[idx];
        nib = (v.x != 0u) | ((v.y != 0u) << 1) | ((v.z != 0u) << 2) | ((v.w != 0u) << 3);
    } else {
        uint32_t v = ((const uint32_t*)m)[idx];
        nib = ((v & 0x000000FFu) ? 1u : 0u) | ((v & 0x0000FF00u) ? 2u : 0u)
            | ((v & 0x00FF0000u) ? 4u : 0u) | ((v & 0xFF000000u) ? 8u : 0u);
    }
    uint32_t sh = nib << (4 * (lane & 7));
    sh |= __shfl_xor_sync(0xffffffffu, sh, 1);
    sh |= __shfl_xor_sync(0xffffffffu, sh, 2);
    sh |= __shfl_xor_sync(0xffffffffu, sh, 4);
    if ((lane & 7) == 0) g_maskbits[idx >> 3] = sh;
}

// ===========================================================================
// fp32 -> fp16 hi conversion: one launch covers X (8 slices) + 4 weights.
// ===========================================================================
__global__ __launch_bounds__(256) void cvt_all_kernel(
    const float* __restrict__ x,
    const float* __restrict__ w0, const float* __restrict__ w1,
    const float* __restrict__ w2, const float* __restrict__ w3)
{
    const int z = blockIdx.y;
    const float* src;
    __half* dst;
    if (z < 8) {
        src = x   + (size_t)z * (Mtot / 8) * Dn;
        dst = g_ahi + (size_t)z * (Mtot / 8) * Dn;
    } else {
        const float* ws[4] = {w0, w1, w2, w3};
        src = ws[z - 8];
        dst = g_whi + (size_t)(z - 8) * Dn * Dn;
    }
    const size_t i = (size_t)blockIdx.x * 256 + threadIdx.x;
    float4 v = ((const float4*)src)[i];
    __half2 a = __floats2half2_rn(v.x, v.y);
    __half2 b = __floats2half2_rn(v.z, v.w);
    ((uint2*)dst)[i] = make_uint2(*(uint32_t*)&a, *(uint32_t*)&b);
}

// ===========================================================================
// fp16 tensor-core GEMM (single pass): C[128x128] = Ah[.,1024] @ Wh[.,1024]^T
// 4-stage cp.async ring, ONE __syncthreads per K-chunk.
// ===========================================================================
#define KC 32
#define PITCH 40                 // halves per smem row (80 B)
#define TILE_B (128 * PITCH * 2) // 10240
#define STG (2 * TILE_B)         // Ah, Bh = 20480
#define NSTAGE 4
#define DYNSM (NSTAGE * STG)     // 81920

__global__ __launch_bounds__(256, 2) void mma_gemm_kernel(
    const __half* __restrict__ Ahi,
    const __half* __restrict__ Whi,
    float* __restrict__ out,
    int mode)
{
    extern __shared__ char dsm[];
    const uint32_t sbase = smem_u32(dsm);

    const int tid  = threadIdx.x;
    const int lane = tid & 31;
    const int wid  = tid >> 5;
    const int wr   = wid >> 2;
    const int wc   = wid & 3;
    const int bm   = blockIdx.y * 128;
    const int bn   = blockIdx.x * 128;
    const int z    = blockIdx.z;

    const __half* WhiZ = Whi + (size_t)z * Dn * Dn;

    const int row = tid >> 1;
    const int gh  = tid & 1;
    const __half* sA_h = Ahi  + (size_t)(bm + row) * Dn + gh * 16;
    const __half* sB_h = WhiZ + (size_t)(bn + row) * Dn + gh * 16;
    const uint32_t sd0 = sbase + (uint32_t)row * (PITCH * 2) + gh * 32;

    const int NC = Dn / KC;     // 32
    auto issue = [&](int ck) {
        const uint32_t sd = sd0 + (ck & (NSTAGE - 1)) * STG;
        const size_t o = (size_t)ck * KC;
        CPA16(sd,                 sA_h + o);
        CPA16(sd + 16,            sA_h + o + 8);
        CPA16(sd + TILE_B,        sB_h + o);
        CPA16(sd + TILE_B + 16,   sB_h + o + 8);
        CPA_COMMIT();
    };

    float acc[4][4][4];
    #pragma unroll
    for (int i = 0; i < 4; i++)
        #pragma unroll
        for (int j = 0; j < 4; j++)
            #pragma unroll
            for (int v = 0; v < 4; v++) acc[i][j][v] = 0.f;

    issue(0);
    issue(1);
    issue(2);

    for (int ck = 0; ck < NC; ck++) {
        // wait so that chunk ck is complete (exact tail drain)
        if (ck <= NC - 3)      { CPA_WAITG(2); }
        else if (ck == NC - 2) { CPA_WAITG(1); }
        else                   { CPA_WAITG(0); }
        __syncthreads();
        if (ck + 3 < NC) issue(ck + 3);   // writes stage (ck-1)%4, freed by sync

        const uint32_t stg = sbase + (ck & (NSTAGE - 1)) * STG;
        #pragma unroll
        for (int ks = 0; ks < 2; ks++) {
            uint32_t b[4][2];
            #pragma unroll
            for (int jj = 0; jj < 2; jj++) {
                int n = wc * 32 + jj * 16 + ((lane >> 4) & 1) * 8 + (lane & 7);
                int k = ks * 16 + ((lane >> 3) & 1) * 8;
                uint32_t ad = stg + TILE_B + (uint32_t)(n * PITCH + k) * 2;
                LDSM4(b[2 * jj][0], b[2 * jj][1], b[2 * jj + 1][0], b[2 * jj + 1][1], ad);
            }
            #pragma unroll
            for (int i = 0; i < 4; i++) {
                int m = wr * 64 + i * 16 + ((lane >> 3) & 1) * 8 + (lane & 7);
                int k = ks * 16 + ((lane >> 4) & 1) * 8;
                uint32_t adh = stg + (uint32_t)(m * PITCH + k) * 2;
                uint32_t a0, a1, a2, a3;
                LDSM4(a0, a1, a2, a3, adh);
                #pragma unroll
                for (int j = 0; j < 4; j++)
                    MMA16816(acc[i][j], a0, a1, a2, a3, b[j][0], b[j][1]);
            }
        }
    }

    // ---- epilogue ----
    #pragma unroll
    for (int i = 0; i < 4; i++) {
        #pragma unroll
        for (int j = 0; j < 4; j++) {
            int ml = wr * 64 + i * 16 + (lane >> 2);
            int nl = wc * 32 + j * 8 + 2 * (lane & 3);
            int m = bm + ml, n = bn + nl;
            if (mode == 0) {
                __half* dh = (z == 0) ? g_qhi : (z == 1) ? g_khi : g_vhi;
                int bb2 = m >> 11, ss = m & 2047;
                int hh = n >> 6,  hd = n & 63;
                size_t base = (((size_t)bb2 * Hn + hh) * Sn + ss) * HDn + hd;
                __half2 h = __floats2half2_rn(acc[i][j][0], acc[i][j][1]);
                *(uint32_t*)&dh[base] = *(uint32_t*)&h;
                h = __floats2half2_rn(acc[i][j][2], acc[i][j][3]);
                *(uint32_t*)&dh[base + 8 * HDn] = *(uint32_t*)&h;
            } else {
                *(float2*)&out[(size_t)m * Dn + n] =
                    make_float2(acc[i][j][0], acc[i][j][1]);
                *(float2*)&out[(size_t)(m + 8) * Dn + n] =
                    make_float2(acc[i][j][2], acc[i][j][3]);
            }
        }
    }
}

// ===========================================================================
// Tensor-core flash attention, single-pass fp16 MMAs (Qh*Kh, Ph*Vh).
// 2-stage cp.async, ONE __syncthreads per K-tile (wait -> sync -> issue).
// ===========================================================================
#define AP     72                 // halves per row (144 B)
#define APB    144
#define TILE18 18432              // 128 * 144
#define OFF_KH 0
#define OFF_VH 18432
#define OFF_MK 36864              // 128 rows x 16 B of bits
#define KVBUF  38912              // 2*18432 + 2048
#define QSZ    18432
#define ATT_SMEM (QSZ + 2 * KVBUF)   // 96256

__global__ __launch_bounds__(256, 2) void attn_mma_kernel()
{
    extern __shared__ char smn[];
    const uint32_t sb = smem_u32(smn);
    const int tid = threadIdx.x, lane = tid & 31, w = tid >> 5;
    const int qt = blockIdx.x, bh = blockIdx.y;
    const int b = bh >> 4, h = bh & 15;
    const int qbase = qt * 128;
    const size_t head = (size_t)bh * Sn * HDn;
    const int row = tid >> 1, seg = tid & 1;
    const uint32_t rowb = (uint32_t)row * APB + seg * 64;

    // Q tile (persistent)
    {
        const uint4* qh = (const uint4*)(g_qhi + head + (size_t)(qbase + row) * HDn + seg * 32);
        uint4* dh = (uint4*)(smn + rowb);
        #pragma unroll
        for (int i = 0; i < 4; i++) dh[i] = qh[i];
    }

    const char* mbits_row = (const char*)g_maskbits + ((size_t)b * Sn + qbase + row) * (Sn / 8);
    const char* gkh = (const char*)(g_khi + head + (size_t)row * HDn + seg * 32);
    const char* gvh = (const char*)(g_vhi + head + (size_t)row * HDn + seg * 32);

    auto issue_tile = [&](int kt, int s) {
        const uint32_t bb = sb + QSZ + s * KVBUF;
        const size_t go = (size_t)kt * 128 * HDn * 2;
        #pragma unroll
        for (int i = 0; i < 4; i++) {
            CPA16(bb + OFF_KH + rowb + i * 16, gkh + go + i * 16);
            CPA16(bb + OFF_VH + rowb + i * 16, gvh + go + i * 16);
        }
        if (seg == 0)
            CPA16(bb + OFF_MK + (uint32_t)row * 16, mbits_row + kt * 16);
        CPA_COMMIT();
    };

    float o[8][4];
    #pragma unroll
    for (int j = 0; j < 8; j++)
        #pragma unroll
        for (int v = 0; v < 4; v++) o[j][v] = 0.f;
    float m_r0 = -1e30f, m_r1 = -1e30f, l_r0 = 0.f, l_r1 = 0.f;

    const int wq0  = w * 16;
    const int r_lo = lane >> 2, c4 = lane & 3;
    const int mA = wq0 + ((lane >> 3) & 1) * 8 + (lane & 7);
    const int kA = ((lane >> 4) & 1) * 8;
    const uint32_t aQh = sb + (uint32_t)(mA * AP + kA) * 2;
    const int nK = ((lane >> 4) & 1) * 8 + (lane & 7);
    const int kK = ((lane >> 3) & 1) * 8;
    const int kV = ((lane >> 3) & 1) * 8 + (lane & 7);
    const int nV = ((lane >> 4) & 1) * 8;

    issue_tile(0, 0);

    for (int kt = 0; kt < 16; kt++) {
        const int s = kt & 1;
        CPA_WAITG(0);            // tile kt complete (only one in flight)
        __syncthreads();         // all warps done with buffer s (prev use)
        if (kt < 15) issue_tile(kt + 1, s ^ 1);   // overlaps compute below
        const uint32_t bb = sb + QSZ + s * KVBUF;

        // ---- S = Qh Kh^T (single pass) ----
        float sacc[16][4];
        #pragma unroll
        for (int j = 0; j < 16; j++)
            #pragma unroll
            for (int v = 0; v < 4; v++) sacc[j][v] = 0.f;

        #pragma unroll
        for (int ks = 0; ks < 4; ks++) {
            uint32_t ah0, ah1, ah2, ah3;
            LDSM4(ah0, ah1, ah2, ah3, aQh + ks * 32);
            #pragma unroll
            for (int jj = 0; jj < 8; jj++) {
                const int j0 = 2 * jj;
                const uint32_t kaddr =
                    bb + OFF_KH + (uint32_t)((j0 * 8 + nK) * AP + ks * 16 + kK) * 2;
                uint32_t b0, b1, b2, b3;
                LDSM4(b0, b1, b2, b3, kaddr);
                MMA16816(sacc[j0],     ah0, ah1, ah2, ah3, b0, b1);
                MMA16816(sacc[j0 + 1], ah0, ah1, ah2, ah3, b2, b3);
            }
        }

        // ---- bit-mask + online softmax ----
        const uint4 mw0 = *(const uint4*)(smn + QSZ + s * KVBUF + OFF_MK + (wq0 + r_lo) * 16);
        const uint4 mw1 = *(const uint4*)(smn + QSZ + s * KVBUF + OFF_MK + (wq0 + r_lo + 8) * 16);
        uint32_t w0a[4] = {mw0.x, mw0.y, mw0.z, mw0.w};
        uint32_t w1a[4] = {mw1.x, mw1.y, mw1.z, mw1.w};
        float tm0 = -1e30f, tm1 = -1e30f;
        #pragma unroll
        for (int j = 0; j < 16; j++) {
            const uint32_t bits0 = w0a[j >> 2] >> (8 * (j & 3) + 2 * c4);
            const uint32_t bits1 = w1a[j >> 2] >> (8 * (j & 3) + 2 * c4);
            float s0 = (bits0 & 1u) ? sacc[j][0] * 0.125f : -1e30f;
            float s1 = (bits0 & 2u) ? sacc[j][1] * 0.125f : -1e30f;
            float s2 = (bits1 & 1u) ? sacc[j][2] * 0.125f : -1e30f;
            float s3 = (bits1 & 2u) ? sacc[j][3] * 0.125f : -1e30f;
            sacc[j][0] = s0; sacc[j][1] = s1; sacc[j][2] = s2; sacc[j][3] = s3;
            tm0 = fmaxf(tm0, fmaxf(s0, s1));
            tm1 = fmaxf(tm1, fmaxf(s2, s3));
        }
        tm0 = fmaxf(tm0, __shfl_xor_sync(0xffffffffu, tm0, 1));
        tm0 = fmaxf(tm0, __shfl_xor_sync(0xffffffffu, tm0, 2));
        tm1 = fmaxf(tm1, __shfl_xor_sync(0xffffffffu, tm1, 1));
        tm1 = fmaxf(tm1, __shfl_xor_sync(0xffffffffu, tm1, 2));
        const float mn0 = fmaxf(m_r0, tm0), mn1 = fmaxf(m_r1, tm1);
        const float al_0 = __expf(m_r0 - mn0), al_1 = __expf(m_r1 - mn1);
        m_r0 = mn0; m_r1 = mn1;
        float ps0 = 0.f, ps1 = 0.f;
        #pragma unroll
        for (int j = 0; j < 16; j++) {
            float p0 = __expf(sacc[j][0] - mn0); sacc[j][0] = p0; ps0 += p0;
            float p1 = __expf(sacc[j][1] - mn0); sacc[j][1] = p1; ps0 += p1;
            float p2 = __expf(sacc[j][2] - mn1); sacc[j][2] = p2; ps1 += p2;
            float p3 = __expf(sacc[j][3] - mn1); sacc[j][3] = p3; ps1 += p3;
        }
        ps0 += __shfl_xor_sync(0xffffffffu, ps0, 1);
        ps0 += __shfl_xor_sync(0xffffffffu, ps0, 2);
        ps1 += __shfl_xor_sync(0xffffffffu, ps1, 1);
        ps1 += __shfl_xor_sync(0xffffffffu, ps1, 2);
        l_r0 = l_r0 * al_0 + ps0;
        l_r1 = l_r1 * al_1 + ps1;
        #pragma unroll
        for (int j = 0; j < 8; j++) {
            o[j][0] *= al_0; o[j][1] *= al_0; o[j][2] *= al_1; o[j][3] *= al_1;
        }

        // ---- O += Ph Vh (single pass, V via ldmatrix.trans) ----
        #pragma unroll
        for (int kt2 = 0; kt2 < 8; kt2++) {
            const int j0 = 2 * kt2;
            __half2 hp;
            hp = __floats2half2_rn(sacc[j0][0], sacc[j0][1]);
            const uint32_t p0 = *(uint32_t*)&hp;
            hp = __floats2half2_rn(sacc[j0][2], sacc[j0][3]);
            const uint32_t p1 = *(uint32_t*)&hp;
            hp = __floats2half2_rn(sacc[j0 + 1][0], sacc[j0 + 1][1]);
            const uint32_t p2 = *(uint32_t*)&hp;
            hp = __floats2half2_rn(sacc[j0 + 1][2], sacc[j0 + 1][3]);
            const uint32_t p3 = *(uint32_t*)&hp;
            #pragma unroll
            for (int jj = 0; jj < 4; jj++) {
                const int jv = 2 * jj;
                const uint32_t va =
                    bb + OFF_VH + (uint32_t)((kt2 * 16 + kV) * AP + jv * 8 + nV) * 2;
                uint32_t v0, v1, v2, v3;
                LDSM4T(v0, v1, v2, v3, va);
                MMA16816(o[jv],     p0, p1, p2, p3, v0, v1);
                MMA16816(o[jv + 1], p0, p1, p2, p3, v2, v3);
            }
        }
    }

    // ---- epilogue: O/l -> fp16 into out-GEMM operand buffer ----
    const float inv0 = 1.f / fmaxf(l_r0, 1e-30f);
    const float inv1 = 1.f / fmaxf(l_r1, 1e-30f);
    const int r1g = qbase + wq0 + r_lo;
    #pragma unroll
    for (int j = 0; j < 8; j++) {
        const size_t idx0 = ((size_t)b * Sn + r1g) * Dn + h * 64 + j * 8 + 2 * c4;
        __half2 h2;
        h2 = __floats2half2_rn(o[j][0] * inv0, o[j][1] * inv0);
        *(uint32_t*)&g_ahi[idx0] = *(uint32_t*)&h2;
        h2 = __floats2half2_rn(o[j][2] * inv1, o[j][3] * inv1);
        *(uint32_t*)&g_ahi[idx0 + 8 * Dn] = *(uint32_t*)&h2;
    }
}

// ---------------------------------------------------------------------------
extern "C" void kernel_launch(void* const* d_in, const int* in_sizes, int n_in,
                              void* d_out, int out_size)
{
    const float* x    = (const float*)d_in[0];
    const void*  mask = d_in[1];
    const float* wq   = (const float*)d_in[2];
    const float* wk   = (const float*)d_in[3];
    const float* wv   = (const float*)d_in[4];
    const float* wo   = (const float*)d_in[5];
    float* out = (float*)d_out;

    cudaFuncSetAttribute(mma_gemm_kernel,
                         cudaFuncAttributeMaxDynamicSharedMemorySize, DYNSM);
    cudaFuncSetAttribute(attn_mma_kernel,
                         cudaFuncAttributeMaxDynamicSharedMemorySize, ATT_SMEM);

    detect_mask_kernel<<<1, 256>>>((const uint32_t*)mask);
    const size_t mask_elts = (size_t)Bn * Sn * Sn;
    pack_mask_kernel<<<(unsigned)(mask_elts / 1024), 256>>>(mask);

    __half *ahi, *whi;
    cudaGetSymbolAddress((void**)&ahi, g_ahi);
    cudaGetSymbolAddress((void**)&whi, g_whi);

    // X (8 slices) + 4 weights -> fp16 in one launch
    cvt_all_kernel<<<dim3((unsigned)((size_t)Dn * Dn / 1024), 12), 256>>>(x, wq, wk, wv, wo);

    // QKV projections -> fp16 Q/K/V, single-pass
    dim3 g1(Dn / 128, Mtot / 128, 3);
    mma_gemm_kernel<<<g1, 256, DYNSM>>>(ahi, whi, nullptr, 0);

    // Tensor-core flash attention -> writes g_ahi
    dim3 g2(Sn / 128, Bn * Hn);
    attn_mma_kernel<<<g2, 256, ATT_SMEM>>>();

    // Output projection (single-pass)
    dim3 g3(Dn / 128, Mtot / 128, 1);
    mma_gemm_kernel<<<g3, 256, DYNSM>>>(ahi, whi + 3 * (size_t)Dn * Dn, out, 1);
}